// round 2
// baseline (speedup 1.0000x reference)
#include <cuda_runtime.h>
#include <math.h>

#define SEQ 4096
#define NB 4
#define HID 1024
#define HD 256
#define MTOT (NB*SEQ)
#define DW 512            // gamma^513 ~ 8.5e-8, far below rel-err threshold

typedef unsigned long long u64;

// ---------------- static device scratch (no cudaMalloc allowed) ----------------
__device__ float g_Q[(size_t)MTOT*HD];
__device__ float g_K[(size_t)MTOT*HD];
__device__ float g_V[(size_t)MTOT*HD];
__device__ float g_cosQ[SEQ*128];
__device__ float g_sinQ[SEQ*128];
__device__ float g_cosK[SEQ*128];
__device__ float g_sinK[SEQ*128];
__device__ float g_gamma[SEQ];
__device__ double g_invf[128];
__device__ double g_l2sb[128];

// ---------------- packed fp32x2 helpers (Blackwell FFMA2 pipe) ----------------
__device__ __forceinline__ u64 pack2(float x, float y) {
    u64 r; asm("mov.b64 %0, {%1, %2};" : "=l"(r) : "f"(x), "f"(y)); return r;
}
__device__ __forceinline__ float2 unpk(u64 v) {
    float2 r; asm("mov.b64 {%0, %1}, %2;" : "=f"(r.x), "=f"(r.y) : "l"(v)); return r;
}
__device__ __forceinline__ void fma2(u64 &d, u64 a, u64 b) {
    asm("fma.rn.f32x2 %0, %1, %2, %0;" : "+l"(d) : "l"(a), "l"(b));
}

// ---------------- constants ----------------
__global__ void const_kernel() {
    int t = blockIdx.x * blockDim.x + threadIdx.x;
    if (t < 128) {
        g_invf[t] = pow(10000.0, -(double)t / 128.0);
        double sb = ((double)(2 * t) + 0.4 * 256.0) / (1.4 * 256.0);
        g_l2sb[t] = log2(sb);
    }
    if (t < SEQ) g_gamma[t] = (float)pow(0.96875, (double)t);
}

// ---------------- xpos sin/cos/scale tables ----------------
__global__ void tables_kernel() {
    int pos = blockIdx.x, j = threadIdx.x;
    float invf = (float)g_invf[j];
    float arg = (float)pos * invf;               // fp32 phase, matches reference rounding
    double ad = (double)arg;
    double qd = rint(ad * 0.63661977236758134308);   // 2/pi
    double rd = fma(qd, -1.5707963267948966, ad);
    rd = fma(qd, -6.123233995736766e-17, rd);        // pi/2 tail
    int qi = ((long long)qd) & 3;
    float rf = (float)rd;
    float sr = sinf(rf), cr = cosf(rf);
    float s, c;
    if      (qi == 0) { s =  sr; c =  cr; }
    else if (qi == 1) { s =  cr; c = -sr; }
    else if (qi == 2) { s = -sr; c = -cr; }
    else              { s = -cr; c =  sr; }
    float p  = (float)pos * (1.0f / 512.0f);
    float l2 = (float)g_l2sb[j];
    float sc  = exp2f(p * l2);
    float isc = exp2f(-p * l2);
    int idx = pos * 128 + j;
    g_cosQ[idx] = c * sc;   g_sinQ[idx] = s * sc;
    g_cosK[idx] = c * isc;  g_sinK[idx] = s * isc;
}

// ---------------- projection GEMM + xpos epilogue ----------------
// C[16384x256] = X[16384x1024] @ W[1024x256]; z=0:Q(xpos) 1:K(xpos inv) 2:V
// BM=128 BN=128 BK=16, 256 threads, per-thread 8x8 via f32x2 row pairs.
#define PBM 128
#define PBN 128
#define PBK 16

__global__ void __launch_bounds__(256, 2) proj_kernel(
    const float* __restrict__ X, const float* __restrict__ WQ,
    const float* __restrict__ WK, const float* __restrict__ WV)
{
    int z = blockIdx.z;
    const float* W = (z == 0) ? WQ : (z == 1 ? WK : WV);
    float* O = (z == 0) ? g_Q : (z == 1 ? g_K : g_V);

    __shared__ __align__(16) float As[PBK][132];   // [k][m] transposed
    __shared__ __align__(16) float Bs[PBK][132];   // [k][n]

    int tid = threadIdx.x;
    int tx = tid & 15, ty = tid >> 4;
    int row0 = blockIdx.y * PBM;
    int col0 = blockIdx.x * PBN;

    u64 acc[2][2][2][4];   // [rowgrp][rowpair][colgrp][ci]
    #pragma unroll
    for (int g = 0; g < 2; g++)
        #pragma unroll
        for (int rp = 0; rp < 2; rp++)
            #pragma unroll
            for (int cg = 0; cg < 2; cg++)
                #pragma unroll
                for (int ci = 0; ci < 4; ci++) acc[g][rp][cg][ci] = 0ULL;

    for (int kt = 0; kt < HID; kt += PBK) {
        #pragma unroll
        for (int l = 0; l < 2; l++) {            // A tile 128x16 -> transposed
            int fi = tid + l * 256;
            int r = fi >> 2, kq = (fi & 3) * 4;
            float4 a = *(const float4*)(X + (size_t)(row0 + r) * HID + kt + kq);
            As[kq + 0][r] = a.x; As[kq + 1][r] = a.y;
            As[kq + 2][r] = a.z; As[kq + 3][r] = a.w;
        }
        #pragma unroll
        for (int l = 0; l < 2; l++) {            // B tile 16x128
            int fi = tid + l * 256;
            int r = fi >> 5, c4 = (fi & 31) * 4;
            *(float4*)&Bs[r][c4] = *(const float4*)(W + (size_t)(kt + r) * HD + col0 + c4);
        }
        __syncthreads();
        #pragma unroll
        for (int kk = 0; kk < PBK; kk++) {
            u64 a[2][2];
            #pragma unroll
            for (int g = 0; g < 2; g++) {
                a[g][0] = *(const u64*)&As[kk][ty * 4 + g * 64];
                a[g][1] = *(const u64*)&As[kk][ty * 4 + g * 64 + 2];
            }
            #pragma unroll
            for (int cg = 0; cg < 2; cg++) {
                float4 bv = *(const float4*)&Bs[kk][tx * 4 + cg * 64];
                u64 bd[4];
                bd[0] = pack2(bv.x, bv.x); bd[1] = pack2(bv.y, bv.y);
                bd[2] = pack2(bv.z, bv.z); bd[3] = pack2(bv.w, bv.w);
                #pragma unroll
                for (int g = 0; g < 2; g++)
                    #pragma unroll
                    for (int rp = 0; rp < 2; rp++) {
                        fma2(acc[g][rp][cg][0], a[g][rp], bd[0]);
                        fma2(acc[g][rp][cg][1], a[g][rp], bd[1]);
                        fma2(acc[g][rp][cg][2], a[g][rp], bd[2]);
                        fma2(acc[g][rp][cg][3], a[g][rp], bd[3]);
                    }
            }
        }
        __syncthreads();
    }

    const float* ct = (z == 0) ? g_cosQ : g_cosK;
    const float* st = (z == 0) ? g_sinQ : g_sinK;
    #pragma unroll
    for (int g = 0; g < 2; g++)
        #pragma unroll
        for (int rp = 0; rp < 2; rp++)
            #pragma unroll
            for (int h = 0; h < 2; h++) {
                int r = row0 + ty * 4 + g * 64 + 2 * rp + h;
                int pos = r & (SEQ - 1);
                #pragma unroll
                for (int cg = 0; cg < 2; cg++) {
                    float v[4];
                    #pragma unroll
                    for (int ci = 0; ci < 4; ci++) {
                        float2 t2 = unpk(acc[g][rp][cg][ci]);
                        v[ci] = h ? t2.y : t2.x;
                    }
                    int colb = col0 + tx * 4 + cg * 64;
                    float4 ov;
                    if (z < 2) {
                        int j0 = colb >> 1;
                        float C0 = ct[pos * 128 + j0],     S0 = st[pos * 128 + j0];
                        float C1 = ct[pos * 128 + j0 + 1], S1 = st[pos * 128 + j0 + 1];
                        ov.x = v[0] * C0 - v[1] * S0;
                        ov.y = v[1] * C0 + v[0] * S0;
                        ov.z = v[2] * C1 - v[3] * S1;
                        ov.w = v[3] * C1 + v[2] * S1;
                    } else {
                        ov.x = v[0]; ov.y = v[1]; ov.z = v[2]; ov.w = v[3];
                    }
                    *(float4*)(O + (size_t)r * HD + colb) = ov;
                }
            }
}

// ---------------- banded retention attention ----------------
// Per block: 64 queries x one batch. Key tiles of 128 in [q0-512, q0].
#define ABQ 64
#define ABK 128
// smem floats: Qs 64x260, Kt 64x130 (d-major), Ss 64x130, Vs 32x260
#define SM_QS 0
#define SM_KT (64*260)
#define SM_SS (SM_KT + 64*130)
#define SM_VS (SM_SS + 64*130)
#define ATTN_SMEM_FLOATS (SM_VS + 32*260)
#define ATTN_SMEM_BYTES (ATTN_SMEM_FLOATS * 4)

__global__ void __launch_bounds__(256, 1) attn_kernel(float* __restrict__ out)
{
    extern __shared__ __align__(16) float smem[];
    float* Qs = smem + SM_QS;
    float* Kt = smem + SM_KT;
    float* Ss = smem + SM_SS;
    float* Vs = smem + SM_VS;

    int tid = threadIdx.x;
    int b = blockIdx.y;
    int q0 = blockIdx.x * ABQ;
    size_t base = (size_t)b * SEQ;

    // load Q tile 64x256 (resident for whole block)
    #pragma unroll
    for (int l = 0; l < 16; l++) {
        int fi = tid + l * 256;
        int r = fi >> 6, c4 = (fi & 63) * 4;
        *(float4*)&Qs[r * 260 + c4] = *(const float4*)&g_Q[(base + q0 + r) * HD + c4];
    }

    int ty2 = tid >> 5, tx2 = tid & 31;   // phase-2 layout: 8 rows x (2+64-strided) cols
    int tx1 = tid & 15, ty1 = tid >> 4;   // phase-1 layout

    u64 o[8][4];
    #pragma unroll
    for (int rr = 0; rr < 8; rr++)
        #pragma unroll
        for (int cg = 0; cg < 4; cg++) o[rr][cg] = 0ULL;

    int kt_lo = q0 - DW; if (kt_lo < 0) kt_lo = 0;

    for (int kt = kt_lo; kt <= q0; kt += ABK) {
        // ---- phase 1: S = Q @ K^T (64x128) ----
        u64 s[4][4];
        #pragma unroll
        for (int r = 0; r < 4; r++)
            #pragma unroll
            for (int cg = 0; cg < 4; cg++) s[r][cg] = 0ULL;

        for (int dc = 0; dc < HD; dc += 64) {
            __syncthreads();
            #pragma unroll
            for (int l = 0; l < 8; l++) {        // K chunk 128x64 -> transposed [d][m]
                int fi = tid + l * 256;
                int m = fi >> 4, d4 = (fi & 15) * 4;
                float4 k4 = *(const float4*)&g_K[(base + kt + m) * HD + dc + d4];
                Kt[(d4 + 0) * 130 + m] = k4.x;
                Kt[(d4 + 1) * 130 + m] = k4.y;
                Kt[(d4 + 2) * 130 + m] = k4.z;
                Kt[(d4 + 3) * 130 + m] = k4.w;
            }
            __syncthreads();
            #pragma unroll 2
            for (int d = 0; d < 64; d++) {
                u64 kf[4];
                #pragma unroll
                for (int cg = 0; cg < 4; cg++)
                    kf[cg] = *(const u64*)&Kt[d * 130 + tx1 * 2 + cg * 32];
                #pragma unroll
                for (int r = 0; r < 4; r++) {
                    float qv = Qs[(ty1 * 4 + r) * 260 + dc + d];
                    u64 qd = pack2(qv, qv);
                    fma2(s[r][0], qd, kf[0]);
                    fma2(s[r][1], qd, kf[1]);
                    fma2(s[r][2], qd, kf[2]);
                    fma2(s[r][3], qd, kf[3]);
                }
            }
        }
        __syncthreads();

        // ---- decay + stage S ----
        int dqk = q0 - kt;
        #pragma unroll
        for (int r = 0; r < 4; r++)
            #pragma unroll
            for (int cg = 0; cg < 4; cg++) {
                float2 sv = unpk(s[r][cg]);
                int row = ty1 * 4 + r;
                int c0 = tx1 * 2 + cg * 32;
                int e0 = dqk + row - c0;
                float g0 = (e0 >= 0) ? g_gamma[e0] : 0.0f;
                float g1 = (e0 >= 1) ? g_gamma[e0 - 1] : 0.0f;
                Ss[row * 130 + c0]     = sv.x * g0;
                Ss[row * 130 + c0 + 1] = sv.y * g1;
            }

        // ---- phase 2: O += S @ V (64x256) ----
        for (int vc = 0; vc < ABK; vc += 32) {
            __syncthreads();
            #pragma unroll
            for (int l = 0; l < 8; l++) {        // V chunk 32x256
                int fi = tid + l * 256;
                int r = fi >> 6, c4 = (fi & 63) * 4;
                *(float4*)&Vs[r * 260 + c4] =
                    *(const float4*)&g_V[(base + kt + vc + r) * HD + c4];
            }
            __syncthreads();
            #pragma unroll 2
            for (int k = 0; k < 32; k++) {
                u64 vf[4];
                #pragma unroll
                for (int cg = 0; cg < 4; cg++)
                    vf[cg] = *(const u64*)&Vs[k * 260 + tx2 * 2 + cg * 64];
                #pragma unroll
                for (int rr = 0; rr < 8; rr++) {
                    float sv = Ss[(ty2 * 8 + rr) * 130 + vc + k];
                    u64 sd = pack2(sv, sv);
                    fma2(o[rr][0], sd, vf[0]);
                    fma2(o[rr][1], sd, vf[1]);
                    fma2(o[rr][2], sd, vf[2]);
                    fma2(o[rr][3], sd, vf[3]);
                }
            }
        }
        __syncthreads();
    }

    // ---- store O ----
    #pragma unroll
    for (int rr = 0; rr < 8; rr++) {
        size_t rowo = (base + q0 + ty2 * 8 + rr) * HD;
        #pragma unroll
        for (int cg = 0; cg < 4; cg++)
            *(u64*)&out[rowo + tx2 * 2 + cg * 64] = o[rr][cg];
    }
}

// ---------------- launch ----------------
extern "C" void kernel_launch(void* const* d_in, const int* in_sizes, int n_in,
                              void* d_out, int out_size) {
    const float* X  = (const float*)d_in[0];
    const float* WQ = (const float*)d_in[1];
    const float* WK = (const float*)d_in[2];
    const float* WV = (const float*)d_in[3];
    float* out = (float*)d_out;

    const_kernel<<<16, 256>>>();
    tables_kernel<<<SEQ, 128>>>();

    dim3 pg(HD / PBN, MTOT / PBM, 3);
    proj_kernel<<<pg, 256>>>(X, WQ, WK, WV);

    cudaFuncSetAttribute(attn_kernel, cudaFuncAttributeMaxDynamicSharedMemorySize,
                         ATTN_SMEM_BYTES);
    dim3 ag(SEQ / ABQ, NB);
    attn_kernel<<<ag, 256, ATTN_SMEM_BYTES>>>(out);
}

// round 5
// speedup vs baseline: 1.4717x; 1.4717x over previous
#include <cuda_runtime.h>
#include <cuda_bf16.h>
#include <math.h>
#include <stdint.h>

#define SEQ 4096
#define NB 4
#define HID 1024
#define HD 256
#define MTOT (NB*SEQ)
#define DW 512            // gamma^513 ~ 8.5e-8, far below rel-err threshold

typedef unsigned long long u64;

// ---------------- static device scratch (no cudaMalloc allowed) ----------------
__device__ float g_Q[(size_t)MTOT*HD];
__device__ float g_K[(size_t)MTOT*HD];
__device__ float g_V[(size_t)MTOT*HD];
__device__ __nv_bfloat16 g_Xh[(size_t)MTOT*HID];
__device__ __nv_bfloat16 g_Xm[(size_t)MTOT*HID];
__device__ __nv_bfloat16 g_Wh[3*HID*HD];   // [z][k][n]
__device__ __nv_bfloat16 g_Wm[3*HID*HD];
__device__ float g_cosQ[SEQ*128];
__device__ float g_sinQ[SEQ*128];
__device__ float g_cosK[SEQ*128];
__device__ float g_sinK[SEQ*128];
__device__ float g_gamma[SEQ];
__device__ double g_invf[128];
__device__ double g_l2sb[128];

// ---------------- packed fp32x2 helpers (attention SIMT path) ----------------
__device__ __forceinline__ u64 pack2(float x, float y) {
    u64 r; asm("mov.b64 %0, {%1, %2};" : "=l"(r) : "f"(x), "f"(y)); return r;
}
__device__ __forceinline__ float2 unpk(u64 v) {
    float2 r; asm("mov.b64 {%0, %1}, %2;" : "=f"(r.x), "=f"(r.y) : "l"(v)); return r;
}
__device__ __forceinline__ void fma2(u64 &d, u64 a, u64 b) {
    asm("fma.rn.f32x2 %0, %1, %2, %0;" : "+l"(d) : "l"(a), "l"(b));
}

// ---------------- mma / async helpers (baseline PTX, sm_80+ ISA only) ----------------
__device__ __forceinline__ uint32_t smem_u32(const void* p) {
    uint32_t a;
    asm("{ .reg .u64 t; cvta.to.shared.u64 t, %1; cvt.u32.u64 %0, t; }" : "=r"(a) : "l"(p));
    return a;
}
__device__ __forceinline__ void cp16(uint32_t dst, const void* src) {
    asm volatile("cp.async.cg.shared.global [%0], [%1], 16;" :: "r"(dst), "l"(src));
}
#define CP_COMMIT()  asm volatile("cp.async.commit_group;" ::: "memory")
#define CP_WAIT(n)   asm volatile("cp.async.wait_group %0;" :: "n"(n) : "memory")

__device__ __forceinline__ void ldsm4(uint32_t (&r)[4], uint32_t a) {
    asm volatile("ldmatrix.sync.aligned.m8n8.x4.shared.b16 {%0,%1,%2,%3}, [%4];"
                 : "=r"(r[0]), "=r"(r[1]), "=r"(r[2]), "=r"(r[3]) : "r"(a));
}
__device__ __forceinline__ void ldsm4t(uint32_t (&r)[4], uint32_t a) {
    asm volatile("ldmatrix.sync.aligned.m8n8.x4.trans.shared.b16 {%0,%1,%2,%3}, [%4];"
                 : "=r"(r[0]), "=r"(r[1]), "=r"(r[2]), "=r"(r[3]) : "r"(a));
}
__device__ __forceinline__ void mma16816(float* d, const uint32_t* a, uint32_t b0, uint32_t b1) {
    asm volatile(
        "mma.sync.aligned.m16n8k16.row.col.f32.bf16.bf16.f32 "
        "{%0,%1,%2,%3}, {%4,%5,%6,%7}, {%8,%9}, {%0,%1,%2,%3};"
        : "+f"(d[0]), "+f"(d[1]), "+f"(d[2]), "+f"(d[3])
        : "r"(a[0]), "r"(a[1]), "r"(a[2]), "r"(a[3]), "r"(b0), "r"(b1));
}

// ---------------- constants ----------------
__global__ void const_kernel() {
    int t = blockIdx.x * blockDim.x + threadIdx.x;
    if (t < 128) {
        g_invf[t] = pow(10000.0, -(double)t / 128.0);
        double sb = ((double)(2 * t) + 0.4 * 256.0) / (1.4 * 256.0);
        g_l2sb[t] = log2(sb);
    }
    if (t < SEQ) g_gamma[t] = (float)pow(0.96875, (double)t);
}

// ---------------- xpos sin/cos/scale tables ----------------
__global__ void tables_kernel() {
    int pos = blockIdx.x, j = threadIdx.x;
    float invf = (float)g_invf[j];
    float arg = (float)pos * invf;
    double ad = (double)arg;
    double qd = rint(ad * 0.63661977236758134308);
    double rd = fma(qd, -1.5707963267948966, ad);
    rd = fma(qd, -6.123233995736766e-17, rd);
    int qi = ((long long)qd) & 3;
    float rf = (float)rd;
    float sr = sinf(rf), cr = cosf(rf);
    float s, c;
    if      (qi == 0) { s =  sr; c =  cr; }
    else if (qi == 1) { s =  cr; c = -sr; }
    else if (qi == 2) { s = -sr; c = -cr; }
    else              { s = -cr; c =  sr; }
    float p  = (float)pos * (1.0f / 512.0f);
    float l2 = (float)g_l2sb[j];
    float sc  = exp2f(p * l2);
    float isc = exp2f(-p * l2);
    int idx = pos * 128 + j;
    g_cosQ[idx] = c * sc;   g_sinQ[idx] = s * sc;
    g_cosK[idx] = c * isc;  g_sinK[idx] = s * isc;
}

// ---------------- prep: split X / W into bf16 (hi, mid) ----------------
__global__ void splitx_kernel(const float* __restrict__ X) {
    size_t i = (size_t)blockIdx.x * blockDim.x + threadIdx.x;   // 4 floats each
    float4 x = ((const float4*)X)[i];
    __nv_bfloat16 h0 = __float2bfloat16(x.x), h1 = __float2bfloat16(x.y);
    __nv_bfloat16 h2 = __float2bfloat16(x.z), h3 = __float2bfloat16(x.w);
    __nv_bfloat16 m0 = __float2bfloat16(x.x - __bfloat162float(h0));
    __nv_bfloat16 m1 = __float2bfloat16(x.y - __bfloat162float(h1));
    __nv_bfloat16 m2 = __float2bfloat16(x.z - __bfloat162float(h2));
    __nv_bfloat16 m3 = __float2bfloat16(x.w - __bfloat162float(h3));
    __nv_bfloat162* ph = (__nv_bfloat162*)g_Xh;
    __nv_bfloat162* pm = (__nv_bfloat162*)g_Xm;
    __nv_bfloat162 a; a.x = h0; a.y = h1; ph[2*i] = a;
    a.x = h2; a.y = h3; ph[2*i+1] = a;
    a.x = m0; a.y = m1; pm[2*i] = a;
    a.x = m2; a.y = m3; pm[2*i+1] = a;
}

__global__ void splitw_kernel(const float* __restrict__ WQ,
                              const float* __restrict__ WK,
                              const float* __restrict__ WV) {
    int idx = blockIdx.x * blockDim.x + threadIdx.x;   // [z][k][n], 3*1024*256
    int z = idx >> 18;
    int kn = idx & 0x3FFFF;
    const float* W = (z == 0) ? WQ : (z == 1 ? WK : WV);
    float w = W[kn];
    __nv_bfloat16 h = __float2bfloat16(w);
    g_Wh[idx] = h;
    g_Wm[idx] = __float2bfloat16(w - __bfloat162float(h));
}

// ---------------- projection GEMM on mma.sync bf16 (split-3) ----------------
// CTA = 128M x 256N, K=1024 in 32 stages of KC=32, cp.async double-buffered.
// A smem: [m][term(2)][k32] -> 128 rows x 128B. B smem: [k][term(2)][n256] -> 32 rows x 1024B.
// XOR swizzle on 16B chunks keeps ldmatrix conflict-free.
#define PKC 32
#define STG_A 16384
#define STG_B 32768
#define STG_BYTES (STG_A + STG_B)
#define PROJ_SMEM (2 * STG_BYTES)

__global__ void __launch_bounds__(256, 1) proj_mma_kernel()
{
    extern __shared__ __align__(1024) char sm[];
    uint32_t smb = smem_u32(sm);
    int tid = threadIdx.x;
    int z = blockIdx.x;
    int m0 = blockIdx.y * 128;

    const __nv_bfloat16* Wh = g_Wh + (size_t)z * HID * HD;
    const __nv_bfloat16* Wm = g_Wm + (size_t)z * HID * HD;

    // --- copy geometry (per thread: 4 A chunks + 8 B chunks of 16B) ---
    const __nv_bfloat16* srcA[4]; uint32_t dstA[4];
    #pragma unroll
    for (int i = 0; i < 4; i++) {
        int id = tid + i * 256;           // 0..1023
        int m = id >> 3, cc = id & 7;     // cc = term*4 + c
        int term = cc >> 2, c = cc & 3;
        srcA[i] = (term ? g_Xm : g_Xh) + (size_t)(m0 + m) * HID + c * 8;
        dstA[i] = (uint32_t)(m * 128 + ((cc ^ (m & 7)) << 4));
    }
    const __nv_bfloat16* srcB[8]; uint32_t dstB[8];
    #pragma unroll
    for (int i = 0; i < 8; i++) {
        int id = tid + i * 256;           // 0..2047
        int k = id >> 6, cc = id & 63;    // cc = term*32 + n_c
        int term = cc >> 5, n_c = cc & 31;
        srcB[i] = (term ? Wm : Wh) + (size_t)k * HD + n_c * 8;
        dstB[i] = (uint32_t)(STG_A + k * 1024 + ((cc ^ (k & 7)) << 4));
    }

    // --- compute geometry ---
    int w = tid >> 5, l = tid & 31;
    int wm = (w >> 2) * 64, wn = (w & 3) * 64;
    int la = l & 15, hsel = l >> 4;       // ldmatrix lane row / half-select
    uint32_t arowb = (uint32_t)((wm + la) * 128);
    uint32_t amx = (uint32_t)(la & 7);
    uint32_t brow = (uint32_t)((la) * 1024);
    uint32_t bmx = (uint32_t)(la & 7);
    uint32_t bnc0 = (uint32_t)(wn >> 3);

    float d[4][8][4];
    #pragma unroll
    for (int mt = 0; mt < 4; mt++)
        #pragma unroll
        for (int nt = 0; nt < 8; nt++)
            #pragma unroll
            for (int r = 0; r < 4; r++) d[mt][nt][r] = 0.0f;

    // stage 0 copy
    {
        uint32_t bb = smb;
        #pragma unroll
        for (int i = 0; i < 4; i++) cp16(bb + dstA[i], srcA[i]);
        #pragma unroll
        for (int i = 0; i < 8; i++) cp16(bb + dstB[i], srcB[i]);
        CP_COMMIT();
    }

    for (int s = 0; s < 32; s++) {
        if (s + 1 < 32) {
            uint32_t bb = smb + (uint32_t)((s + 1) & 1) * STG_BYTES;
            int kt = (s + 1) * PKC;
            #pragma unroll
            for (int i = 0; i < 4; i++) cp16(bb + dstA[i], srcA[i] + kt);
            #pragma unroll
            for (int i = 0; i < 8; i++) cp16(bb + dstB[i], srcB[i] + (size_t)kt * HD);
            CP_COMMIT();
            CP_WAIT(1);
        } else {
            CP_WAIT(0);
        }
        __syncthreads();

        uint32_t AS = smb + (uint32_t)(s & 1) * STG_BYTES;
        uint32_t BS = AS + STG_A;   // FIX (R5): B tile lives after the A tile

        #pragma unroll
        for (int kk8 = 0; kk8 < 4; kk8 += 2) {         // two k16 slabs
            uint32_t ah[4][4], am[4][4];
            #pragma unroll
            for (int mt = 0; mt < 4; mt++) {
                uint32_t rb = AS + arowb + (uint32_t)(mt * 2048);
                ldsm4(ah[mt], rb + ((((uint32_t)(0 + kk8 + hsel)) ^ amx) << 4));
                ldsm4(am[mt], rb + ((((uint32_t)(4 + kk8 + hsel)) ^ amx) << 4));
            }
            uint32_t krow = BS + (uint32_t)((kk8 >> 1) * 16 * 1024) + brow;
            #pragma unroll
            for (int half = 0; half < 2; half++) {
                uint32_t bh[2][4], bm[2][4];
                #pragma unroll
                for (int j2 = 0; j2 < 2; j2++) {
                    uint32_t nc = bnc0 + (uint32_t)(half * 4 + j2 * 2 + hsel);
                    ldsm4t(bh[j2], krow + (((nc)       ^ bmx) << 4));
                    ldsm4t(bm[j2], krow + (((nc + 32u) ^ bmx) << 4));
                }
                #pragma unroll
                for (int nt = 0; nt < 4; nt++) {
                    uint32_t h0 = bh[nt >> 1][(nt & 1) * 2], h1 = bh[nt >> 1][(nt & 1) * 2 + 1];
                    uint32_t q0 = bm[nt >> 1][(nt & 1) * 2], q1 = bm[nt >> 1][(nt & 1) * 2 + 1];
                    #pragma unroll
                    for (int mt = 0; mt < 4; mt++) {
                        float* dd = d[mt][half * 4 + nt];
                        mma16816(dd, ah[mt], h0, h1);
                        mma16816(dd, ah[mt], q0, q1);
                        mma16816(dd, am[mt], h0, h1);
                    }
                }
            }
        }
        __syncthreads();
    }

    // ---- epilogue: rotary (for Q,K) + store ----
    float* O = (z == 0) ? g_Q : (z == 1 ? g_K : g_V);
    const float* ct = (z == 0) ? g_cosQ : g_cosK;
    const float* st = (z == 0) ? g_sinQ : g_sinK;
    int mrb = m0 + wm + (l >> 2);
    int ncb = wn + (l & 3) * 2;
    #pragma unroll
    for (int mt = 0; mt < 4; mt++)
        #pragma unroll
        for (int r2 = 0; r2 < 2; r2++) {
            int m = mrb + mt * 16 + r2 * 8;
            int pos = m & (SEQ - 1);
            #pragma unroll
            for (int nt = 0; nt < 8; nt++) {
                int n = ncb + nt * 8;
                float v0 = d[mt][nt][r2 * 2], v1 = d[mt][nt][r2 * 2 + 1];
                float2 ov;
                if (z < 2) {
                    int j = n >> 1;
                    float C = ct[pos * 128 + j], S = st[pos * 128 + j];
                    ov.x = v0 * C - v1 * S;
                    ov.y = v1 * C + v0 * S;
                } else {
                    ov.x = v0; ov.y = v1;
                }
                *(float2*)(O + (size_t)m * HD + n) = ov;
            }
        }
}

// ---------------- banded retention attention (SIMT fp32x2, unchanged) ----------------
#define ABQ 64
#define ABK 128
#define SM_QS 0
#define SM_KT (64*260)
#define SM_SS (SM_KT + 64*130)
#define SM_VS (SM_SS + 64*130)
#define ATTN_SMEM_FLOATS (SM_VS + 32*260)
#define ATTN_SMEM_BYTES (ATTN_SMEM_FLOATS * 4)

__global__ void __launch_bounds__(256, 1) attn_kernel(float* __restrict__ out)
{
    extern __shared__ __align__(16) float smem[];
    float* Qs = smem + SM_QS;
    float* Kt = smem + SM_KT;
    float* Ss = smem + SM_SS;
    float* Vs = smem + SM_VS;

    int tid = threadIdx.x;
    int b = blockIdx.y;
    int q0 = blockIdx.x * ABQ;
    size_t base = (size_t)b * SEQ;

    #pragma unroll
    for (int l = 0; l < 16; l++) {
        int fi = tid + l * 256;
        int r = fi >> 6, c4 = (fi & 63) * 4;
        *(float4*)&Qs[r * 260 + c4] = *(const float4*)&g_Q[(base + q0 + r) * HD + c4];
    }

    int ty2 = tid >> 5, tx2 = tid & 31;
    int tx1 = tid & 15, ty1 = tid >> 4;

    u64 o[8][4];
    #pragma unroll
    for (int rr = 0; rr < 8; rr++)
        #pragma unroll
        for (int cg = 0; cg < 4; cg++) o[rr][cg] = 0ULL;

    int kt_lo = q0 - DW; if (kt_lo < 0) kt_lo = 0;

    for (int kt = kt_lo; kt <= q0; kt += ABK) {
        u64 s[4][4];
        #pragma unroll
        for (int r = 0; r < 4; r++)
            #pragma unroll
            for (int cg = 0; cg < 4; cg++) s[r][cg] = 0ULL;

        for (int dc = 0; dc < HD; dc += 64) {
            __syncthreads();
            #pragma unroll
            for (int l = 0; l < 8; l++) {
                int fi = tid + l * 256;
                int m = fi >> 4, d4 = (fi & 15) * 4;
                float4 k4 = *(const float4*)&g_K[(base + kt + m) * HD + dc + d4];
                Kt[(d4 + 0) * 130 + m] = k4.x;
                Kt[(d4 + 1) * 130 + m] = k4.y;
                Kt[(d4 + 2) * 130 + m] = k4.z;
                Kt[(d4 + 3) * 130 + m] = k4.w;
            }
            __syncthreads();
            #pragma unroll 2
            for (int d = 0; d < 64; d++) {
                u64 kf[4];
                #pragma unroll
                for (int cg = 0; cg < 4; cg++)
                    kf[cg] = *(const u64*)&Kt[d * 130 + tx1 * 2 + cg * 32];
                #pragma unroll
                for (int r = 0; r < 4; r++) {
                    float qv = Qs[(ty1 * 4 + r) * 260 + dc + d];
                    u64 qd = pack2(qv, qv);
                    fma2(s[r][0], qd, kf[0]);
                    fma2(s[r][1], qd, kf[1]);
                    fma2(s[r][2], qd, kf[2]);
                    fma2(s[r][3], qd, kf[3]);
                }
            }
        }
        __syncthreads();

        int dqk = q0 - kt;
        #pragma unroll
        for (int r = 0; r < 4; r++)
            #pragma unroll
            for (int cg = 0; cg < 4; cg++) {
                float2 sv = unpk(s[r][cg]);
                int row = ty1 * 4 + r;
                int c0 = tx1 * 2 + cg * 32;
                int e0 = dqk + row - c0;
                float g0 = (e0 >= 0) ? g_gamma[e0] : 0.0f;
                float g1 = (e0 >= 1) ? g_gamma[e0 - 1] : 0.0f;
                Ss[row * 130 + c0]     = sv.x * g0;
                Ss[row * 130 + c0 + 1] = sv.y * g1;
            }

        for (int vc = 0; vc < ABK; vc += 32) {
            __syncthreads();
            #pragma unroll
            for (int l = 0; l < 8; l++) {
                int fi = tid + l * 256;
                int r = fi >> 6, c4 = (fi & 63) * 4;
                *(float4*)&Vs[r * 260 + c4] =
                    *(const float4*)&g_V[(base + kt + vc + r) * HD + c4];
            }
            __syncthreads();
            #pragma unroll 2
            for (int k = 0; k < 32; k++) {
                u64 vf[4];
                #pragma unroll
                for (int cg = 0; cg < 4; cg++)
                    vf[cg] = *(const u64*)&Vs[k * 260 + tx2 * 2 + cg * 64];
                #pragma unroll
                for (int rr = 0; rr < 8; rr++) {
                    float sv = Ss[(ty2 * 8 + rr) * 130 + vc + k];
                    u64 sd = pack2(sv, sv);
                    fma2(o[rr][0], sd, vf[0]);
                    fma2(o[rr][1], sd, vf[1]);
                    fma2(o[rr][2], sd, vf[2]);
                    fma2(o[rr][3], sd, vf[3]);
                }
            }
        }
        __syncthreads();
    }

    #pragma unroll
    for (int rr = 0; rr < 8; rr++) {
        size_t rowo = (base + q0 + ty2 * 8 + rr) * HD;
        #pragma unroll
        for (int cg = 0; cg < 4; cg++)
            *(u64*)&out[rowo + tx2 * 2 + cg * 64] = o[rr][cg];
    }
}

// ---------------- launch ----------------
extern "C" void kernel_launch(void* const* d_in, const int* in_sizes, int n_in,
                              void* d_out, int out_size) {
    const float* X  = (const float*)d_in[0];
    const float* WQ = (const float*)d_in[1];
    const float* WK = (const float*)d_in[2];
    const float* WV = (const float*)d_in[3];
    float* out = (float*)d_out;

    const_kernel<<<16, 256>>>();
    tables_kernel<<<SEQ, 128>>>();

    splitx_kernel<<<(MTOT * HID / 4) / 256, 256>>>(X);
    splitw_kernel<<<(3 * HID * HD) / 256, 256>>>(WQ, WK, WV);

    cudaFuncSetAttribute(proj_mma_kernel, cudaFuncAttributeMaxDynamicSharedMemorySize,
                         PROJ_SMEM);
    dim3 pg(3, MTOT / 128);
    proj_mma_kernel<<<pg, 256, PROJ_SMEM>>>();

    cudaFuncSetAttribute(attn_kernel, cudaFuncAttributeMaxDynamicSharedMemorySize,
                         ATTN_SMEM_BYTES);
    dim3 ag(SEQ / ABQ, NB);
    attn_kernel<<<ag, 256, ATTN_SMEM_BYTES>>>(out);
}

// round 6
// speedup vs baseline: 2.4271x; 1.6493x over previous
#include <cuda_runtime.h>
#include <cuda_bf16.h>
#include <math.h>
#include <stdint.h>

#define SEQ 4096
#define NB 4
#define HID 1024
#define HD 256
#define MTOT (NB*SEQ)
#define DW 512            // gamma^513 ~ 8.5e-8, far below rel-err threshold

typedef unsigned long long u64;

// ---------------- static device scratch (no cudaMalloc allowed) ----------------
// Q/K/V stored as packed bf16 (hi,mid): row layout [term0 d0..255][term1 d0..255], 512 elems/row
__device__ __nv_bfloat16 g_Qb[(size_t)MTOT*512];
__device__ __nv_bfloat16 g_Kb[(size_t)MTOT*512];
__device__ __nv_bfloat16 g_Vb[(size_t)MTOT*512];
__device__ __nv_bfloat16 g_Xh[(size_t)MTOT*HID];
__device__ __nv_bfloat16 g_Xm[(size_t)MTOT*HID];
__device__ __nv_bfloat16 g_Wh[3*HID*HD];   // [z][k][n]
__device__ __nv_bfloat16 g_Wm[3*HID*HD];
__device__ float g_cosQ[SEQ*128];
__device__ float g_sinQ[SEQ*128];
__device__ float g_cosK[SEQ*128];
__device__ float g_sinK[SEQ*128];
__device__ float g_gamma[SEQ];
__device__ double g_invf[128];
__device__ double g_l2sb[128];

// ---------------- mma / async helpers (baseline PTX, sm_80+ ISA only) ----------------
__device__ __forceinline__ uint32_t smem_u32(const void* p) {
    uint32_t a;
    asm("{ .reg .u64 t; cvta.to.shared.u64 t, %1; cvt.u32.u64 %0, t; }" : "=r"(a) : "l"(p));
    return a;
}
__device__ __forceinline__ void cp16(uint32_t dst, const void* src) {
    asm volatile("cp.async.cg.shared.global [%0], [%1], 16;" :: "r"(dst), "l"(src));
}
#define CP_COMMIT()  asm volatile("cp.async.commit_group;" ::: "memory")
#define CP_WAIT(n)   asm volatile("cp.async.wait_group %0;" :: "n"(n) : "memory")

__device__ __forceinline__ void ldsm4(uint32_t (&r)[4], uint32_t a) {
    asm volatile("ldmatrix.sync.aligned.m8n8.x4.shared.b16 {%0,%1,%2,%3}, [%4];"
                 : "=r"(r[0]), "=r"(r[1]), "=r"(r[2]), "=r"(r[3]) : "r"(a));
}
__device__ __forceinline__ void ldsm4t(uint32_t (&r)[4], uint32_t a) {
    asm volatile("ldmatrix.sync.aligned.m8n8.x4.trans.shared.b16 {%0,%1,%2,%3}, [%4];"
                 : "=r"(r[0]), "=r"(r[1]), "=r"(r[2]), "=r"(r[3]) : "r"(a));
}
__device__ __forceinline__ void mma16816(float* d, const uint32_t* a, uint32_t b0, uint32_t b1) {
    asm volatile(
        "mma.sync.aligned.m16n8k16.row.col.f32.bf16.bf16.f32 "
        "{%0,%1,%2,%3}, {%4,%5,%6,%7}, {%8,%9}, {%0,%1,%2,%3};"
        : "+f"(d[0]), "+f"(d[1]), "+f"(d[2]), "+f"(d[3])
        : "r"(a[0]), "r"(a[1]), "r"(a[2]), "r"(a[3]), "r"(b0), "r"(b1));
}
__device__ __forceinline__ uint32_t bf16pair(float a, float b) {
    __nv_bfloat162 t; t.x = __float2bfloat16(a); t.y = __float2bfloat16(b);
    uint32_t r; asm("mov.b32 %0, %1;" : "=r"(r) : "r"(*(uint32_t*)&t)); return r;
}

// ---------------- constants ----------------
__global__ void const_kernel() {
    int t = blockIdx.x * blockDim.x + threadIdx.x;
    if (t < 128) {
        g_invf[t] = pow(10000.0, -(double)t / 128.0);
        double sb = ((double)(2 * t) + 0.4 * 256.0) / (1.4 * 256.0);
        g_l2sb[t] = log2(sb);
    }
    if (t < SEQ) g_gamma[t] = (float)pow(0.96875, (double)t);
}

// ---------------- xpos sin/cos/scale tables ----------------
__global__ void tables_kernel() {
    int pos = blockIdx.x, j = threadIdx.x;
    float invf = (float)g_invf[j];
    float arg = (float)pos * invf;
    double ad = (double)arg;
    double qd = rint(ad * 0.63661977236758134308);
    double rd = fma(qd, -1.5707963267948966, ad);
    rd = fma(qd, -6.123233995736766e-17, rd);
    int qi = ((long long)qd) & 3;
    float rf = (float)rd;
    float sr = sinf(rf), cr = cosf(rf);
    float s, c;
    if      (qi == 0) { s =  sr; c =  cr; }
    else if (qi == 1) { s =  cr; c = -sr; }
    else if (qi == 2) { s = -sr; c = -cr; }
    else              { s = -cr; c =  sr; }
    float p  = (float)pos * (1.0f / 512.0f);
    float l2 = (float)g_l2sb[j];
    float sc  = exp2f(p * l2);
    float isc = exp2f(-p * l2);
    int idx = pos * 128 + j;
    g_cosQ[idx] = c * sc;   g_sinQ[idx] = s * sc;
    g_cosK[idx] = c * isc;  g_sinK[idx] = s * isc;
}

// ---------------- prep: split X / W into bf16 (hi, mid) ----------------
__global__ void splitx_kernel(const float* __restrict__ X) {
    size_t i = (size_t)blockIdx.x * blockDim.x + threadIdx.x;   // 4 floats each
    float4 x = ((const float4*)X)[i];
    __nv_bfloat16 h0 = __float2bfloat16(x.x), h1 = __float2bfloat16(x.y);
    __nv_bfloat16 h2 = __float2bfloat16(x.z), h3 = __float2bfloat16(x.w);
    __nv_bfloat16 m0 = __float2bfloat16(x.x - __bfloat162float(h0));
    __nv_bfloat16 m1 = __float2bfloat16(x.y - __bfloat162float(h1));
    __nv_bfloat16 m2 = __float2bfloat16(x.z - __bfloat162float(h2));
    __nv_bfloat16 m3 = __float2bfloat16(x.w - __bfloat162float(h3));
    __nv_bfloat162* ph = (__nv_bfloat162*)g_Xh;
    __nv_bfloat162* pm = (__nv_bfloat162*)g_Xm;
    __nv_bfloat162 a; a.x = h0; a.y = h1; ph[2*i] = a;
    a.x = h2; a.y = h3; ph[2*i+1] = a;
    a.x = m0; a.y = m1; pm[2*i] = a;
    a.x = m2; a.y = m3; pm[2*i+1] = a;
}

__global__ void splitw_kernel(const float* __restrict__ WQ,
                              const float* __restrict__ WK,
                              const float* __restrict__ WV) {
    int idx = blockIdx.x * blockDim.x + threadIdx.x;   // [z][k][n], 3*1024*256
    int z = idx >> 18;
    int kn = idx & 0x3FFFF;
    const float* W = (z == 0) ? WQ : (z == 1 ? WK : WV);
    float w = W[kn];
    __nv_bfloat16 h = __float2bfloat16(w);
    g_Wh[idx] = h;
    g_Wm[idx] = __float2bfloat16(w - __bfloat162float(h));
}

// ---------------- projection GEMM on mma.sync bf16 (split-3) ----------------
#define PKC 32
#define STG_A 16384
#define STG_B 32768
#define STG_BYTES (STG_A + STG_B)
#define PROJ_SMEM (2 * STG_BYTES)

__global__ void __launch_bounds__(256, 1) proj_mma_kernel()
{
    extern __shared__ __align__(1024) char sm[];
    uint32_t smb = smem_u32(sm);
    int tid = threadIdx.x;
    int z = blockIdx.x;
    int m0 = blockIdx.y * 128;

    const __nv_bfloat16* Wh = g_Wh + (size_t)z * HID * HD;
    const __nv_bfloat16* Wm = g_Wm + (size_t)z * HID * HD;

    const __nv_bfloat16* srcA[4]; uint32_t dstA[4];
    #pragma unroll
    for (int i = 0; i < 4; i++) {
        int id = tid + i * 256;
        int m = id >> 3, cc = id & 7;
        int term = cc >> 2, c = cc & 3;
        srcA[i] = (term ? g_Xm : g_Xh) + (size_t)(m0 + m) * HID + c * 8;
        dstA[i] = (uint32_t)(m * 128 + ((cc ^ (m & 7)) << 4));
    }
    const __nv_bfloat16* srcB[8]; uint32_t dstB[8];
    #pragma unroll
    for (int i = 0; i < 8; i++) {
        int id = tid + i * 256;
        int k = id >> 6, cc = id & 63;
        int term = cc >> 5, n_c = cc & 31;
        srcB[i] = (term ? Wm : Wh) + (size_t)k * HD + n_c * 8;
        dstB[i] = (uint32_t)(STG_A + k * 1024 + ((cc ^ (k & 7)) << 4));
    }

    int w = tid >> 5, l = tid & 31;
    int wm = (w >> 2) * 64, wn = (w & 3) * 64;
    int la = l & 15, hsel = l >> 4;
    uint32_t arowb = (uint32_t)((wm + la) * 128);
    uint32_t amx = (uint32_t)(la & 7);
    uint32_t brow = (uint32_t)(la * 1024);
    uint32_t bmx = (uint32_t)(la & 7);
    uint32_t bnc0 = (uint32_t)(wn >> 3);

    float d[4][8][4];
    #pragma unroll
    for (int mt = 0; mt < 4; mt++)
        #pragma unroll
        for (int nt = 0; nt < 8; nt++)
            #pragma unroll
            for (int r = 0; r < 4; r++) d[mt][nt][r] = 0.0f;

    {
        uint32_t bb = smb;
        #pragma unroll
        for (int i = 0; i < 4; i++) cp16(bb + dstA[i], srcA[i]);
        #pragma unroll
        for (int i = 0; i < 8; i++) cp16(bb + dstB[i], srcB[i]);
        CP_COMMIT();
    }

    for (int s = 0; s < 32; s++) {
        if (s + 1 < 32) {
            uint32_t bb = smb + (uint32_t)((s + 1) & 1) * STG_BYTES;
            int kt = (s + 1) * PKC;
            #pragma unroll
            for (int i = 0; i < 4; i++) cp16(bb + dstA[i], srcA[i] + kt);
            #pragma unroll
            for (int i = 0; i < 8; i++) cp16(bb + dstB[i], srcB[i] + (size_t)kt * HD);
            CP_COMMIT();
            CP_WAIT(1);
        } else {
            CP_WAIT(0);
        }
        __syncthreads();

        uint32_t AS = smb + (uint32_t)(s & 1) * STG_BYTES;
        uint32_t BS = AS + STG_A;

        #pragma unroll
        for (int kk8 = 0; kk8 < 4; kk8 += 2) {
            uint32_t ah[4][4], am[4][4];
            #pragma unroll
            for (int mt = 0; mt < 4; mt++) {
                uint32_t rb = AS + arowb + (uint32_t)(mt * 2048);
                ldsm4(ah[mt], rb + ((((uint32_t)(0 + kk8 + hsel)) ^ amx) << 4));
                ldsm4(am[mt], rb + ((((uint32_t)(4 + kk8 + hsel)) ^ amx) << 4));
            }
            uint32_t krow = BS + (uint32_t)((kk8 >> 1) * 16 * 1024) + brow;
            #pragma unroll
            for (int half = 0; half < 2; half++) {
                uint32_t bh[2][4], bm[2][4];
                #pragma unroll
                for (int j2 = 0; j2 < 2; j2++) {
                    uint32_t nc = bnc0 + (uint32_t)(half * 4 + j2 * 2 + hsel);
                    ldsm4t(bh[j2], krow + (((nc)       ^ bmx) << 4));
                    ldsm4t(bm[j2], krow + (((nc + 32u) ^ bmx) << 4));
                }
                #pragma unroll
                for (int nt = 0; nt < 4; nt++) {
                    uint32_t h0 = bh[nt >> 1][(nt & 1) * 2], h1 = bh[nt >> 1][(nt & 1) * 2 + 1];
                    uint32_t q0 = bm[nt >> 1][(nt & 1) * 2], q1 = bm[nt >> 1][(nt & 1) * 2 + 1];
                    #pragma unroll
                    for (int mt = 0; mt < 4; mt++) {
                        float* dd = d[mt][half * 4 + nt];
                        mma16816(dd, ah[mt], h0, h1);
                        mma16816(dd, ah[mt], q0, q1);
                        mma16816(dd, am[mt], h0, h1);
                    }
                }
            }
        }
        __syncthreads();
    }

    // ---- epilogue: rotary (Q,K) + bf16 hi/mid pack + store ----
    __nv_bfloat16* O = (z == 0) ? g_Qb : (z == 1 ? g_Kb : g_Vb);
    const float* ct = (z == 0) ? g_cosQ : g_cosK;
    const float* st = (z == 0) ? g_sinQ : g_sinK;
    int mrb = m0 + wm + (l >> 2);
    int ncb = wn + (l & 3) * 2;
    #pragma unroll
    for (int mt = 0; mt < 4; mt++)
        #pragma unroll
        for (int r2 = 0; r2 < 2; r2++) {
            int m = mrb + mt * 16 + r2 * 8;
            int pos = m & (SEQ - 1);
            #pragma unroll
            for (int nt = 0; nt < 8; nt++) {
                int n = ncb + nt * 8;
                float v0 = d[mt][nt][r2 * 2], v1 = d[mt][nt][r2 * 2 + 1];
                float o0, o1;
                if (z < 2) {
                    int j = n >> 1;
                    float C = ct[pos * 128 + j], S = st[pos * 128 + j];
                    o0 = v0 * C - v1 * S;
                    o1 = v1 * C + v0 * S;
                } else {
                    o0 = v0; o1 = v1;
                }
                float h0f = __bfloat162float(__float2bfloat16(o0));
                float h1f = __bfloat162float(__float2bfloat16(o1));
                uint32_t hp = bf16pair(o0, o1);
                uint32_t mp = bf16pair(o0 - h0f, o1 - h1f);
                *(uint32_t*)(O + (size_t)m * 512 + n)       = hp;
                *(uint32_t*)(O + (size_t)m * 512 + 256 + n) = mp;
            }
        }
}

// ---------------- banded retention attention on mma.sync bf16 (split-3) ----------------
// CTA = 64 queries, key tiles of 64; smem: Q 64KB + 2x64KB K/V bufs + 16KB S staging.
#define ASM_Q  0
#define ASM_B0 65536
#define ASM_B1 131072
#define ASM_S  196608
#define ATTN_SMEM 212992

__device__ __forceinline__ uint32_t swz64(uint32_t row, uint32_t cc) {   // 1024B rows
    return row * 1024u + (((cc & 56u) | ((cc ^ row) & 7u)) << 4);
}
__device__ __forceinline__ uint32_t swzS(uint32_t row, uint32_t cc) {    // 256B rows
    return row * 256u + (((cc & 8u) | ((cc ^ row) & 7u)) << 4);
}

__global__ void __launch_bounds__(256, 1) attn_mma_kernel(float* __restrict__ out)
{
    extern __shared__ __align__(1024) char sm[];
    uint32_t smb = smem_u32(sm);
    int tid = threadIdx.x;
    int b = blockIdx.y;
    int q0 = blockIdx.x * 64;
    size_t base = (size_t)b * SEQ;

    // per-thread tile-copy geometry: 16 chunks of 16B (64KB tile / 256 threads)
    // chunk id: row = id>>6, cc = id&63
    // Q load (group 1, shared with K0)
    #pragma unroll
    for (int i = 0; i < 16; i++) {
        int id = tid + i * 256;
        uint32_t row = (uint32_t)(id >> 6), cc = (uint32_t)(id & 63);
        cp16(smb + ASM_Q + swz64(row, cc), g_Qb + (base + q0 + row) * 512 + cc * 8);
    }
    int kt_lo = q0 - DW; if (kt_lo < 0) kt_lo = 0;
    int nt = ((q0 - kt_lo) >> 6) + 1;
    #pragma unroll
    for (int i = 0; i < 16; i++) {
        int id = tid + i * 256;
        uint32_t row = (uint32_t)(id >> 6), cc = (uint32_t)(id & 63);
        cp16(smb + ASM_B0 + swz64(row, cc), g_Kb + (base + kt_lo + row) * 512 + cc * 8);
    }
    CP_COMMIT();
    #pragma unroll
    for (int i = 0; i < 16; i++) {
        int id = tid + i * 256;
        uint32_t row = (uint32_t)(id >> 6), cc = (uint32_t)(id & 63);
        cp16(smb + ASM_B1 + swz64(row, cc), g_Vb + (base + kt_lo + row) * 512 + cc * 8);
    }
    CP_COMMIT();

    int w = tid >> 5, l = tid & 31;
    int wm = w >> 2, wn = w & 3;          // 2 M-halves x 4 N-quarters
    uint32_t la = (uint32_t)(l & 15), hsel = (uint32_t)(l >> 4);

    float o[2][8][4];
    #pragma unroll
    for (int mt = 0; mt < 2; mt++)
        #pragma unroll
        for (int j = 0; j < 8; j++)
            #pragma unroll
            for (int r = 0; r < 4; r++) o[mt][j][r] = 0.0f;

    for (int it = 0; it < nt; it++) {
        int kt = kt_lo + it * 64;

        CP_WAIT(1);
        __syncthreads();                  // K(it) ready in B0 (and Q on it=0)

        // ---- phase 1: S = Q * K^T (64x64), split-3 ----
        float sacc[2][2][4];
        #pragma unroll
        for (int mt = 0; mt < 2; mt++)
            #pragma unroll
            for (int nti = 0; nti < 2; nti++)
                #pragma unroll
                for (int r = 0; r < 4; r++) sacc[mt][nti][r] = 0.0f;

        #pragma unroll 4
        for (int ks = 0; ks < 16; ks++) {
            uint32_t qh[2][4], qm[2][4];
            #pragma unroll
            for (int mt = 0; mt < 2; mt++) {
                uint32_t row = (uint32_t)(wm * 32 + mt * 16) + la;
                ldsm4(qh[mt], smb + ASM_Q + swz64(row, (uint32_t)(ks * 2) + hsel));
                ldsm4(qm[mt], smb + ASM_Q + swz64(row, 32u + (uint32_t)(ks * 2) + hsel));
            }
            uint32_t kh[4], km[4];
            {
                uint32_t row = (uint32_t)(wn * 16) + la;
                ldsm4(kh, smb + ASM_B0 + swz64(row, (uint32_t)(ks * 2) + hsel));
                ldsm4(km, smb + ASM_B0 + swz64(row, 32u + (uint32_t)(ks * 2) + hsel));
            }
            #pragma unroll
            for (int mt = 0; mt < 2; mt++)
                #pragma unroll
                for (int nti = 0; nti < 2; nti++) {
                    float* dd = sacc[mt][nti];
                    mma16816(dd, qh[mt], kh[nti], kh[nti + 2]);   // hi*hi
                    mma16816(dd, qh[mt], km[nti], km[nti + 2]);   // hi*mid
                    mma16816(dd, qm[mt], kh[nti], kh[nti + 2]);   // mid*hi
                }
        }

        // ---- decay + bf16 split + stage S ----
        int dq = q0 - kt;
        #pragma unroll
        for (int mt = 0; mt < 2; mt++)
            #pragma unroll
            for (int nti = 0; nti < 2; nti++) {
                int qr0 = wm * 32 + mt * 16 + (l >> 2);
                int key = wn * 16 + nti * 8 + (l & 3) * 2;
                #pragma unroll
                for (int h = 0; h < 2; h++) {
                    int q = qr0 + 8 * h;
                    int e0 = dq + q - key;
                    float g0 = (e0 >= 0) ? g_gamma[e0] : 0.0f;
                    float g1 = (e0 >= 1) ? g_gamma[e0 - 1] : 0.0f;
                    float s0 = sacc[mt][nti][2 * h] * g0;
                    float s1 = sacc[mt][nti][2 * h + 1] * g1;
                    float h0f = __bfloat162float(__float2bfloat16(s0));
                    float h1f = __bfloat162float(__float2bfloat16(s1));
                    uint32_t hp = bf16pair(s0, s1);
                    uint32_t mp = bf16pair(s0 - h0f, s1 - h1f);
                    uint32_t cc = (uint32_t)(key >> 3);
                    uint32_t inb = (uint32_t)((key & 7) * 2);
                    *(uint32_t*)(sm + ASM_S + swzS((uint32_t)q, cc) + inb)      = hp;
                    *(uint32_t*)(sm + ASM_S + swzS((uint32_t)q, 8u + cc) + inb) = mp;
                }
            }
        __syncthreads();                  // Ss published; B0 free

        if (it + 1 < nt) {
            #pragma unroll
            for (int i = 0; i < 16; i++) {
                int id = tid + i * 256;
                uint32_t row = (uint32_t)(id >> 6), cc = (uint32_t)(id & 63);
                cp16(smb + ASM_B0 + swz64(row, cc),
                     g_Kb + (base + kt + 64 + row) * 512 + cc * 8);
            }
            CP_COMMIT();
            CP_WAIT(1);
        } else {
            CP_WAIT(0);
        }
        __syncthreads();                  // V(it) ready in B1

        // ---- phase 2: O += S * V (64x256), split-3 ----
        #pragma unroll
        for (int ks2 = 0; ks2 < 4; ks2++) {
            uint32_t sh[2][4], sd[2][4];
            #pragma unroll
            for (int mt = 0; mt < 2; mt++) {
                uint32_t row = (uint32_t)(wm * 32 + mt * 16) + la;
                ldsm4(sh[mt], smb + ASM_S + swzS(row, (uint32_t)(ks2 * 2) + hsel));
                ldsm4(sd[mt], smb + ASM_S + swzS(row, 8u + (uint32_t)(ks2 * 2) + hsel));
            }
            uint32_t vrow = (uint32_t)(ks2 * 16) + la;
            #pragma unroll
            for (int j = 0; j < 4; j++) {
                uint32_t vh[4], vm[4];
                uint32_t cc = (uint32_t)(wn * 8 + j * 2) + hsel;
                ldsm4t(vh, smb + ASM_B1 + swz64(vrow, cc));
                ldsm4t(vm, smb + ASM_B1 + swz64(vrow, 32u + cc));
                #pragma unroll
                for (int nti = 0; nti < 2; nti++) {
                    uint32_t b0h = vh[nti * 2], b1h = vh[nti * 2 + 1];
                    uint32_t b0m = vm[nti * 2], b1m = vm[nti * 2 + 1];
                    #pragma unroll
                    for (int mt = 0; mt < 2; mt++) {
                        float* dd = o[mt][j * 2 + nti];
                        mma16816(dd, sh[mt], b0h, b1h);   // Sh*Vh
                        mma16816(dd, sh[mt], b0m, b1m);   // Sh*Vm
                        mma16816(dd, sd[mt], b0h, b1h);   // Sm*Vh
                    }
                }
            }
        }
        __syncthreads();                  // B1 free

        if (it + 1 < nt) {
            #pragma unroll
            for (int i = 0; i < 16; i++) {
                int id = tid + i * 256;
                uint32_t row = (uint32_t)(id >> 6), cc = (uint32_t)(id & 63);
                cp16(smb + ASM_B1 + swz64(row, cc),
                     g_Vb + (base + kt + 64 + row) * 512 + cc * 8);
            }
            CP_COMMIT();
        }
    }

    // ---- store O (fp32) ----
    #pragma unroll
    for (int mt = 0; mt < 2; mt++)
        #pragma unroll
        for (int h = 0; h < 2; h++) {
            int q = q0 + wm * 32 + mt * 16 + (l >> 2) + 8 * h;
            size_t ro = (base + q) * (size_t)HD;
            #pragma unroll
            for (int j = 0; j < 8; j++) {
                int vd = wn * 64 + j * 8 + (l & 3) * 2;
                float2 v;
                v.x = o[mt][j][2 * h];
                v.y = o[mt][j][2 * h + 1];
                *(float2*)(out + ro + vd) = v;
            }
        }
}

// ---------------- launch ----------------
extern "C" void kernel_launch(void* const* d_in, const int* in_sizes, int n_in,
                              void* d_out, int out_size) {
    const float* X  = (const float*)d_in[0];
    const float* WQ = (const float*)d_in[1];
    const float* WK = (const float*)d_in[2];
    const float* WV = (const float*)d_in[3];
    float* out = (float*)d_out;

    const_kernel<<<16, 256>>>();
    tables_kernel<<<SEQ, 128>>>();

    splitx_kernel<<<(MTOT * HID / 4) / 256, 256>>>(X);
    splitw_kernel<<<(3 * HID * HD) / 256, 256>>>(WQ, WK, WV);

    cudaFuncSetAttribute(proj_mma_kernel, cudaFuncAttributeMaxDynamicSharedMemorySize,
                         PROJ_SMEM);
    dim3 pg(3, MTOT / 128);
    proj_mma_kernel<<<pg, 256, PROJ_SMEM>>>();

    cudaFuncSetAttribute(attn_mma_kernel, cudaFuncAttributeMaxDynamicSharedMemorySize,
                         ATTN_SMEM);
    dim3 ag(SEQ / 64, NB);
    attn_mma_kernel<<<ag, 256, ATTN_SMEM>>>(out);
}

// round 7
// speedup vs baseline: 2.8182x; 1.1611x over previous
#include <cuda_runtime.h>
#include <cuda_bf16.h>
#include <cuda_fp16.h>
#include <math.h>
#include <stdint.h>

#define SEQ 4096
#define NB 4
#define HID 1024
#define HD 256
#define MTOT (NB*SEQ)
#define DW 512            // gamma^513 ~ 8.5e-8, far below rel-err threshold

typedef unsigned long long u64;

// ---------------- static device scratch (no cudaMalloc allowed) ----------------
// Q/K/V stored as packed bf16 (hi,mid): row layout [term0 d0..255][term1 d0..255]
__device__ __nv_bfloat16 g_Qb[(size_t)MTOT*512];
__device__ __nv_bfloat16 g_Kb[(size_t)MTOT*512];
__device__ __nv_bfloat16 g_Vb[(size_t)MTOT*512];
__device__ __half g_Xh[(size_t)MTOT*HID];   // X as plain fp16 (split-2 scheme)
__device__ __half g_Wh[3*HID*HD];           // [z][k][n], W*1024 hi
__device__ __half g_Wm[3*HID*HD];           // [z][k][n], W*1024 mid
__device__ float g_cosQ[SEQ*128];
__device__ float g_sinQ[SEQ*128];
__device__ float g_cosK[SEQ*128];
__device__ float g_sinK[SEQ*128];
__device__ float g_gamma[SEQ];
__device__ double g_invf[128];
__device__ double g_l2sb[128];

// ---------------- mma / async helpers (baseline PTX, sm_80+ ISA only) ----------------
__device__ __forceinline__ uint32_t smem_u32(const void* p) {
    uint32_t a;
    asm("{ .reg .u64 t; cvta.to.shared.u64 t, %1; cvt.u32.u64 %0, t; }" : "=r"(a) : "l"(p));
    return a;
}
__device__ __forceinline__ void cp16(uint32_t dst, const void* src) {
    asm volatile("cp.async.cg.shared.global [%0], [%1], 16;" :: "r"(dst), "l"(src));
}
#define CP_COMMIT()  asm volatile("cp.async.commit_group;" ::: "memory")
#define CP_WAIT(n)   asm volatile("cp.async.wait_group %0;" :: "n"(n) : "memory")

__device__ __forceinline__ void ldsm4(uint32_t (&r)[4], uint32_t a) {
    asm volatile("ldmatrix.sync.aligned.m8n8.x4.shared.b16 {%0,%1,%2,%3}, [%4];"
                 : "=r"(r[0]), "=r"(r[1]), "=r"(r[2]), "=r"(r[3]) : "r"(a));
}
__device__ __forceinline__ void ldsm4t(uint32_t (&r)[4], uint32_t a) {
    asm volatile("ldmatrix.sync.aligned.m8n8.x4.trans.shared.b16 {%0,%1,%2,%3}, [%4];"
                 : "=r"(r[0]), "=r"(r[1]), "=r"(r[2]), "=r"(r[3]) : "r"(a));
}
__device__ __forceinline__ void mma16816(float* d, const uint32_t* a, uint32_t b0, uint32_t b1) {
    asm volatile(
        "mma.sync.aligned.m16n8k16.row.col.f32.bf16.bf16.f32 "
        "{%0,%1,%2,%3}, {%4,%5,%6,%7}, {%8,%9}, {%0,%1,%2,%3};"
        : "+f"(d[0]), "+f"(d[1]), "+f"(d[2]), "+f"(d[3])
        : "r"(a[0]), "r"(a[1]), "r"(a[2]), "r"(a[3]), "r"(b0), "r"(b1));
}
__device__ __forceinline__ void mma16816h(float* d, const uint32_t* a, uint32_t b0, uint32_t b1) {
    asm volatile(
        "mma.sync.aligned.m16n8k16.row.col.f32.f16.f16.f32 "
        "{%0,%1,%2,%3}, {%4,%5,%6,%7}, {%8,%9}, {%0,%1,%2,%3};"
        : "+f"(d[0]), "+f"(d[1]), "+f"(d[2]), "+f"(d[3])
        : "r"(a[0]), "r"(a[1]), "r"(a[2]), "r"(a[3]), "r"(b0), "r"(b1));
}
__device__ __forceinline__ uint32_t bf16pair(float a, float b) {
    __nv_bfloat162 t; t.x = __float2bfloat16(a); t.y = __float2bfloat16(b);
    uint32_t r; asm("mov.b32 %0, %1;" : "=r"(r) : "r"(*(uint32_t*)&t)); return r;
}

// ---------------- constants ----------------
__global__ void const_kernel() {
    int t = blockIdx.x * blockDim.x + threadIdx.x;
    if (t < 128) {
        g_invf[t] = pow(10000.0, -(double)t / 128.0);
        double sb = ((double)(2 * t) + 0.4 * 256.0) / (1.4 * 256.0);
        g_l2sb[t] = log2(sb);
    }
    if (t < SEQ) g_gamma[t] = (float)pow(0.96875, (double)t);
}

// ---------------- xpos sin/cos/scale tables ----------------
__global__ void tables_kernel() {
    int pos = blockIdx.x, j = threadIdx.x;
    float invf = (float)g_invf[j];
    float arg = (float)pos * invf;
    double ad = (double)arg;
    double qd = rint(ad * 0.63661977236758134308);
    double rd = fma(qd, -1.5707963267948966, ad);
    rd = fma(qd, -6.123233995736766e-17, rd);
    int qi = ((long long)qd) & 3;
    float rf = (float)rd;
    float sr = sinf(rf), cr = cosf(rf);
    float s, c;
    if      (qi == 0) { s =  sr; c =  cr; }
    else if (qi == 1) { s =  cr; c = -sr; }
    else if (qi == 2) { s = -sr; c = -cr; }
    else              { s = -cr; c =  sr; }
    float p  = (float)pos * (1.0f / 512.0f);
    float l2 = (float)g_l2sb[j];
    float sc  = exp2f(p * l2);
    float isc = exp2f(-p * l2);
    int idx = pos * 128 + j;
    g_cosQ[idx] = c * sc;   g_sinQ[idx] = s * sc;
    g_cosK[idx] = c * isc;  g_sinK[idx] = s * isc;
}

// ---------------- prep: X -> fp16; W*1024 -> fp16 (hi, mid) ----------------
__global__ void splitx_kernel(const float* __restrict__ X) {
    size_t i = (size_t)blockIdx.x * blockDim.x + threadIdx.x;   // 4 floats each
    float4 x = ((const float4*)X)[i];
    __half2* ph = (__half2*)g_Xh;
    __half2 a;
    a.x = __float2half(x.x); a.y = __float2half(x.y); ph[2*i]   = a;
    a.x = __float2half(x.z); a.y = __float2half(x.w); ph[2*i+1] = a;
}

__global__ void splitw_kernel(const float* __restrict__ WQ,
                              const float* __restrict__ WK,
                              const float* __restrict__ WV) {
    int idx = blockIdx.x * blockDim.x + threadIdx.x;   // [z][k][n], 3*1024*256
    int z = idx >> 18;
    int kn = idx & 0x3FFFF;
    const float* W = (z == 0) ? WQ : (z == 1 ? WK : WV);
    float w = W[kn] * 1024.0f;          // scale into fp16-normal range
    __half h = __float2half(w);
    g_Wh[idx] = h;
    g_Wm[idx] = __float2half(w - __half2float(h));
}

// ---------------- projection GEMM on mma.sync fp16 (split-2) ----------------
// CTA = 128M x 256N, K=1024 in 32 stages of KC=32, cp.async double-buffered.
// A smem: 128 rows x 64B (fp16 X), 80B stride -> bank-conflict-free, 10240B.
// B smem: 32 k-rows x [hi 512B | mid 512B] = 1024B rows, XOR swizzle, 32KB.
#define PKC 32
#define PSTG_A 10240
#define PSTG_BYTES (PSTG_A + 32768)
#define PROJ_SMEM (2 * PSTG_BYTES)

__global__ void __launch_bounds__(256, 1) proj_mma_kernel()
{
    extern __shared__ __align__(1024) char sm[];
    uint32_t smb = smem_u32(sm);
    int tid = threadIdx.x;
    int z = blockIdx.x;
    int m0 = blockIdx.y * 128;

    const __half* Wh = g_Wh + (size_t)z * HID * HD;
    const __half* Wm = g_Wm + (size_t)z * HID * HD;

    // A copy: 2 chunks/thread (512 chunks of 16B)
    const __half* srcA[2]; uint32_t dstA[2];
    #pragma unroll
    for (int i = 0; i < 2; i++) {
        int id = tid + i * 256;
        int m = id >> 2, c = id & 3;
        srcA[i] = g_Xh + (size_t)(m0 + m) * HID + c * 8;
        dstA[i] = (uint32_t)(m * 80 + c * 16);
    }
    // B copy: 8 chunks/thread (2048 chunks)
    const __half* srcB[8]; uint32_t dstB[8];
    #pragma unroll
    for (int i = 0; i < 8; i++) {
        int id = tid + i * 256;
        int k = id >> 6, cc = id & 63;
        int term = cc >> 5, n_c = cc & 31;
        srcB[i] = (term ? Wm : Wh) + (size_t)k * HD + n_c * 8;
        dstB[i] = (uint32_t)(PSTG_A + k * 1024 + ((cc ^ (k & 7)) << 4));
    }

    int w = tid >> 5, l = tid & 31;
    int wm = (w >> 2) * 64, wn = (w & 3) * 64;
    int la = l & 15, hsel = l >> 4;
    uint32_t bmx = (uint32_t)(la & 7);
    uint32_t brow = (uint32_t)(la * 1024);
    uint32_t bnc0 = (uint32_t)(wn >> 3);

    float d[4][8][4];
    #pragma unroll
    for (int mt = 0; mt < 4; mt++)
        #pragma unroll
        for (int nt = 0; nt < 8; nt++)
            #pragma unroll
            for (int r = 0; r < 4; r++) d[mt][nt][r] = 0.0f;

    {
        uint32_t bb = smb;
        #pragma unroll
        for (int i = 0; i < 2; i++) cp16(bb + dstA[i], srcA[i]);
        #pragma unroll
        for (int i = 0; i < 8; i++) cp16(bb + dstB[i], srcB[i]);
        CP_COMMIT();
    }

    for (int s = 0; s < 32; s++) {
        if (s + 1 < 32) {
            uint32_t bb = smb + (uint32_t)((s + 1) & 1) * PSTG_BYTES;
            int kt = (s + 1) * PKC;
            #pragma unroll
            for (int i = 0; i < 2; i++) cp16(bb + dstA[i], srcA[i] + kt);
            #pragma unroll
            for (int i = 0; i < 8; i++) cp16(bb + dstB[i], srcB[i] + (size_t)kt * HD);
            CP_COMMIT();
            CP_WAIT(1);
        } else {
            CP_WAIT(0);
        }
        __syncthreads();

        uint32_t AS = smb + (uint32_t)(s & 1) * PSTG_BYTES;
        uint32_t BS = AS + PSTG_A;

        #pragma unroll
        for (int slab = 0; slab < 2; slab++) {          // two k16 slabs
            uint32_t ah[4][4];
            #pragma unroll
            for (int mt = 0; mt < 4; mt++) {
                uint32_t row = (uint32_t)(wm + mt * 16 + la);
                ldsm4(ah[mt], AS + row * 80 + (uint32_t)((slab * 2 + hsel) * 16));
            }
            uint32_t krow = BS + (uint32_t)(slab * 16 * 1024) + brow;
            #pragma unroll
            for (int half = 0; half < 2; half++) {
                uint32_t bh[2][4], bm[2][4];
                #pragma unroll
                for (int j2 = 0; j2 < 2; j2++) {
                    uint32_t nc = bnc0 + (uint32_t)(half * 4 + j2 * 2 + hsel);
                    ldsm4t(bh[j2], krow + (((nc)       ^ bmx) << 4));
                    ldsm4t(bm[j2], krow + (((nc + 32u) ^ bmx) << 4));
                }
                #pragma unroll
                for (int nt = 0; nt < 4; nt++) {
                    uint32_t h0 = bh[nt >> 1][(nt & 1) * 2], h1 = bh[nt >> 1][(nt & 1) * 2 + 1];
                    uint32_t q0 = bm[nt >> 1][(nt & 1) * 2], q1 = bm[nt >> 1][(nt & 1) * 2 + 1];
                    #pragma unroll
                    for (int mt = 0; mt < 4; mt++) {
                        float* dd = d[mt][half * 4 + nt];
                        mma16816h(dd, ah[mt], h0, h1);   // Xh * Wh
                        mma16816h(dd, ah[mt], q0, q1);   // Xh * Wm
                    }
                }
            }
        }
        __syncthreads();
    }

    // ---- epilogue: unscale (W was x1024) + rotary (Q,K) + bf16 hi/mid pack + store ----
    __nv_bfloat16* O = (z == 0) ? g_Qb : (z == 1 ? g_Kb : g_Vb);
    const float* ct = (z == 0) ? g_cosQ : g_cosK;
    const float* st = (z == 0) ? g_sinQ : g_sinK;
    const float DS = 0.0009765625f;     // 2^-10
    int mrb = m0 + wm + (l >> 2);
    int ncb = wn + (l & 3) * 2;
    #pragma unroll
    for (int mt = 0; mt < 4; mt++)
        #pragma unroll
        for (int r2 = 0; r2 < 2; r2++) {
            int m = mrb + mt * 16 + r2 * 8;
            int pos = m & (SEQ - 1);
            #pragma unroll
            for (int nt = 0; nt < 8; nt++) {
                int n = ncb + nt * 8;
                float v0 = d[mt][nt][r2 * 2] * DS, v1 = d[mt][nt][r2 * 2 + 1] * DS;
                float o0, o1;
                if (z < 2) {
                    int j = n >> 1;
                    float C = ct[pos * 128 + j], S = st[pos * 128 + j];
                    o0 = v0 * C - v1 * S;
                    o1 = v1 * C + v0 * S;
                } else {
                    o0 = v0; o1 = v1;
                }
                float h0f = __bfloat162float(__float2bfloat16(o0));
                float h1f = __bfloat162float(__float2bfloat16(o1));
                uint32_t hp = bf16pair(o0, o1);
                uint32_t mp = bf16pair(o0 - h0f, o1 - h1f);
                *(uint32_t*)(O + (size_t)m * 512 + n)       = hp;
                *(uint32_t*)(O + (size_t)m * 512 + 256 + n) = mp;
            }
        }
}

// ---------------- banded retention attention on mma.sync bf16 (split-3) ----------------
#define ASM_Q  0
#define ASM_B0 65536
#define ASM_B1 131072
#define ASM_S  196608
#define ATTN_SMEM 212992

__device__ __forceinline__ uint32_t swz64(uint32_t row, uint32_t cc) {   // 1024B rows
    return row * 1024u + (((cc & 56u) | ((cc ^ row) & 7u)) << 4);
}
__device__ __forceinline__ uint32_t swzS(uint32_t row, uint32_t cc) {    // 256B rows
    return row * 256u + (((cc & 8u) | ((cc ^ row) & 7u)) << 4);
}

__global__ void __launch_bounds__(256, 1) attn_mma_kernel(float* __restrict__ out)
{
    extern __shared__ __align__(1024) char sm[];
    uint32_t smb = smem_u32(sm);
    int tid = threadIdx.x;
    int b = blockIdx.y;
    int q0 = blockIdx.x * 64;
    size_t base = (size_t)b * SEQ;

    #pragma unroll
    for (int i = 0; i < 16; i++) {
        int id = tid + i * 256;
        uint32_t row = (uint32_t)(id >> 6), cc = (uint32_t)(id & 63);
        cp16(smb + ASM_Q + swz64(row, cc), g_Qb + (base + q0 + row) * 512 + cc * 8);
    }
    int kt_lo = q0 - DW; if (kt_lo < 0) kt_lo = 0;
    int nt = ((q0 - kt_lo) >> 6) + 1;
    #pragma unroll
    for (int i = 0; i < 16; i++) {
        int id = tid + i * 256;
        uint32_t row = (uint32_t)(id >> 6), cc = (uint32_t)(id & 63);
        cp16(smb + ASM_B0 + swz64(row, cc), g_Kb + (base + kt_lo + row) * 512 + cc * 8);
    }
    CP_COMMIT();
    #pragma unroll
    for (int i = 0; i < 16; i++) {
        int id = tid + i * 256;
        uint32_t row = (uint32_t)(id >> 6), cc = (uint32_t)(id & 63);
        cp16(smb + ASM_B1 + swz64(row, cc), g_Vb + (base + kt_lo + row) * 512 + cc * 8);
    }
    CP_COMMIT();

    int w = tid >> 5, l = tid & 31;
    int wm = w >> 2, wn = w & 3;
    uint32_t la = (uint32_t)(l & 15), hsel = (uint32_t)(l >> 4);

    float o[2][8][4];
    #pragma unroll
    for (int mt = 0; mt < 2; mt++)
        #pragma unroll
        for (int j = 0; j < 8; j++)
            #pragma unroll
            for (int r = 0; r < 4; r++) o[mt][j][r] = 0.0f;

    for (int it = 0; it < nt; it++) {
        int kt = kt_lo + it * 64;

        CP_WAIT(1);
        __syncthreads();

        float sacc[2][2][4];
        #pragma unroll
        for (int mt = 0; mt < 2; mt++)
            #pragma unroll
            for (int nti = 0; nti < 2; nti++)
                #pragma unroll
                for (int r = 0; r < 4; r++) sacc[mt][nti][r] = 0.0f;

        #pragma unroll 4
        for (int ks = 0; ks < 16; ks++) {
            uint32_t qh[2][4], qm[2][4];
            #pragma unroll
            for (int mt = 0; mt < 2; mt++) {
                uint32_t row = (uint32_t)(wm * 32 + mt * 16) + la;
                ldsm4(qh[mt], smb + ASM_Q + swz64(row, (uint32_t)(ks * 2) + hsel));
                ldsm4(qm[mt], smb + ASM_Q + swz64(row, 32u + (uint32_t)(ks * 2) + hsel));
            }
            uint32_t kh[4], km[4];
            {
                uint32_t row = (uint32_t)(wn * 16) + la;
                ldsm4(kh, smb + ASM_B0 + swz64(row, (uint32_t)(ks * 2) + hsel));
                ldsm4(km, smb + ASM_B0 + swz64(row, 32u + (uint32_t)(ks * 2) + hsel));
            }
            #pragma unroll
            for (int mt = 0; mt < 2; mt++)
                #pragma unroll
                for (int nti = 0; nti < 2; nti++) {
                    float* dd = sacc[mt][nti];
                    mma16816(dd, qh[mt], kh[nti], kh[nti + 2]);
                    mma16816(dd, qh[mt], km[nti], km[nti + 2]);
                    mma16816(dd, qm[mt], kh[nti], kh[nti + 2]);
                }
        }

        int dq = q0 - kt;
        #pragma unroll
        for (int mt = 0; mt < 2; mt++)
            #pragma unroll
            for (int nti = 0; nti < 2; nti++) {
                int qr0 = wm * 32 + mt * 16 + (l >> 2);
                int key = wn * 16 + nti * 8 + (l & 3) * 2;
                #pragma unroll
                for (int h = 0; h < 2; h++) {
                    int q = qr0 + 8 * h;
                    int e0 = dq + q - key;
                    float g0 = (e0 >= 0) ? g_gamma[e0] : 0.0f;
                    float g1 = (e0 >= 1) ? g_gamma[e0 - 1] : 0.0f;
                    float s0 = sacc[mt][nti][2 * h] * g0;
                    float s1 = sacc[mt][nti][2 * h + 1] * g1;
                    float h0f = __bfloat162float(__float2bfloat16(s0));
                    float h1f = __bfloat162float(__float2bfloat16(s1));
                    uint32_t hp = bf16pair(s0, s1);
                    uint32_t mp = bf16pair(s0 - h0f, s1 - h1f);
                    uint32_t cc = (uint32_t)(key >> 3);
                    uint32_t inb = (uint32_t)((key & 7) * 2);
                    *(uint32_t*)(sm + ASM_S + swzS((uint32_t)q, cc) + inb)      = hp;
                    *(uint32_t*)(sm + ASM_S + swzS((uint32_t)q, 8u + cc) + inb) = mp;
                }
            }
        __syncthreads();

        if (it + 1 < nt) {
            #pragma unroll
            for (int i = 0; i < 16; i++) {
                int id = tid + i * 256;
                uint32_t row = (uint32_t)(id >> 6), cc = (uint32_t)(id & 63);
                cp16(smb + ASM_B0 + swz64(row, cc),
                     g_Kb + (base + kt + 64 + row) * 512 + cc * 8);
            }
            CP_COMMIT();
            CP_WAIT(1);
        } else {
            CP_WAIT(0);
        }
        __syncthreads();

        #pragma unroll
        for (int ks2 = 0; ks2 < 4; ks2++) {
            uint32_t sh[2][4], sd[2][4];
            #pragma unroll
            for (int mt = 0; mt < 2; mt++) {
                uint32_t row = (uint32_t)(wm * 32 + mt * 16) + la;
                ldsm4(sh[mt], smb + ASM_S + swzS(row, (uint32_t)(ks2 * 2) + hsel));
                ldsm4(sd[mt], smb + ASM_S + swzS(row, 8u + (uint32_t)(ks2 * 2) + hsel));
            }
            uint32_t vrow = (uint32_t)(ks2 * 16) + la;
            #pragma unroll
            for (int j = 0; j < 4; j++) {
                uint32_t vh[4], vm[4];
                uint32_t cc = (uint32_t)(wn * 8 + j * 2) + hsel;
                ldsm4t(vh, smb + ASM_B1 + swz64(vrow, cc));
                ldsm4t(vm, smb + ASM_B1 + swz64(vrow, 32u + cc));
                #pragma unroll
                for (int nti = 0; nti < 2; nti++) {
                    uint32_t b0h = vh[nti * 2], b1h = vh[nti * 2 + 1];
                    uint32_t b0m = vm[nti * 2], b1m = vm[nti * 2 + 1];
                    #pragma unroll
                    for (int mt = 0; mt < 2; mt++) {
                        float* dd = o[mt][j * 2 + nti];
                        mma16816(dd, sh[mt], b0h, b1h);
                        mma16816(dd, sh[mt], b0m, b1m);
                        mma16816(dd, sd[mt], b0h, b1h);
                    }
                }
            }
        }
        __syncthreads();

        if (it + 1 < nt) {
            #pragma unroll
            for (int i = 0; i < 16; i++) {
                int id = tid + i * 256;
                uint32_t row = (uint32_t)(id >> 6), cc = (uint32_t)(id & 63);
                cp16(smb + ASM_B1 + swz64(row, cc),
                     g_Vb + (base + kt + 64 + row) * 512 + cc * 8);
            }
            CP_COMMIT();
        }
    }

    #pragma unroll
    for (int mt = 0; mt < 2; mt++)
        #pragma unroll
        for (int h = 0; h < 2; h++) {
            int q = q0 + wm * 32 + mt * 16 + (l >> 2) + 8 * h;
            size_t ro = (base + q) * (size_t)HD;
            #pragma unroll
            for (int j = 0; j < 8; j++) {
                int vd = wn * 64 + j * 8 + (l & 3) * 2;
                float2 v;
                v.x = o[mt][j][2 * h];
                v.y = o[mt][j][2 * h + 1];
                *(float2*)(out + ro + vd) = v;
            }
        }
}

// ---------------- launch ----------------
extern "C" void kernel_launch(void* const* d_in, const int* in_sizes, int n_in,
                              void* d_out, int out_size) {
    const float* X  = (const float*)d_in[0];
    const float* WQ = (const float*)d_in[1];
    const float* WK = (const float*)d_in[2];
    const float* WV = (const float*)d_in[3];
    float* out = (float*)d_out;

    const_kernel<<<16, 256>>>();
    tables_kernel<<<SEQ, 128>>>();

    splitx_kernel<<<(MTOT * HID / 4) / 256, 256>>>(X);
    splitw_kernel<<<(3 * HID * HD) / 256, 256>>>(WQ, WK, WV);

    cudaFuncSetAttribute(proj_mma_kernel, cudaFuncAttributeMaxDynamicSharedMemorySize,
                         PROJ_SMEM);
    dim3 pg(3, MTOT / 128);
    proj_mma_kernel<<<pg, 256, PROJ_SMEM>>>();

    cudaFuncSetAttribute(attn_mma_kernel, cudaFuncAttributeMaxDynamicSharedMemorySize,
                         ATTN_SMEM);
    dim3 ag(SEQ / 64, NB);
    attn_mma_kernel<<<ag, 256, ATTN_SMEM>>>(out);
}

// round 8
// speedup vs baseline: 2.9839x; 1.0588x over previous
#include <cuda_runtime.h>
#include <cuda_bf16.h>
#include <cuda_fp16.h>
#include <math.h>
#include <stdint.h>

#define SEQ 4096
#define NB 4
#define HID 1024
#define HD 256
#define MTOT (NB*SEQ)
#define DW 512            // gamma^513 ~ 8.5e-8, far below rel-err threshold

typedef unsigned long long u64;

// ---------------- static device scratch (no cudaMalloc allowed) ----------------
// Q/K stored as packed bf16 (hi,mid): row layout [term0 d0..255][term1 d0..255]
__device__ __nv_bfloat16 g_Qb[(size_t)MTOT*512];
__device__ __nv_bfloat16 g_Kb[(size_t)MTOT*512];
__device__ __half g_Vf[(size_t)MTOT*HD];    // V as plain fp16 (no xpos scale -> fp16-safe)
__device__ __half g_Xh[(size_t)MTOT*HID];   // X as plain fp16 (split-2 scheme)
__device__ __half g_Wh[3*HID*HD];           // [z][k][n], W*1024 hi
__device__ __half g_Wm[3*HID*HD];           // [z][k][n], W*1024 mid
__device__ float g_cosQ[SEQ*128];
__device__ float g_sinQ[SEQ*128];
__device__ float g_cosK[SEQ*128];
__device__ float g_sinK[SEQ*128];
__device__ float g_gamma[SEQ];
__device__ double g_invf[128];
__device__ double g_l2sb[128];

// ---------------- mma / async helpers (baseline PTX, sm_80+ ISA only) ----------------
__device__ __forceinline__ uint32_t smem_u32(const void* p) {
    uint32_t a;
    asm("{ .reg .u64 t; cvta.to.shared.u64 t, %1; cvt.u32.u64 %0, t; }" : "=r"(a) : "l"(p));
    return a;
}
__device__ __forceinline__ void cp16(uint32_t dst, const void* src) {
    asm volatile("cp.async.cg.shared.global [%0], [%1], 16;" :: "r"(dst), "l"(src));
}
#define CP_COMMIT()  asm volatile("cp.async.commit_group;" ::: "memory")
#define CP_WAIT(n)   asm volatile("cp.async.wait_group %0;" :: "n"(n) : "memory")

__device__ __forceinline__ void ldsm4(uint32_t (&r)[4], uint32_t a) {
    asm volatile("ldmatrix.sync.aligned.m8n8.x4.shared.b16 {%0,%1,%2,%3}, [%4];"
                 : "=r"(r[0]), "=r"(r[1]), "=r"(r[2]), "=r"(r[3]) : "r"(a));
}
__device__ __forceinline__ void ldsm4t(uint32_t (&r)[4], uint32_t a) {
    asm volatile("ldmatrix.sync.aligned.m8n8.x4.trans.shared.b16 {%0,%1,%2,%3}, [%4];"
                 : "=r"(r[0]), "=r"(r[1]), "=r"(r[2]), "=r"(r[3]) : "r"(a));
}
__device__ __forceinline__ void mma16816(float* d, const uint32_t* a, uint32_t b0, uint32_t b1) {
    asm volatile(
        "mma.sync.aligned.m16n8k16.row.col.f32.bf16.bf16.f32 "
        "{%0,%1,%2,%3}, {%4,%5,%6,%7}, {%8,%9}, {%0,%1,%2,%3};"
        : "+f"(d[0]), "+f"(d[1]), "+f"(d[2]), "+f"(d[3])
        : "r"(a[0]), "r"(a[1]), "r"(a[2]), "r"(a[3]), "r"(b0), "r"(b1));
}
__device__ __forceinline__ void mma16816h(float* d, const uint32_t* a, uint32_t b0, uint32_t b1) {
    asm volatile(
        "mma.sync.aligned.m16n8k16.row.col.f32.f16.f16.f32 "
        "{%0,%1,%2,%3}, {%4,%5,%6,%7}, {%8,%9}, {%0,%1,%2,%3};"
        : "+f"(d[0]), "+f"(d[1]), "+f"(d[2]), "+f"(d[3])
        : "r"(a[0]), "r"(a[1]), "r"(a[2]), "r"(a[3]), "r"(b0), "r"(b1));
}
__device__ __forceinline__ uint32_t bf16pair(float a, float b) {
    __nv_bfloat162 t; t.x = __float2bfloat16(a); t.y = __float2bfloat16(b);
    uint32_t r; asm("mov.b32 %0, %1;" : "=r"(r) : "r"(*(uint32_t*)&t)); return r;
}
__device__ __forceinline__ uint32_t fp16pair(float a, float b) {
    __half2 t; t.x = __float2half(a); t.y = __float2half(b);
    uint32_t r; asm("mov.b32 %0, %1;" : "=r"(r) : "r"(*(uint32_t*)&t)); return r;
}

// ---------------- constants ----------------
__global__ void const_kernel() {
    int t = blockIdx.x * blockDim.x + threadIdx.x;
    if (t < 128) {
        g_invf[t] = pow(10000.0, -(double)t / 128.0);
        double sb = ((double)(2 * t) + 0.4 * 256.0) / (1.4 * 256.0);
        g_l2sb[t] = log2(sb);
    }
    if (t < SEQ) g_gamma[t] = (float)pow(0.96875, (double)t);
}

// ---------------- xpos sin/cos/scale tables ----------------
__global__ void tables_kernel() {
    int pos = blockIdx.x, j = threadIdx.x;
    float invf = (float)g_invf[j];
    float arg = (float)pos * invf;
    double ad = (double)arg;
    double qd = rint(ad * 0.63661977236758134308);
    double rd = fma(qd, -1.5707963267948966, ad);
    rd = fma(qd, -6.123233995736766e-17, rd);
    int qi = ((long long)qd) & 3;
    float rf = (float)rd;
    float sr = sinf(rf), cr = cosf(rf);
    float s, c;
    if      (qi == 0) { s =  sr; c =  cr; }
    else if (qi == 1) { s =  cr; c = -sr; }
    else if (qi == 2) { s = -sr; c = -cr; }
    else              { s = -cr; c =  sr; }
    float p  = (float)pos * (1.0f / 512.0f);
    float l2 = (float)g_l2sb[j];
    float sc  = exp2f(p * l2);
    float isc = exp2f(-p * l2);
    int idx = pos * 128 + j;
    g_cosQ[idx] = c * sc;   g_sinQ[idx] = s * sc;
    g_cosK[idx] = c * isc;  g_sinK[idx] = s * isc;
}

// ---------------- prep: X -> fp16; W*1024 -> fp16 (hi, mid) ----------------
__global__ void splitx_kernel(const float* __restrict__ X) {
    size_t i = (size_t)blockIdx.x * blockDim.x + threadIdx.x;   // 4 floats each
    float4 x = ((const float4*)X)[i];
    __half2* ph = (__half2*)g_Xh;
    __half2 a;
    a.x = __float2half(x.x); a.y = __float2half(x.y); ph[2*i]   = a;
    a.x = __float2half(x.z); a.y = __float2half(x.w); ph[2*i+1] = a;
}

__global__ void splitw_kernel(const float* __restrict__ WQ,
                              const float* __restrict__ WK,
                              const float* __restrict__ WV) {
    int idx = blockIdx.x * blockDim.x + threadIdx.x;   // [z][k][n], 3*1024*256
    int z = idx >> 18;
    int kn = idx & 0x3FFFF;
    const float* W = (z == 0) ? WQ : (z == 1 ? WK : WV);
    float w = W[kn] * 1024.0f;          // scale into fp16-normal range
    __half h = __float2half(w);
    g_Wh[idx] = h;
    g_Wm[idx] = __float2half(w - __half2float(h));
}

// ---------------- projection GEMM on mma.sync fp16 (split-2) ----------------
// CTA = 128M x 256N, K=1024 in 32 stages of KC=32, cp.async 3-stage ring.
#define PKC 32
#define PSTG_A 10240
#define PSTG_BYTES (PSTG_A + 32768)
#define PROJ_SMEM (3 * PSTG_BYTES)

__global__ void __launch_bounds__(256, 1) proj_mma_kernel()
{
    extern __shared__ __align__(1024) char sm[];
    uint32_t smb = smem_u32(sm);
    int tid = threadIdx.x;
    int z = blockIdx.x;
    int m0 = blockIdx.y * 128;

    const __half* Wh = g_Wh + (size_t)z * HID * HD;
    const __half* Wm = g_Wm + (size_t)z * HID * HD;

    // A copy: 2 chunks/thread (512 chunks of 16B)
    const __half* srcA[2]; uint32_t dstA[2];
    #pragma unroll
    for (int i = 0; i < 2; i++) {
        int id = tid + i * 256;
        int m = id >> 2, c = id & 3;
        srcA[i] = g_Xh + (size_t)(m0 + m) * HID + c * 8;
        dstA[i] = (uint32_t)(m * 80 + c * 16);
    }
    // B copy: 8 chunks/thread (2048 chunks)
    const __half* srcB[8]; uint32_t dstB[8];
    #pragma unroll
    for (int i = 0; i < 8; i++) {
        int id = tid + i * 256;
        int k = id >> 6, cc = id & 63;
        int term = cc >> 5, n_c = cc & 31;
        srcB[i] = (term ? Wm : Wh) + (size_t)k * HD + n_c * 8;
        dstB[i] = (uint32_t)(PSTG_A + k * 1024 + ((cc ^ (k & 7)) << 4));
    }

    int w = tid >> 5, l = tid & 31;
    int wm = (w >> 2) * 64, wn = (w & 3) * 64;
    int la = l & 15, hsel = l >> 4;
    uint32_t bmx = (uint32_t)(la & 7);
    uint32_t brow = (uint32_t)(la * 1024);
    uint32_t bnc0 = (uint32_t)(wn >> 3);

    float d[4][8][4];
    #pragma unroll
    for (int mt = 0; mt < 4; mt++)
        #pragma unroll
        for (int nt = 0; nt < 8; nt++)
            #pragma unroll
            for (int r = 0; r < 4; r++) d[mt][nt][r] = 0.0f;

    // prologue: stages 0, 1
    #pragma unroll
    for (int p = 0; p < 2; p++) {
        uint32_t bb = smb + (uint32_t)p * PSTG_BYTES;
        int kt = p * PKC;
        #pragma unroll
        for (int i = 0; i < 2; i++) cp16(bb + dstA[i], srcA[i] + kt);
        #pragma unroll
        for (int i = 0; i < 8; i++) cp16(bb + dstB[i], srcB[i] + (size_t)kt * HD);
        CP_COMMIT();
    }

    int buf = 0, nbuf = 2;    // buffer of stage s; buffer for stage s+2
    for (int s = 0; s < 32; s++) {
        if (s + 2 < 32) {
            uint32_t bb = smb + (uint32_t)nbuf * PSTG_BYTES;
            int kt = (s + 2) * PKC;
            #pragma unroll
            for (int i = 0; i < 2; i++) cp16(bb + dstA[i], srcA[i] + kt);
            #pragma unroll
            for (int i = 0; i < 8; i++) cp16(bb + dstB[i], srcB[i] + (size_t)kt * HD);
            CP_COMMIT();
            CP_WAIT(2);
        } else if (s + 1 < 32) {
            CP_WAIT(1);
        } else {
            CP_WAIT(0);
        }
        __syncthreads();

        uint32_t AS = smb + (uint32_t)buf * PSTG_BYTES;
        uint32_t BS = AS + PSTG_A;
        buf = (buf + 1 == 3) ? 0 : buf + 1;
        nbuf = (nbuf + 1 == 3) ? 0 : nbuf + 1;

        #pragma unroll
        for (int slab = 0; slab < 2; slab++) {          // two k16 slabs
            uint32_t ah[4][4];
            #pragma unroll
            for (int mt = 0; mt < 4; mt++) {
                uint32_t row = (uint32_t)(wm + mt * 16 + la);
                ldsm4(ah[mt], AS + row * 80 + (uint32_t)((slab * 2 + hsel) * 16));
            }
            uint32_t krow = BS + (uint32_t)(slab * 16 * 1024) + brow;
            #pragma unroll
            for (int half = 0; half < 2; half++) {
                uint32_t bh[2][4], bm[2][4];
                #pragma unroll
                for (int j2 = 0; j2 < 2; j2++) {
                    uint32_t nc = bnc0 + (uint32_t)(half * 4 + j2 * 2 + hsel);
                    ldsm4t(bh[j2], krow + (((nc)       ^ bmx) << 4));
                    ldsm4t(bm[j2], krow + (((nc + 32u) ^ bmx) << 4));
                }
                #pragma unroll
                for (int nt = 0; nt < 4; nt++) {
                    uint32_t h0 = bh[nt >> 1][(nt & 1) * 2], h1 = bh[nt >> 1][(nt & 1) * 2 + 1];
                    uint32_t q0 = bm[nt >> 1][(nt & 1) * 2], q1 = bm[nt >> 1][(nt & 1) * 2 + 1];
                    #pragma unroll
                    for (int mt = 0; mt < 4; mt++) {
                        float* dd = d[mt][half * 4 + nt];
                        mma16816h(dd, ah[mt], h0, h1);   // Xh * Wh
                        mma16816h(dd, ah[mt], q0, q1);   // Xh * Wm
                    }
                }
            }
        }
        __syncthreads();
    }

    // ---- epilogue: unscale (W was x1024) + rotary (Q,K) + store ----
    const float* ct = (z == 0) ? g_cosQ : g_cosK;
    const float* st = (z == 0) ? g_sinQ : g_sinK;
    __nv_bfloat16* Oqk = (z == 0) ? g_Qb : g_Kb;
    const float DS = 0.0009765625f;     // 2^-10
    int mrb = m0 + wm + (l >> 2);
    int ncb = wn + (l & 3) * 2;
    #pragma unroll
    for (int mt = 0; mt < 4; mt++)
        #pragma unroll
        for (int r2 = 0; r2 < 2; r2++) {
            int m = mrb + mt * 16 + r2 * 8;
            int pos = m & (SEQ - 1);
            #pragma unroll
            for (int nt = 0; nt < 8; nt++) {
                int n = ncb + nt * 8;
                float v0 = d[mt][nt][r2 * 2] * DS, v1 = d[mt][nt][r2 * 2 + 1] * DS;
                if (z < 2) {
                    int j = n >> 1;
                    float C = ct[pos * 128 + j], S = st[pos * 128 + j];
                    float o0 = v0 * C - v1 * S;
                    float o1 = v1 * C + v0 * S;
                    float h0f = __bfloat162float(__float2bfloat16(o0));
                    float h1f = __bfloat162float(__float2bfloat16(o1));
                    uint32_t hp = bf16pair(o0, o1);
                    uint32_t mp = bf16pair(o0 - h0f, o1 - h1f);
                    *(uint32_t*)(Oqk + (size_t)m * 512 + n)       = hp;
                    *(uint32_t*)(Oqk + (size_t)m * 512 + 256 + n) = mp;
                } else {
                    *(uint32_t*)(g_Vf + (size_t)m * HD + n) = fp16pair(v0, v1);
                }
            }
        }
}

// ---------------- banded retention attention ----------------
// phase1: bf16 split-3 (Q,K need bf16 range due to xpos scaling)
// phase2: fp16 (S hi/mid split-2 x V single)
#define ASM_Q  0
#define ASM_B0 65536
#define ASM_B1 131072
#define ASM_S  163840
#define ATTN_SMEM 180224

__device__ __forceinline__ uint32_t swz64(uint32_t row, uint32_t cc) {   // 1024B rows
    return row * 1024u + (((cc & 56u) | ((cc ^ row) & 7u)) << 4);
}
__device__ __forceinline__ uint32_t swzV(uint32_t row, uint32_t cc) {    // 512B rows
    return row * 512u + (((cc & 24u) | ((cc ^ row) & 7u)) << 4);
}
__device__ __forceinline__ uint32_t swzS(uint32_t row, uint32_t cc) {    // 256B rows
    return row * 256u + (((cc & 8u) | ((cc ^ row) & 7u)) << 4);
}

__global__ void __launch_bounds__(256, 1) attn_mma_kernel(float* __restrict__ out)
{
    extern __shared__ __align__(1024) char sm[];
    uint32_t smb = smem_u32(sm);
    int tid = threadIdx.x;
    int b = blockIdx.y;
    int q0 = blockIdx.x * 64;
    size_t base = (size_t)b * SEQ;

    #pragma unroll
    for (int i = 0; i < 16; i++) {
        int id = tid + i * 256;
        uint32_t row = (uint32_t)(id >> 6), cc = (uint32_t)(id & 63);
        cp16(smb + ASM_Q + swz64(row, cc), g_Qb + (base + q0 + row) * 512 + cc * 8);
    }
    int kt_lo = q0 - DW; if (kt_lo < 0) kt_lo = 0;
    int nt = ((q0 - kt_lo) >> 6) + 1;
    #pragma unroll
    for (int i = 0; i < 16; i++) {
        int id = tid + i * 256;
        uint32_t row = (uint32_t)(id >> 6), cc = (uint32_t)(id & 63);
        cp16(smb + ASM_B0 + swz64(row, cc), g_Kb + (base + kt_lo + row) * 512 + cc * 8);
    }
    CP_COMMIT();
    #pragma unroll
    for (int i = 0; i < 8; i++) {       // V tile: 64 rows x 512B = 32KB
        int id = tid + i * 256;
        uint32_t row = (uint32_t)(id >> 5), cc = (uint32_t)(id & 31);
        cp16(smb + ASM_B1 + swzV(row, cc), g_Vf + (base + kt_lo + row) * HD + cc * 8);
    }
    CP_COMMIT();

    int w = tid >> 5, l = tid & 31;
    int wm = w >> 2, wn = w & 3;
    uint32_t la = (uint32_t)(l & 15), hsel = (uint32_t)(l >> 4);

    float o[2][8][4];
    #pragma unroll
    for (int mt = 0; mt < 2; mt++)
        #pragma unroll
        for (int j = 0; j < 8; j++)
            #pragma unroll
            for (int r = 0; r < 4; r++) o[mt][j][r] = 0.0f;

    for (int it = 0; it < nt; it++) {
        int kt = kt_lo + it * 64;

        CP_WAIT(1);
        __syncthreads();

        // ---- phase 1: S = Q K^T, bf16 split-3 ----
        float sacc[2][2][4];
        #pragma unroll
        for (int mt = 0; mt < 2; mt++)
            #pragma unroll
            for (int nti = 0; nti < 2; nti++)
                #pragma unroll
                for (int r = 0; r < 4; r++) sacc[mt][nti][r] = 0.0f;

        #pragma unroll 4
        for (int ks = 0; ks < 16; ks++) {
            uint32_t qh[2][4], qm[2][4];
            #pragma unroll
            for (int mt = 0; mt < 2; mt++) {
                uint32_t row = (uint32_t)(wm * 32 + mt * 16) + la;
                ldsm4(qh[mt], smb + ASM_Q + swz64(row, (uint32_t)(ks * 2) + hsel));
                ldsm4(qm[mt], smb + ASM_Q + swz64(row, 32u + (uint32_t)(ks * 2) + hsel));
            }
            uint32_t kh[4], km[4];
            {
                uint32_t row = (uint32_t)(wn * 16) + la;
                ldsm4(kh, smb + ASM_B0 + swz64(row, (uint32_t)(ks * 2) + hsel));
                ldsm4(km, smb + ASM_B0 + swz64(row, 32u + (uint32_t)(ks * 2) + hsel));
            }
            #pragma unroll
            for (int mt = 0; mt < 2; mt++)
                #pragma unroll
                for (int nti = 0; nti < 2; nti++) {
                    float* dd = sacc[mt][nti];
                    mma16816(dd, qh[mt], kh[nti], kh[nti + 2]);
                    mma16816(dd, qh[mt], km[nti], km[nti + 2]);
                    mma16816(dd, qm[mt], kh[nti], kh[nti + 2]);
                }
        }

        // ---- decay + fp16 split + stage S ----
        int dq = q0 - kt;
        #pragma unroll
        for (int mt = 0; mt < 2; mt++)
            #pragma unroll
            for (int nti = 0; nti < 2; nti++) {
                int qr0 = wm * 32 + mt * 16 + (l >> 2);
                int key = wn * 16 + nti * 8 + (l & 3) * 2;
                #pragma unroll
                for (int h = 0; h < 2; h++) {
                    int q = qr0 + 8 * h;
                    int e0 = dq + q - key;
                    float g0 = (e0 >= 0) ? g_gamma[e0] : 0.0f;
                    float g1 = (e0 >= 1) ? g_gamma[e0 - 1] : 0.0f;
                    float s0 = sacc[mt][nti][2 * h] * g0;
                    float s1 = sacc[mt][nti][2 * h + 1] * g1;
                    float h0f = __half2float(__float2half(s0));
                    float h1f = __half2float(__float2half(s1));
                    uint32_t hp = fp16pair(s0, s1);
                    uint32_t mp = fp16pair(s0 - h0f, s1 - h1f);
                    uint32_t cc = (uint32_t)(key >> 3);
                    uint32_t inb = (uint32_t)((key & 7) * 2);
                    *(uint32_t*)(sm + ASM_S + swzS((uint32_t)q, cc) + inb)      = hp;
                    *(uint32_t*)(sm + ASM_S + swzS((uint32_t)q, 8u + cc) + inb) = mp;
                }
            }
        __syncthreads();

        if (it + 1 < nt) {
            #pragma unroll
            for (int i = 0; i < 16; i++) {
                int id = tid + i * 256;
                uint32_t row = (uint32_t)(id >> 6), cc = (uint32_t)(id & 63);
                cp16(smb + ASM_B0 + swz64(row, cc),
                     g_Kb + (base + kt + 64 + row) * 512 + cc * 8);
            }
            CP_COMMIT();
            CP_WAIT(1);
        } else {
            CP_WAIT(0);
        }
        __syncthreads();

        // ---- phase 2: O += S V, fp16 (split-2 x single) ----
        #pragma unroll
        for (int ks2 = 0; ks2 < 4; ks2++) {
            uint32_t sh[2][4], sd[2][4];
            #pragma unroll
            for (int mt = 0; mt < 2; mt++) {
                uint32_t row = (uint32_t)(wm * 32 + mt * 16) + la;
                ldsm4(sh[mt], smb + ASM_S + swzS(row, (uint32_t)(ks2 * 2) + hsel));
                ldsm4(sd[mt], smb + ASM_S + swzS(row, 8u + (uint32_t)(ks2 * 2) + hsel));
            }
            uint32_t vrow = (uint32_t)(ks2 * 16) + la;
            #pragma unroll
            for (int j = 0; j < 4; j++) {
                uint32_t vh[4];
                uint32_t cc = (uint32_t)(wn * 8 + j * 2) + hsel;
                ldsm4t(vh, smb + ASM_B1 + swzV(vrow, cc));
                #pragma unroll
                for (int nti = 0; nti < 2; nti++) {
                    uint32_t b0 = vh[nti * 2], b1 = vh[nti * 2 + 1];
                    #pragma unroll
                    for (int mt = 0; mt < 2; mt++) {
                        float* dd = o[mt][j * 2 + nti];
                        mma16816h(dd, sh[mt], b0, b1);   // Sh * V
                        mma16816h(dd, sd[mt], b0, b1);   // Sm * V
                    }
                }
            }
        }
        __syncthreads();

        if (it + 1 < nt) {
            #pragma unroll
            for (int i = 0; i < 8; i++) {
                int id = tid + i * 256;
                uint32_t row = (uint32_t)(id >> 5), cc = (uint32_t)(id & 31);
                cp16(smb + ASM_B1 + swzV(row, cc),
                     g_Vf + (base + kt + 64 + row) * HD + cc * 8);
            }
            CP_COMMIT();
        }
    }

    #pragma unroll
    for (int mt = 0; mt < 2; mt++)
        #pragma unroll
        for (int h = 0; h < 2; h++) {
            int q = q0 + wm * 32 + mt * 16 + (l >> 2) + 8 * h;
            size_t ro = (base + q) * (size_t)HD;
            #pragma unroll
            for (int j = 0; j < 8; j++) {
                int vd = wn * 64 + j * 8 + (l & 3) * 2;
                float2 v;
                v.x = o[mt][j][2 * h];
                v.y = o[mt][j][2 * h + 1];
                *(float2*)(out + ro + vd) = v;
            }
        }
}

// ---------------- launch ----------------
extern "C" void kernel_launch(void* const* d_in, const int* in_sizes, int n_in,
                              void* d_out, int out_size) {
    const float* X  = (const float*)d_in[0];
    const float* WQ = (const float*)d_in[1];
    const float* WK = (const float*)d_in[2];
    const float* WV = (const float*)d_in[3];
    float* out = (float*)d_out;

    const_kernel<<<16, 256>>>();
    tables_kernel<<<SEQ, 128>>>();

    splitx_kernel<<<(MTOT * HID / 4) / 256, 256>>>(X);
    splitw_kernel<<<(3 * HID * HD) / 256, 256>>>(WQ, WK, WV);

    cudaFuncSetAttribute(proj_mma_kernel, cudaFuncAttributeMaxDynamicSharedMemorySize,
                         PROJ_SMEM);
    dim3 pg(3, MTOT / 128);
    proj_mma_kernel<<<pg, 256, PROJ_SMEM>>>();

    cudaFuncSetAttribute(attn_mma_kernel, cudaFuncAttributeMaxDynamicSharedMemorySize,
                         ATTN_SMEM);
    dim3 ag(SEQ / 64, NB);
    attn_mma_kernel<<<ag, 256, ATTN_SMEM>>>(out);
}

// round 9
// speedup vs baseline: 3.2107x; 1.0760x over previous
#include <cuda_runtime.h>
#include <cuda_bf16.h>
#include <cuda_fp16.h>
#include <math.h>
#include <stdint.h>

#define SEQ 4096
#define NB 4
#define HID 1024
#define HD 256
#define MTOT (NB*SEQ)
#define DW 320            // gamma^320 ~ 3.9e-5 << current 4.1e-4 error floor

typedef unsigned long long u64;

// ---------------- static device scratch (no cudaMalloc allowed) ----------------
// Q/K stored as packed bf16 (hi,mid): row layout [term0 d0..255][term1 d0..255]
__device__ __nv_bfloat16 g_Qb[(size_t)MTOT*512];
__device__ __nv_bfloat16 g_Kb[(size_t)MTOT*512];
__device__ __half g_Vf[(size_t)MTOT*HD];    // V as plain fp16 (no xpos scale -> fp16-safe)
__device__ __half g_Xh[(size_t)MTOT*HID];   // X as plain fp16 (split-2 scheme)
__device__ __half g_Wh[3*HID*HD];           // [z][k][n], W*1024 hi
__device__ __half g_Wm[3*HID*HD];           // [z][k][n], W*1024 mid
__device__ float g_cosQ[SEQ*128];
__device__ float g_sinQ[SEQ*128];
__device__ float g_cosK[SEQ*128];
__device__ float g_sinK[SEQ*128];
__device__ float g_gamma[SEQ];
__device__ double g_invf[128];
__device__ double g_l2sb[128];

// ---------------- mma / async helpers (baseline PTX, sm_80+ ISA only) ----------------
__device__ __forceinline__ uint32_t smem_u32(const void* p) {
    uint32_t a;
    asm("{ .reg .u64 t; cvta.to.shared.u64 t, %1; cvt.u32.u64 %0, t; }" : "=r"(a) : "l"(p));
    return a;
}
__device__ __forceinline__ void cp16(uint32_t dst, const void* src) {
    asm volatile("cp.async.cg.shared.global [%0], [%1], 16;" :: "r"(dst), "l"(src));
}
#define CP_COMMIT()  asm volatile("cp.async.commit_group;" ::: "memory")
#define CP_WAIT(n)   asm volatile("cp.async.wait_group %0;" :: "n"(n) : "memory")

__device__ __forceinline__ void ldsm4(uint32_t (&r)[4], uint32_t a) {
    asm volatile("ldmatrix.sync.aligned.m8n8.x4.shared.b16 {%0,%1,%2,%3}, [%4];"
                 : "=r"(r[0]), "=r"(r[1]), "=r"(r[2]), "=r"(r[3]) : "r"(a));
}
__device__ __forceinline__ void ldsm4t(uint32_t (&r)[4], uint32_t a) {
    asm volatile("ldmatrix.sync.aligned.m8n8.x4.trans.shared.b16 {%0,%1,%2,%3}, [%4];"
                 : "=r"(r[0]), "=r"(r[1]), "=r"(r[2]), "=r"(r[3]) : "r"(a));
}
__device__ __forceinline__ void mma16816(float* d, const uint32_t* a, uint32_t b0, uint32_t b1) {
    asm volatile(
        "mma.sync.aligned.m16n8k16.row.col.f32.bf16.bf16.f32 "
        "{%0,%1,%2,%3}, {%4,%5,%6,%7}, {%8,%9}, {%0,%1,%2,%3};"
        : "+f"(d[0]), "+f"(d[1]), "+f"(d[2]), "+f"(d[3])
        : "r"(a[0]), "r"(a[1]), "r"(a[2]), "r"(a[3]), "r"(b0), "r"(b1));
}
__device__ __forceinline__ void mma16816h(float* d, const uint32_t* a, uint32_t b0, uint32_t b1) {
    asm volatile(
        "mma.sync.aligned.m16n8k16.row.col.f32.f16.f16.f32 "
        "{%0,%1,%2,%3}, {%4,%5,%6,%7}, {%8,%9}, {%0,%1,%2,%3};"
        : "+f"(d[0]), "+f"(d[1]), "+f"(d[2]), "+f"(d[3])
        : "r"(a[0]), "r"(a[1]), "r"(a[2]), "r"(a[3]), "r"(b0), "r"(b1));
}
__device__ __forceinline__ uint32_t bf16pair(float a, float b) {
    __nv_bfloat162 t; t.x = __float2bfloat16(a); t.y = __float2bfloat16(b);
    uint32_t r; asm("mov.b32 %0, %1;" : "=r"(r) : "r"(*(uint32_t*)&t)); return r;
}
__device__ __forceinline__ uint32_t fp16pair(float a, float b) {
    __half2 t; t.x = __float2half(a); t.y = __float2half(b);
    uint32_t r; asm("mov.b32 %0, %1;" : "=r"(r) : "r"(*(uint32_t*)&t)); return r;
}

// ---------------- constants ----------------
__global__ void const_kernel() {
    int t = blockIdx.x * blockDim.x + threadIdx.x;
    if (t < 128) {
        g_invf[t] = pow(10000.0, -(double)t / 128.0);
        double sb = ((double)(2 * t) + 0.4 * 256.0) / (1.4 * 256.0);
        g_l2sb[t] = log2(sb);
    }
    if (t < SEQ) g_gamma[t] = (float)pow(0.96875, (double)t);
}

// ---------------- xpos sin/cos/scale tables ----------------
__global__ void tables_kernel() {
    int pos = blockIdx.x, j = threadIdx.x;
    float invf = (float)g_invf[j];
    float arg = (float)pos * invf;
    double ad = (double)arg;
    double qd = rint(ad * 0.63661977236758134308);
    double rd = fma(qd, -1.5707963267948966, ad);
    rd = fma(qd, -6.123233995736766e-17, rd);
    int qi = ((long long)qd) & 3;
    float rf = (float)rd;
    float sr = sinf(rf), cr = cosf(rf);
    float s, c;
    if      (qi == 0) { s =  sr; c =  cr; }
    else if (qi == 1) { s =  cr; c = -sr; }
    else if (qi == 2) { s = -sr; c = -cr; }
    else              { s = -cr; c =  sr; }
    float p  = (float)pos * (1.0f / 512.0f);
    float l2 = (float)g_l2sb[j];
    float sc  = exp2f(p * l2);
    float isc = exp2f(-p * l2);
    int idx = pos * 128 + j;
    g_cosQ[idx] = c * sc;   g_sinQ[idx] = s * sc;
    g_cosK[idx] = c * isc;  g_sinK[idx] = s * isc;
}

// ---------------- prep: X -> fp16; W*1024 -> fp16 (hi, mid) ----------------
__global__ void splitx_kernel(const float* __restrict__ X) {
    size_t i = (size_t)blockIdx.x * blockDim.x + threadIdx.x;   // 4 floats each
    float4 x = ((const float4*)X)[i];
    __half2* ph = (__half2*)g_Xh;
    __half2 a;
    a.x = __float2half(x.x); a.y = __float2half(x.y); ph[2*i]   = a;
    a.x = __float2half(x.z); a.y = __float2half(x.w); ph[2*i+1] = a;
}

__global__ void splitw_kernel(const float* __restrict__ WQ,
                              const float* __restrict__ WK,
                              const float* __restrict__ WV) {
    int idx = blockIdx.x * blockDim.x + threadIdx.x;   // [z][k][n], 3*1024*256
    int z = idx >> 18;
    int kn = idx & 0x3FFFF;
    const float* W = (z == 0) ? WQ : (z == 1 ? WK : WV);
    float w = W[kn] * 1024.0f;          // scale into fp16-normal range
    __half h = __float2half(w);
    g_Wh[idx] = h;
    g_Wm[idx] = __float2half(w - __half2float(h));
}

// ---------------- projection GEMM on mma.sync fp16 (split-2) ----------------
// CTA = 128M x 256N, K=1024 in 32 stages of KC=32, cp.async 3-stage ring.
#define PKC 32
#define PSTG_A 10240
#define PSTG_BYTES (PSTG_A + 32768)
#define PROJ_SMEM (3 * PSTG_BYTES)

__global__ void __launch_bounds__(256, 1) proj_mma_kernel()
{
    extern __shared__ __align__(1024) char sm[];
    uint32_t smb = smem_u32(sm);
    int tid = threadIdx.x;
    int z = blockIdx.x;
    int m0 = blockIdx.y * 128;

    const __half* Wh = g_Wh + (size_t)z * HID * HD;
    const __half* Wm = g_Wm + (size_t)z * HID * HD;

    // A copy: 2 chunks/thread (512 chunks of 16B)
    const __half* srcA[2]; uint32_t dstA[2];
    #pragma unroll
    for (int i = 0; i < 2; i++) {
        int id = tid + i * 256;
        int m = id >> 2, c = id & 3;
        srcA[i] = g_Xh + (size_t)(m0 + m) * HID + c * 8;
        dstA[i] = (uint32_t)(m * 80 + c * 16);
    }
    // B copy: 8 chunks/thread (2048 chunks)
    const __half* srcB[8]; uint32_t dstB[8];
    #pragma unroll
    for (int i = 0; i < 8; i++) {
        int id = tid + i * 256;
        int k = id >> 6, cc = id & 63;
        int term = cc >> 5, n_c = cc & 31;
        srcB[i] = (term ? Wm : Wh) + (size_t)k * HD + n_c * 8;
        dstB[i] = (uint32_t)(PSTG_A + k * 1024 + ((cc ^ (k & 7)) << 4));
    }

    int w = tid >> 5, l = tid & 31;
    int wm = (w >> 2) * 64, wn = (w & 3) * 64;
    int la = l & 15, hsel = l >> 4;
    uint32_t bmx = (uint32_t)(la & 7);
    uint32_t brow = (uint32_t)(la * 1024);
    uint32_t bnc0 = (uint32_t)(wn >> 3);

    float d[4][8][4];
    #pragma unroll
    for (int mt = 0; mt < 4; mt++)
        #pragma unroll
        for (int nt = 0; nt < 8; nt++)
            #pragma unroll
            for (int r = 0; r < 4; r++) d[mt][nt][r] = 0.0f;

    // prologue: stages 0, 1
    #pragma unroll
    for (int p = 0; p < 2; p++) {
        uint32_t bb = smb + (uint32_t)p * PSTG_BYTES;
        int kt = p * PKC;
        #pragma unroll
        for (int i = 0; i < 2; i++) cp16(bb + dstA[i], srcA[i] + kt);
        #pragma unroll
        for (int i = 0; i < 8; i++) cp16(bb + dstB[i], srcB[i] + (size_t)kt * HD);
        CP_COMMIT();
    }

    int buf = 0, nbuf = 2;    // buffer of stage s; buffer for stage s+2
    for (int s = 0; s < 32; s++) {
        if (s + 2 < 32) {
            uint32_t bb = smb + (uint32_t)nbuf * PSTG_BYTES;
            int kt = (s + 2) * PKC;
            #pragma unroll
            for (int i = 0; i < 2; i++) cp16(bb + dstA[i], srcA[i] + kt);
            #pragma unroll
            for (int i = 0; i < 8; i++) cp16(bb + dstB[i], srcB[i] + (size_t)kt * HD);
            CP_COMMIT();
            CP_WAIT(2);
        } else if (s + 1 < 32) {
            CP_WAIT(1);
        } else {
            CP_WAIT(0);
        }
        __syncthreads();

        uint32_t AS = smb + (uint32_t)buf * PSTG_BYTES;
        uint32_t BS = AS + PSTG_A;
        buf = (buf + 1 == 3) ? 0 : buf + 1;
        nbuf = (nbuf + 1 == 3) ? 0 : nbuf + 1;

        #pragma unroll
        for (int slab = 0; slab < 2; slab++) {          // two k16 slabs
            uint32_t ah[4][4];
            #pragma unroll
            for (int mt = 0; mt < 4; mt++) {
                uint32_t row = (uint32_t)(wm + mt * 16 + la);
                ldsm4(ah[mt], AS + row * 80 + (uint32_t)((slab * 2 + hsel) * 16));
            }
            uint32_t krow = BS + (uint32_t)(slab * 16 * 1024) + brow;
            #pragma unroll
            for (int half = 0; half < 2; half++) {
                uint32_t bh[2][4], bm[2][4];
                #pragma unroll
                for (int j2 = 0; j2 < 2; j2++) {
                    uint32_t nc = bnc0 + (uint32_t)(half * 4 + j2 * 2 + hsel);
                    ldsm4t(bh[j2], krow + (((nc)       ^ bmx) << 4));
                    ldsm4t(bm[j2], krow + (((nc + 32u) ^ bmx) << 4));
                }
                #pragma unroll
                for (int nt = 0; nt < 4; nt++) {
                    uint32_t h0 = bh[nt >> 1][(nt & 1) * 2], h1 = bh[nt >> 1][(nt & 1) * 2 + 1];
                    uint32_t q0 = bm[nt >> 1][(nt & 1) * 2], q1 = bm[nt >> 1][(nt & 1) * 2 + 1];
                    #pragma unroll
                    for (int mt = 0; mt < 4; mt++) {
                        float* dd = d[mt][half * 4 + nt];
                        mma16816h(dd, ah[mt], h0, h1);   // Xh * Wh
                        mma16816h(dd, ah[mt], q0, q1);   // Xh * Wm
                    }
                }
            }
        }
        __syncthreads();
    }

    // ---- epilogue: unscale (W was x1024) + rotary (Q,K) + store ----
    const float* ct = (z == 0) ? g_cosQ : g_cosK;
    const float* st = (z == 0) ? g_sinQ : g_sinK;
    __nv_bfloat16* Oqk = (z == 0) ? g_Qb : g_Kb;
    const float DS = 0.0009765625f;     // 2^-10
    int mrb = m0 + wm + (l >> 2);
    int ncb = wn + (l & 3) * 2;
    #pragma unroll
    for (int mt = 0; mt < 4; mt++)
        #pragma unroll
        for (int r2 = 0; r2 < 2; r2++) {
            int m = mrb + mt * 16 + r2 * 8;
            int pos = m & (SEQ - 1);
            #pragma unroll
            for (int nt = 0; nt < 8; nt++) {
                int n = ncb + nt * 8;
                float v0 = d[mt][nt][r2 * 2] * DS, v1 = d[mt][nt][r2 * 2 + 1] * DS;
                if (z < 2) {
                    int j = n >> 1;
                    float C = ct[pos * 128 + j], S = st[pos * 128 + j];
                    float o0 = v0 * C - v1 * S;
                    float o1 = v1 * C + v0 * S;
                    float h0f = __bfloat162float(__float2bfloat16(o0));
                    float h1f = __bfloat162float(__float2bfloat16(o1));
                    uint32_t hp = bf16pair(o0, o1);
                    uint32_t mp = bf16pair(o0 - h0f, o1 - h1f);
                    *(uint32_t*)(Oqk + (size_t)m * 512 + n)       = hp;
                    *(uint32_t*)(Oqk + (size_t)m * 512 + 256 + n) = mp;
                } else {
                    *(uint32_t*)(g_Vf + (size_t)m * HD + n) = fp16pair(v0, v1);
                }
            }
        }
}

// ---------------- banded retention attention ----------------
// phase1: bf16 split-3 (Q,K need bf16 range due to xpos scaling)
// phase2: fp16 (S hi/mid split-2 x V single)
#define ASM_Q  0
#define ASM_B0 65536
#define ASM_B1 131072
#define ASM_S  163840
#define ATTN_SMEM 180224

__device__ __forceinline__ uint32_t swz64(uint32_t row, uint32_t cc) {   // 1024B rows
    return row * 1024u + (((cc & 56u) | ((cc ^ row) & 7u)) << 4);
}
__device__ __forceinline__ uint32_t swzV(uint32_t row, uint32_t cc) {    // 512B rows
    return row * 512u + (((cc & 24u) | ((cc ^ row) & 7u)) << 4);
}
__device__ __forceinline__ uint32_t swzS(uint32_t row, uint32_t cc) {    // 256B rows
    return row * 256u + (((cc & 8u) | ((cc ^ row) & 7u)) << 4);
}

__global__ void __launch_bounds__(256, 1) attn_mma_kernel(float* __restrict__ out)
{
    extern __shared__ __align__(1024) char sm[];
    uint32_t smb = smem_u32(sm);
    int tid = threadIdx.x;
    int b = blockIdx.y;
    int q0 = blockIdx.x * 64;
    size_t base = (size_t)b * SEQ;

    #pragma unroll
    for (int i = 0; i < 16; i++) {
        int id = tid + i * 256;
        uint32_t row = (uint32_t)(id >> 6), cc = (uint32_t)(id & 63);
        cp16(smb + ASM_Q + swz64(row, cc), g_Qb + (base + q0 + row) * 512 + cc * 8);
    }
    int kt_lo = q0 - DW; if (kt_lo < 0) kt_lo = 0;
    int nt = ((q0 - kt_lo) >> 6) + 1;
    #pragma unroll
    for (int i = 0; i < 16; i++) {
        int id = tid + i * 256;
        uint32_t row = (uint32_t)(id >> 6), cc = (uint32_t)(id & 63);
        cp16(smb + ASM_B0 + swz64(row, cc), g_Kb + (base + kt_lo + row) * 512 + cc * 8);
    }
    CP_COMMIT();
    #pragma unroll
    for (int i = 0; i < 8; i++) {       // V tile: 64 rows x 512B = 32KB
        int id = tid + i * 256;
        uint32_t row = (uint32_t)(id >> 5), cc = (uint32_t)(id & 31);
        cp16(smb + ASM_B1 + swzV(row, cc), g_Vf + (base + kt_lo + row) * HD + cc * 8);
    }
    CP_COMMIT();

    int w = tid >> 5, l = tid & 31;
    int wm = w >> 2, wn = w & 3;
    uint32_t la = (uint32_t)(l & 15), hsel = (uint32_t)(l >> 4);

    float o[2][8][4];
    #pragma unroll
    for (int mt = 0; mt < 2; mt++)
        #pragma unroll
        for (int j = 0; j < 8; j++)
            #pragma unroll
            for (int r = 0; r < 4; r++) o[mt][j][r] = 0.0f;

    for (int it = 0; it < nt; it++) {
        int kt = kt_lo + it * 64;

        CP_WAIT(1);
        __syncthreads();

        // ---- phase 1: S = Q K^T, bf16 split-3 ----
        float sacc[2][2][4];
        #pragma unroll
        for (int mt = 0; mt < 2; mt++)
            #pragma unroll
            for (int nti = 0; nti < 2; nti++)
                #pragma unroll
                for (int r = 0; r < 4; r++) sacc[mt][nti][r] = 0.0f;

        #pragma unroll 4
        for (int ks = 0; ks < 16; ks++) {
            uint32_t qh[2][4], qm[2][4];
            #pragma unroll
            for (int mt = 0; mt < 2; mt++) {
                uint32_t row = (uint32_t)(wm * 32 + mt * 16) + la;
                ldsm4(qh[mt], smb + ASM_Q + swz64(row, (uint32_t)(ks * 2) + hsel));
                ldsm4(qm[mt], smb + ASM_Q + swz64(row, 32u + (uint32_t)(ks * 2) + hsel));
            }
            uint32_t kh[4], km[4];
            {
                uint32_t row = (uint32_t)(wn * 16) + la;
                ldsm4(kh, smb + ASM_B0 + swz64(row, (uint32_t)(ks * 2) + hsel));
                ldsm4(km, smb + ASM_B0 + swz64(row, 32u + (uint32_t)(ks * 2) + hsel));
            }
            #pragma unroll
            for (int mt = 0; mt < 2; mt++)
                #pragma unroll
                for (int nti = 0; nti < 2; nti++) {
                    float* dd = sacc[mt][nti];
                    mma16816(dd, qh[mt], kh[nti], kh[nti + 2]);
                    mma16816(dd, qh[mt], km[nti], km[nti + 2]);
                    mma16816(dd, qm[mt], kh[nti], kh[nti + 2]);
                }
        }

        // ---- decay + fp16 split + stage S ----
        int dq = q0 - kt;
        #pragma unroll
        for (int mt = 0; mt < 2; mt++)
            #pragma unroll
            for (int nti = 0; nti < 2; nti++) {
                int qr0 = wm * 32 + mt * 16 + (l >> 2);
                int key = wn * 16 + nti * 8 + (l & 3) * 2;
                #pragma unroll
                for (int h = 0; h < 2; h++) {
                    int q = qr0 + 8 * h;
                    int e0 = dq + q - key;
                    float g0 = (e0 >= 0) ? g_gamma[e0] : 0.0f;
                    float g1 = (e0 >= 1) ? g_gamma[e0 - 1] : 0.0f;
                    float s0 = sacc[mt][nti][2 * h] * g0;
                    float s1 = sacc[mt][nti][2 * h + 1] * g1;
                    float h0f = __half2float(__float2half(s0));
                    float h1f = __half2float(__float2half(s1));
                    uint32_t hp = fp16pair(s0, s1);
                    uint32_t mp = fp16pair(s0 - h0f, s1 - h1f);
                    uint32_t cc = (uint32_t)(key >> 3);
                    uint32_t inb = (uint32_t)((key & 7) * 2);
                    *(uint32_t*)(sm + ASM_S + swzS((uint32_t)q, cc) + inb)      = hp;
                    *(uint32_t*)(sm + ASM_S + swzS((uint32_t)q, 8u + cc) + inb) = mp;
                }
            }
        __syncthreads();

        if (it + 1 < nt) {
            #pragma unroll
            for (int i = 0; i < 16; i++) {
                int id = tid + i * 256;
                uint32_t row = (uint32_t)(id >> 6), cc = (uint32_t)(id & 63);
                cp16(smb + ASM_B0 + swz64(row, cc),
                     g_Kb + (base + kt + 64 + row) * 512 + cc * 8);
            }
            CP_COMMIT();
            CP_WAIT(1);
        } else {
            CP_WAIT(0);
        }
        __syncthreads();

        // ---- phase 2: O += S V, fp16 (split-2 x single) ----
        #pragma unroll
        for (int ks2 = 0; ks2 < 4; ks2++) {
            uint32_t sh[2][4], sd[2][4];
            #pragma unroll
            for (int mt = 0; mt < 2; mt++) {
                uint32_t row = (uint32_t)(wm * 32 + mt * 16) + la;
                ldsm4(sh[mt], smb + ASM_S + swzS(row, (uint32_t)(ks2 * 2) + hsel));
                ldsm4(sd[mt], smb + ASM_S + swzS(row, 8u + (uint32_t)(ks2 * 2) + hsel));
            }
            uint32_t vrow = (uint32_t)(ks2 * 16) + la;
            #pragma unroll
            for (int j = 0; j < 4; j++) {
                uint32_t vh[4];
                uint32_t cc = (uint32_t)(wn * 8 + j * 2) + hsel;
                ldsm4t(vh, smb + ASM_B1 + swzV(vrow, cc));
                #pragma unroll
                for (int nti = 0; nti < 2; nti++) {
                    uint32_t b0 = vh[nti * 2], b1 = vh[nti * 2 + 1];
                    #pragma unroll
                    for (int mt = 0; mt < 2; mt++) {
                        float* dd = o[mt][j * 2 + nti];
                        mma16816h(dd, sh[mt], b0, b1);   // Sh * V
                        mma16816h(dd, sd[mt], b0, b1);   // Sm * V
                    }
                }
            }
        }
        __syncthreads();

        if (it + 1 < nt) {
            #pragma unroll
            for (int i = 0; i < 8; i++) {
                int id = tid + i * 256;
                uint32_t row = (uint32_t)(id >> 5), cc = (uint32_t)(id & 31);
                cp16(smb + ASM_B1 + swzV(row, cc),
                     g_Vf + (base + kt + 64 + row) * HD + cc * 8);
            }
            CP_COMMIT();
        }
    }

    #pragma unroll
    for (int mt = 0; mt < 2; mt++)
        #pragma unroll
        for (int h = 0; h < 2; h++) {
            int q = q0 + wm * 32 + mt * 16 + (l >> 2) + 8 * h;
            size_t ro = (base + q) * (size_t)HD;
            #pragma unroll
            for (int j = 0; j < 8; j++) {
                int vd = wn * 64 + j * 8 + (l & 3) * 2;
                float2 v;
                v.x = o[mt][j][2 * h];
                v.y = o[mt][j][2 * h + 1];
                *(float2*)(out + ro + vd) = v;
            }
        }
}

// ---------------- launch ----------------
extern "C" void kernel_launch(void* const* d_in, const int* in_sizes, int n_in,
                              void* d_out, int out_size) {
    const float* X  = (const float*)d_in[0];
    const float* WQ = (const float*)d_in[1];
    const float* WK = (const float*)d_in[2];
    const float* WV = (const float*)d_in[3];
    float* out = (float*)d_out;

    const_kernel<<<16, 256>>>();
    tables_kernel<<<SEQ, 128>>>();

    splitx_kernel<<<(MTOT * HID / 4) / 256, 256>>>(X);
    splitw_kernel<<<(3 * HID * HD) / 256, 256>>>(WQ, WK, WV);

    cudaFuncSetAttribute(proj_mma_kernel, cudaFuncAttributeMaxDynamicSharedMemorySize,
                         PROJ_SMEM);
    dim3 pg(3, MTOT / 128);
    proj_mma_kernel<<<pg, 256, PROJ_SMEM>>>();

    cudaFuncSetAttribute(attn_mma_kernel, cudaFuncAttributeMaxDynamicSharedMemorySize,
                         ATTN_SMEM);
    dim3 ag(SEQ / 64, NB);
    attn_mma_kernel<<<ag, 256, ATTN_SMEM>>>(out);
}

// round 10
// speedup vs baseline: 3.7012x; 1.1528x over previous
#include <cuda_runtime.h>
#include <cuda_bf16.h>
#include <cuda_fp16.h>
#include <math.h>
#include <stdint.h>

#define SEQ 4096
#define NB 4
#define HID 1024
#define HD 256
#define MTOT (NB*SEQ)
#define DW 320            // gamma^320 ~ 3.9e-5 << error floor

typedef unsigned long long u64;

// ---------------- static device scratch (no cudaMalloc allowed) ----------------
// Q/K: single fp16 with RECENTERED xpos scale sb^((pos-2048)/512) (fits fp16 range)
__device__ __half g_Qh[(size_t)MTOT*HD];
__device__ __half g_Kh[(size_t)MTOT*HD];
__device__ __half g_Vf[(size_t)MTOT*HD];    // V plain fp16
__device__ __half g_Xh[(size_t)MTOT*HID];   // X fp16 (proj split-2 scheme)
__device__ __half g_Wh[3*HID*HD];           // [z][k][n], W*1024 hi
__device__ __half g_Wm[3*HID*HD];           // [z][k][n], W*1024 mid
__device__ float g_cosQ[SEQ*128];
__device__ float g_sinQ[SEQ*128];
__device__ float g_cosK[SEQ*128];
__device__ float g_sinK[SEQ*128];
__device__ float g_gamma[SEQ];
__device__ double g_invf[128];
__device__ double g_l2sb[128];

// ---------------- mma / async helpers (baseline PTX, sm_80+ ISA only) ----------------
__device__ __forceinline__ uint32_t smem_u32(const void* p) {
    uint32_t a;
    asm("{ .reg .u64 t; cvta.to.shared.u64 t, %1; cvt.u32.u64 %0, t; }" : "=r"(a) : "l"(p));
    return a;
}
__device__ __forceinline__ void cp16(uint32_t dst, const void* src) {
    asm volatile("cp.async.cg.shared.global [%0], [%1], 16;" :: "r"(dst), "l"(src));
}
#define CP_COMMIT()  asm volatile("cp.async.commit_group;" ::: "memory")
#define CP_WAIT(n)   asm volatile("cp.async.wait_group %0;" :: "n"(n) : "memory")

__device__ __forceinline__ void ldsm4(uint32_t (&r)[4], uint32_t a) {
    asm volatile("ldmatrix.sync.aligned.m8n8.x4.shared.b16 {%0,%1,%2,%3}, [%4];"
                 : "=r"(r[0]), "=r"(r[1]), "=r"(r[2]), "=r"(r[3]) : "r"(a));
}
__device__ __forceinline__ void ldsm4t(uint32_t (&r)[4], uint32_t a) {
    asm volatile("ldmatrix.sync.aligned.m8n8.x4.trans.shared.b16 {%0,%1,%2,%3}, [%4];"
                 : "=r"(r[0]), "=r"(r[1]), "=r"(r[2]), "=r"(r[3]) : "r"(a));
}
__device__ __forceinline__ void mma16816h(float* d, const uint32_t* a, uint32_t b0, uint32_t b1) {
    asm volatile(
        "mma.sync.aligned.m16n8k16.row.col.f32.f16.f16.f32 "
        "{%0,%1,%2,%3}, {%4,%5,%6,%7}, {%8,%9}, {%0,%1,%2,%3};"
        : "+f"(d[0]), "+f"(d[1]), "+f"(d[2]), "+f"(d[3])
        : "r"(a[0]), "r"(a[1]), "r"(a[2]), "r"(a[3]), "r"(b0), "r"(b1));
}
__device__ __forceinline__ uint32_t fp16pair(float a, float b) {
    __half2 t; t.x = __float2half(a); t.y = __float2half(b);
    uint32_t r; asm("mov.b32 %0, %1;" : "=r"(r) : "r"(*(uint32_t*)&t)); return r;
}

// ---------------- constants ----------------
__global__ void const_kernel() {
    int t = blockIdx.x * blockDim.x + threadIdx.x;
    if (t < 128) {
        g_invf[t] = pow(10000.0, -(double)t / 128.0);
        double sb = ((double)(2 * t) + 0.4 * 256.0) / (1.4 * 256.0);
        g_l2sb[t] = log2(sb);
    }
    if (t < SEQ) g_gamma[t] = (float)pow(0.96875, (double)t);
}

// ---------------- xpos sin/cos tables, RECENTERED scale ----------------
__global__ void tables_kernel() {
    int pos = blockIdx.x, j = threadIdx.x;
    float invf = (float)g_invf[j];
    float arg = (float)pos * invf;
    double ad = (double)arg;
    double qd = rint(ad * 0.63661977236758134308);
    double rd = fma(qd, -1.5707963267948966, ad);
    rd = fma(qd, -6.123233995736766e-17, rd);
    int qi = ((long long)qd) & 3;
    float rf = (float)rd;
    float sr = sinf(rf), cr = cosf(rf);
    float s, c;
    if      (qi == 0) { s =  sr; c =  cr; }
    else if (qi == 1) { s =  cr; c = -sr; }
    else if (qi == 2) { s = -sr; c = -cr; }
    else              { s = -cr; c =  sr; }
    // recentered exponent: (pos-2048)/512 in [-4,4] -> scale in [6.8e-3, 147]
    float p  = ((float)pos - 2048.0f) * (1.0f / 512.0f);
    float l2 = (float)g_l2sb[j];
    float sc  = exp2f(p * l2);       // Q scale (recentered)
    float isc = exp2f(-p * l2);      // K scale (recentered inverse)
    int idx = pos * 128 + j;
    g_cosQ[idx] = c * sc;   g_sinQ[idx] = s * sc;
    g_cosK[idx] = c * isc;  g_sinK[idx] = s * isc;
}

// ---------------- prep: X -> fp16 (8 floats/thread); W*1024 -> fp16 (hi, mid) ----------------
__global__ void splitx_kernel(const float* __restrict__ X) {
    size_t i = (size_t)blockIdx.x * blockDim.x + threadIdx.x;   // 8 floats each
    float4 a = ((const float4*)X)[2 * i];
    float4 b = ((const float4*)X)[2 * i + 1];
    uint4 o;
    o.x = fp16pair(a.x, a.y); o.y = fp16pair(a.z, a.w);
    o.z = fp16pair(b.x, b.y); o.w = fp16pair(b.z, b.w);
    ((uint4*)g_Xh)[i] = o;
}

__global__ void splitw_kernel(const float* __restrict__ WQ,
                              const float* __restrict__ WK,
                              const float* __restrict__ WV) {
    int idx = blockIdx.x * blockDim.x + threadIdx.x;   // [z][k][n], 3*1024*256
    int z = idx >> 18;
    int kn = idx & 0x3FFFF;
    const float* W = (z == 0) ? WQ : (z == 1 ? WK : WV);
    float w = W[kn] * 1024.0f;          // scale into fp16-normal range
    __half h = __float2half(w);
    g_Wh[idx] = h;
    g_Wm[idx] = __float2half(w - __half2float(h));
}

// ---------------- projection GEMM on mma.sync fp16 (split-2) ----------------
// CTA = 128M x 256N, K=1024 in 32 stages of KC=32, cp.async 3-stage ring.
#define PKC 32
#define PSTG_A 10240
#define PSTG_BYTES (PSTG_A + 32768)
#define PROJ_SMEM (3 * PSTG_BYTES)

__global__ void __launch_bounds__(256, 1) proj_mma_kernel()
{
    extern __shared__ __align__(1024) char sm[];
    uint32_t smb = smem_u32(sm);
    int tid = threadIdx.x;
    int z = blockIdx.x;
    int m0 = blockIdx.y * 128;

    const __half* Wh = g_Wh + (size_t)z * HID * HD;
    const __half* Wm = g_Wm + (size_t)z * HID * HD;

    // A copy: 2 chunks/thread
    const __half* srcA[2]; uint32_t dstA[2];
    #pragma unroll
    for (int i = 0; i < 2; i++) {
        int id = tid + i * 256;
        int m = id >> 2, c = id & 3;
        srcA[i] = g_Xh + (size_t)(m0 + m) * HID + c * 8;
        dstA[i] = (uint32_t)(m * 80 + c * 16);
    }
    // B copy: 8 chunks/thread
    const __half* srcB[8]; uint32_t dstB[8];
    #pragma unroll
    for (int i = 0; i < 8; i++) {
        int id = tid + i * 256;
        int k = id >> 6, cc = id & 63;
        int term = cc >> 5, n_c = cc & 31;
        srcB[i] = (term ? Wm : Wh) + (size_t)k * HD + n_c * 8;
        dstB[i] = (uint32_t)(PSTG_A + k * 1024 + ((cc ^ (k & 7)) << 4));
    }

    int w = tid >> 5, l = tid & 31;
    int wm = (w >> 2) * 64, wn = (w & 3) * 64;
    int la = l & 15, hsel = l >> 4;
    uint32_t bmx = (uint32_t)(la & 7);
    uint32_t brow = (uint32_t)(la * 1024);
    uint32_t bnc0 = (uint32_t)(wn >> 3);

    float d[4][8][4];
    #pragma unroll
    for (int mt = 0; mt < 4; mt++)
        #pragma unroll
        for (int nt = 0; nt < 8; nt++)
            #pragma unroll
            for (int r = 0; r < 4; r++) d[mt][nt][r] = 0.0f;

    // prologue: stages 0, 1
    #pragma unroll
    for (int p = 0; p < 2; p++) {
        uint32_t bb = smb + (uint32_t)p * PSTG_BYTES;
        int kt = p * PKC;
        #pragma unroll
        for (int i = 0; i < 2; i++) cp16(bb + dstA[i], srcA[i] + kt);
        #pragma unroll
        for (int i = 0; i < 8; i++) cp16(bb + dstB[i], srcB[i] + (size_t)kt * HD);
        CP_COMMIT();
    }

    int buf = 0, nbuf = 2;
    for (int s = 0; s < 32; s++) {
        if (s + 2 < 32) {
            uint32_t bb = smb + (uint32_t)nbuf * PSTG_BYTES;
            int kt = (s + 2) * PKC;
            #pragma unroll
            for (int i = 0; i < 2; i++) cp16(bb + dstA[i], srcA[i] + kt);
            #pragma unroll
            for (int i = 0; i < 8; i++) cp16(bb + dstB[i], srcB[i] + (size_t)kt * HD);
            CP_COMMIT();
            CP_WAIT(2);
        } else if (s + 1 < 32) {
            CP_WAIT(1);
        } else {
            CP_WAIT(0);
        }
        __syncthreads();

        uint32_t AS = smb + (uint32_t)buf * PSTG_BYTES;
        uint32_t BS = AS + PSTG_A;
        buf = (buf + 1 == 3) ? 0 : buf + 1;
        nbuf = (nbuf + 1 == 3) ? 0 : nbuf + 1;

        #pragma unroll
        for (int slab = 0; slab < 2; slab++) {
            uint32_t ah[4][4];
            #pragma unroll
            for (int mt = 0; mt < 4; mt++) {
                uint32_t row = (uint32_t)(wm + mt * 16 + la);
                ldsm4(ah[mt], AS + row * 80 + (uint32_t)((slab * 2 + hsel) * 16));
            }
            uint32_t krow = BS + (uint32_t)(slab * 16 * 1024) + brow;
            #pragma unroll
            for (int half = 0; half < 2; half++) {
                uint32_t bh[2][4], bm[2][4];
                #pragma unroll
                for (int j2 = 0; j2 < 2; j2++) {
                    uint32_t nc = bnc0 + (uint32_t)(half * 4 + j2 * 2 + hsel);
                    ldsm4t(bh[j2], krow + (((nc)       ^ bmx) << 4));
                    ldsm4t(bm[j2], krow + (((nc + 32u) ^ bmx) << 4));
                }
                #pragma unroll
                for (int nt = 0; nt < 4; nt++) {
                    uint32_t h0 = bh[nt >> 1][(nt & 1) * 2], h1 = bh[nt >> 1][(nt & 1) * 2 + 1];
                    uint32_t q0 = bm[nt >> 1][(nt & 1) * 2], q1 = bm[nt >> 1][(nt & 1) * 2 + 1];
                    #pragma unroll
                    for (int mt = 0; mt < 4; mt++) {
                        float* dd = d[mt][half * 4 + nt];
                        mma16816h(dd, ah[mt], h0, h1);   // Xh * Wh
                        mma16816h(dd, ah[mt], q0, q1);   // Xh * Wm
                    }
                }
            }
        }
        __syncthreads();
    }

    // ---- epilogue: unscale + recentered rotary (Q,K as single fp16) + store ----
    const float* ct = (z == 0) ? g_cosQ : g_cosK;
    const float* st = (z == 0) ? g_sinQ : g_sinK;
    __half* Oqk = (z == 0) ? g_Qh : g_Kh;
    const float DS = 0.0009765625f;     // 2^-10
    int mrb = m0 + wm + (l >> 2);
    int ncb = wn + (l & 3) * 2;
    #pragma unroll
    for (int mt = 0; mt < 4; mt++)
        #pragma unroll
        for (int r2 = 0; r2 < 2; r2++) {
            int m = mrb + mt * 16 + r2 * 8;
            int pos = m & (SEQ - 1);
            #pragma unroll
            for (int nt = 0; nt < 8; nt++) {
                int n = ncb + nt * 8;
                float v0 = d[mt][nt][r2 * 2] * DS, v1 = d[mt][nt][r2 * 2 + 1] * DS;
                if (z < 2) {
                    int j = n >> 1;
                    float C = ct[pos * 128 + j], S = st[pos * 128 + j];
                    float o0 = v0 * C - v1 * S;
                    float o1 = v1 * C + v0 * S;
                    *(uint32_t*)(Oqk + (size_t)m * HD + n) = fp16pair(o0, o1);
                } else {
                    *(uint32_t*)(g_Vf + (size_t)m * HD + n) = fp16pair(v0, v1);
                }
            }
        }
}

// ---------------- banded retention attention (all fp16 mma) ----------------
// phase1: Q,K single fp16 (recentered scale) -> 1 mma/step
// phase2: S hi/mid fp16 split-2 x V single fp16
#define ASM_Q  0
#define ASM_B0 32768
#define ASM_B1 65536
#define ASM_S  98304
#define ATTN_SMEM 114688

__device__ __forceinline__ uint32_t swzV(uint32_t row, uint32_t cc) {    // 512B rows
    return row * 512u + (((cc & 24u) | ((cc ^ row) & 7u)) << 4);
}
__device__ __forceinline__ uint32_t swzS(uint32_t row, uint32_t cc) {    // 256B rows
    return row * 256u + (((cc & 8u) | ((cc ^ row) & 7u)) << 4);
}

__global__ void __launch_bounds__(256, 2) attn_mma_kernel(float* __restrict__ out)
{
    extern __shared__ __align__(1024) char sm[];
    uint32_t smb = smem_u32(sm);
    int tid = threadIdx.x;
    int b = blockIdx.y;
    int q0 = blockIdx.x * 64;
    size_t base = (size_t)b * SEQ;

    // Q tile: 64 rows x 512B = 32KB
    #pragma unroll
    for (int i = 0; i < 8; i++) {
        int id = tid + i * 256;
        uint32_t row = (uint32_t)(id >> 5), cc = (uint32_t)(id & 31);
        cp16(smb + ASM_Q + swzV(row, cc), g_Qh + (base + q0 + row) * HD + cc * 8);
    }
    int kt_lo = q0 - DW; if (kt_lo < 0) kt_lo = 0;
    int nt = ((q0 - kt_lo) >> 6) + 1;
    #pragma unroll
    for (int i = 0; i < 8; i++) {       // K tile: 32KB
        int id = tid + i * 256;
        uint32_t row = (uint32_t)(id >> 5), cc = (uint32_t)(id & 31);
        cp16(smb + ASM_B0 + swzV(row, cc), g_Kh + (base + kt_lo + row) * HD + cc * 8);
    }
    CP_COMMIT();
    #pragma unroll
    for (int i = 0; i < 8; i++) {       // V tile: 32KB
        int id = tid + i * 256;
        uint32_t row = (uint32_t)(id >> 5), cc = (uint32_t)(id & 31);
        cp16(smb + ASM_B1 + swzV(row, cc), g_Vf + (base + kt_lo + row) * HD + cc * 8);
    }
    CP_COMMIT();

    int w = tid >> 5, l = tid & 31;
    int wm = w >> 2, wn = w & 3;
    uint32_t la = (uint32_t)(l & 15), hsel = (uint32_t)(l >> 4);

    float o[2][8][4];
    #pragma unroll
    for (int mt = 0; mt < 2; mt++)
        #pragma unroll
        for (int j = 0; j < 8; j++)
            #pragma unroll
            for (int r = 0; r < 4; r++) o[mt][j][r] = 0.0f;

    for (int it = 0; it < nt; it++) {
        int kt = kt_lo + it * 64;

        CP_WAIT(1);
        __syncthreads();

        // ---- phase 1: S = Q K^T, single fp16 mma ----
        float sacc[2][2][4];
        #pragma unroll
        for (int mt = 0; mt < 2; mt++)
            #pragma unroll
            for (int nti = 0; nti < 2; nti++)
                #pragma unroll
                for (int r = 0; r < 4; r++) sacc[mt][nti][r] = 0.0f;

        #pragma unroll 4
        for (int ks = 0; ks < 16; ks++) {
            uint32_t qf[2][4];
            #pragma unroll
            for (int mt = 0; mt < 2; mt++) {
                uint32_t row = (uint32_t)(wm * 32 + mt * 16) + la;
                ldsm4(qf[mt], smb + ASM_Q + swzV(row, (uint32_t)(ks * 2) + hsel));
            }
            uint32_t kf[4];
            {
                uint32_t row = (uint32_t)(wn * 16) + la;
                ldsm4(kf, smb + ASM_B0 + swzV(row, (uint32_t)(ks * 2) + hsel));
            }
            #pragma unroll
            for (int mt = 0; mt < 2; mt++)
                #pragma unroll
                for (int nti = 0; nti < 2; nti++)
                    mma16816h(sacc[mt][nti], qf[mt], kf[nti], kf[nti + 2]);
        }

        // ---- decay + fp16 split + stage S ----
        int dq = q0 - kt;
        #pragma unroll
        for (int mt = 0; mt < 2; mt++)
            #pragma unroll
            for (int nti = 0; nti < 2; nti++) {
                int qr0 = wm * 32 + mt * 16 + (l >> 2);
                int key = wn * 16 + nti * 8 + (l & 3) * 2;
                #pragma unroll
                for (int h = 0; h < 2; h++) {
                    int q = qr0 + 8 * h;
                    int e0 = dq + q - key;
                    float g0 = (e0 >= 0) ? g_gamma[e0] : 0.0f;
                    float g1 = (e0 >= 1) ? g_gamma[e0 - 1] : 0.0f;
                    float s0 = sacc[mt][nti][2 * h] * g0;
                    float s1 = sacc[mt][nti][2 * h + 1] * g1;
                    float h0f = __half2float(__float2half(s0));
                    float h1f = __half2float(__float2half(s1));
                    uint32_t hp = fp16pair(s0, s1);
                    uint32_t mp = fp16pair(s0 - h0f, s1 - h1f);
                    uint32_t cc = (uint32_t)(key >> 3);
                    uint32_t inb = (uint32_t)((key & 7) * 2);
                    *(uint32_t*)(sm + ASM_S + swzS((uint32_t)q, cc) + inb)      = hp;
                    *(uint32_t*)(sm + ASM_S + swzS((uint32_t)q, 8u + cc) + inb) = mp;
                }
            }
        __syncthreads();

        if (it + 1 < nt) {
            #pragma unroll
            for (int i = 0; i < 8; i++) {
                int id = tid + i * 256;
                uint32_t row = (uint32_t)(id >> 5), cc = (uint32_t)(id & 31);
                cp16(smb + ASM_B0 + swzV(row, cc),
                     g_Kh + (base + kt + 64 + row) * HD + cc * 8);
            }
            CP_COMMIT();
            CP_WAIT(1);
        } else {
            CP_WAIT(0);
        }
        __syncthreads();

        // ---- phase 2: O += S V, fp16 (split-2 x single) ----
        #pragma unroll
        for (int ks2 = 0; ks2 < 4; ks2++) {
            uint32_t sh[2][4], sd[2][4];
            #pragma unroll
            for (int mt = 0; mt < 2; mt++) {
                uint32_t row = (uint32_t)(wm * 32 + mt * 16) + la;
                ldsm4(sh[mt], smb + ASM_S + swzS(row, (uint32_t)(ks2 * 2) + hsel));
                ldsm4(sd[mt], smb + ASM_S + swzS(row, 8u + (uint32_t)(ks2 * 2) + hsel));
            }
            uint32_t vrow = (uint32_t)(ks2 * 16) + la;
            #pragma unroll
            for (int j = 0; j < 4; j++) {
                uint32_t vh[4];
                uint32_t cc = (uint32_t)(wn * 8 + j * 2) + hsel;
                ldsm4t(vh, smb + ASM_B1 + swzV(vrow, cc));
                #pragma unroll
                for (int nti = 0; nti < 2; nti++) {
                    uint32_t b0 = vh[nti * 2], b1 = vh[nti * 2 + 1];
                    #pragma unroll
                    for (int mt = 0; mt < 2; mt++) {
                        float* dd = o[mt][j * 2 + nti];
                        mma16816h(dd, sh[mt], b0, b1);   // Sh * V
                        mma16816h(dd, sd[mt], b0, b1);   // Sm * V
                    }
                }
            }
        }
        __syncthreads();

        if (it + 1 < nt) {
            #pragma unroll
            for (int i = 0; i < 8; i++) {
                int id = tid + i * 256;
                uint32_t row = (uint32_t)(id >> 5), cc = (uint32_t)(id & 31);
                cp16(smb + ASM_B1 + swzV(row, cc),
                     g_Vf + (base + kt + 64 + row) * HD + cc * 8);
            }
            CP_COMMIT();
        }
    }

    #pragma unroll
    for (int mt = 0; mt < 2; mt++)
        #pragma unroll
        for (int h = 0; h < 2; h++) {
            int q = q0 + wm * 32 + mt * 16 + (l >> 2) + 8 * h;
            size_t ro = (base + q) * (size_t)HD;
            #pragma unroll
            for (int j = 0; j < 8; j++) {
                int vd = wn * 64 + j * 8 + (l & 3) * 2;
                float2 v;
                v.x = o[mt][j][2 * h];
                v.y = o[mt][j][2 * h + 1];
                *(float2*)(out + ro + vd) = v;
            }
        }
}

// ---------------- launch ----------------
extern "C" void kernel_launch(void* const* d_in, const int* in_sizes, int n_in,
                              void* d_out, int out_size) {
    const float* X  = (const float*)d_in[0];
    const float* WQ = (const float*)d_in[1];
    const float* WK = (const float*)d_in[2];
    const float* WV = (const float*)d_in[3];
    float* out = (float*)d_out;

    const_kernel<<<16, 256>>>();
    tables_kernel<<<SEQ, 128>>>();

    splitx_kernel<<<(MTOT * HID / 8) / 256, 256>>>(X);
    splitw_kernel<<<(3 * HID * HD) / 256, 256>>>(WQ, WK, WV);

    cudaFuncSetAttribute(proj_mma_kernel, cudaFuncAttributeMaxDynamicSharedMemorySize,
                         PROJ_SMEM);
    dim3 pg(3, MTOT / 128);
    proj_mma_kernel<<<pg, 256, PROJ_SMEM>>>();

    cudaFuncSetAttribute(attn_mma_kernel, cudaFuncAttributeMaxDynamicSharedMemorySize,
                         ATTN_SMEM);
    dim3 ag(SEQ / 64, NB);
    attn_mma_kernel<<<ag, 256, ATTN_SMEM>>>(out);
}

// round 11
// speedup vs baseline: 4.8007x; 1.2971x over previous
#include <cuda_runtime.h>
#include <cuda_bf16.h>
#include <cuda_fp16.h>
#include <math.h>
#include <stdint.h>

#define SEQ 4096
#define NB 4
#define HID 1024
#define HD 256
#define MTOT (NB*SEQ)
#define DW 320            // gamma^320 ~ 3.9e-5 << error floor

typedef unsigned long long u64;

// ---------------- static device scratch (no cudaMalloc allowed) ----------------
// Q/K: single fp16 with RECENTERED xpos scale sb^((pos-2048)/512) (fits fp16 range)
__device__ __half g_Qh[(size_t)MTOT*HD];
__device__ __half g_Kh[(size_t)MTOT*HD];
__device__ __half g_Vf[(size_t)MTOT*HD];    // V plain fp16
__device__ __half g_Xh[(size_t)MTOT*HID];   // X fp16
__device__ __half g_Wh[3*HID*HD];           // [z][k][n], W*1024 as single fp16
__device__ float g_cosQ[SEQ*128];
__device__ float g_sinQ[SEQ*128];
__device__ float g_cosK[SEQ*128];
__device__ float g_sinK[SEQ*128];
__device__ float g_gamma[SEQ];
__device__ double g_invf[128];
__device__ double g_l2sb[128];

// ---------------- mma / async helpers (baseline PTX, sm_80+ ISA only) ----------------
__device__ __forceinline__ uint32_t smem_u32(const void* p) {
    uint32_t a;
    asm("{ .reg .u64 t; cvta.to.shared.u64 t, %1; cvt.u32.u64 %0, t; }" : "=r"(a) : "l"(p));
    return a;
}
__device__ __forceinline__ void cp16(uint32_t dst, const void* src) {
    asm volatile("cp.async.cg.shared.global [%0], [%1], 16;" :: "r"(dst), "l"(src));
}
#define CP_COMMIT()  asm volatile("cp.async.commit_group;" ::: "memory")
#define CP_WAIT(n)   asm volatile("cp.async.wait_group %0;" :: "n"(n) : "memory")

__device__ __forceinline__ void ldsm4(uint32_t (&r)[4], uint32_t a) {
    asm volatile("ldmatrix.sync.aligned.m8n8.x4.shared.b16 {%0,%1,%2,%3}, [%4];"
                 : "=r"(r[0]), "=r"(r[1]), "=r"(r[2]), "=r"(r[3]) : "r"(a));
}
__device__ __forceinline__ void ldsm4t(uint32_t (&r)[4], uint32_t a) {
    asm volatile("ldmatrix.sync.aligned.m8n8.x4.trans.shared.b16 {%0,%1,%2,%3}, [%4];"
                 : "=r"(r[0]), "=r"(r[1]), "=r"(r[2]), "=r"(r[3]) : "r"(a));
}
__device__ __forceinline__ void mma16816h(float* d, const uint32_t* a, uint32_t b0, uint32_t b1) {
    asm volatile(
        "mma.sync.aligned.m16n8k16.row.col.f32.f16.f16.f32 "
        "{%0,%1,%2,%3}, {%4,%5,%6,%7}, {%8,%9}, {%0,%1,%2,%3};"
        : "+f"(d[0]), "+f"(d[1]), "+f"(d[2]), "+f"(d[3])
        : "r"(a[0]), "r"(a[1]), "r"(a[2]), "r"(a[3]), "r"(b0), "r"(b1));
}
__device__ __forceinline__ uint32_t fp16pair(float a, float b) {
    __half2 t; t.x = __float2half(a); t.y = __float2half(b);
    uint32_t r; asm("mov.b32 %0, %1;" : "=r"(r) : "r"(*(uint32_t*)&t)); return r;
}

// ---------------- constants ----------------
__global__ void const_kernel() {
    int t = blockIdx.x * blockDim.x + threadIdx.x;
    if (t < 128) {
        g_invf[t] = pow(10000.0, -(double)t / 128.0);
        double sb = ((double)(2 * t) + 0.4 * 256.0) / (1.4 * 256.0);
        g_l2sb[t] = log2(sb);
    }
    if (t < SEQ) g_gamma[t] = (float)pow(0.96875, (double)t);
}

// ---------------- xpos sin/cos tables, RECENTERED scale ----------------
__global__ void tables_kernel() {
    int pos = blockIdx.x, j = threadIdx.x;
    float invf = (float)g_invf[j];
    float arg = (float)pos * invf;
    double ad = (double)arg;
    double qd = rint(ad * 0.63661977236758134308);
    double rd = fma(qd, -1.5707963267948966, ad);
    rd = fma(qd, -6.123233995736766e-17, rd);
    int qi = ((long long)qd) & 3;
    float rf = (float)rd;
    float sr = sinf(rf), cr = cosf(rf);
    float s, c;
    if      (qi == 0) { s =  sr; c =  cr; }
    else if (qi == 1) { s =  cr; c = -sr; }
    else if (qi == 2) { s = -sr; c = -cr; }
    else              { s = -cr; c =  sr; }
    // recentered exponent: (pos-2048)/512 in [-4,4] -> scale in [6.8e-3, 147]
    float p  = ((float)pos - 2048.0f) * (1.0f / 512.0f);
    float l2 = (float)g_l2sb[j];
    float sc  = exp2f(p * l2);
    float isc = exp2f(-p * l2);
    int idx = pos * 128 + j;
    g_cosQ[idx] = c * sc;   g_sinQ[idx] = s * sc;
    g_cosK[idx] = c * isc;  g_sinK[idx] = s * isc;
}

// ---------------- prep: X -> fp16 (8 floats/thread); W*1024 -> fp16 ----------------
__global__ void splitx_kernel(const float* __restrict__ X) {
    size_t i = (size_t)blockIdx.x * blockDim.x + threadIdx.x;   // 8 floats each
    float4 a = ((const float4*)X)[2 * i];
    float4 b = ((const float4*)X)[2 * i + 1];
    uint4 o;
    o.x = fp16pair(a.x, a.y); o.y = fp16pair(a.z, a.w);
    o.z = fp16pair(b.x, b.y); o.w = fp16pair(b.z, b.w);
    ((uint4*)g_Xh)[i] = o;
}

__global__ void splitw_kernel(const float* __restrict__ WQ,
                              const float* __restrict__ WK,
                              const float* __restrict__ WV) {
    int idx = blockIdx.x * blockDim.x + threadIdx.x;   // [z][k][n], 3*1024*256
    int z = idx >> 18;
    int kn = idx & 0x3FFFF;
    const float* W = (z == 0) ? WQ : (z == 1 ? WK : WV);
    g_Wh[idx] = __float2half(W[kn] * 1024.0f);   // scale into fp16-normal range
}

// ---------------- projection GEMM on mma.sync fp16 (single term) ----------------
// CTA = 128M x 256N, K=1024 in 32 stages of KC=32, cp.async 4-stage ring.
#define PKC 32
#define PSTG_A 10240
#define PSTG_B 16384
#define PSTG_BYTES (PSTG_A + PSTG_B)
#define PROJ_SMEM (4 * PSTG_BYTES)

__global__ void __launch_bounds__(256, 1) proj_mma_kernel()
{
    extern __shared__ __align__(1024) char sm[];
    uint32_t smb = smem_u32(sm);
    int tid = threadIdx.x;
    int z = blockIdx.x;
    int m0 = blockIdx.y * 128;

    const __half* Wh = g_Wh + (size_t)z * HID * HD;

    // A copy: 2 chunks/thread (128 rows x 64B, 80B stride)
    const __half* srcA[2]; uint32_t dstA[2];
    #pragma unroll
    for (int i = 0; i < 2; i++) {
        int id = tid + i * 256;
        int m = id >> 2, c = id & 3;
        srcA[i] = g_Xh + (size_t)(m0 + m) * HID + c * 8;
        dstA[i] = (uint32_t)(m * 80 + c * 16);
    }
    // B copy: 4 chunks/thread (32 k-rows x 512B, XOR swizzle)
    const __half* srcB[4]; uint32_t dstB[4];
    #pragma unroll
    for (int i = 0; i < 4; i++) {
        int id = tid + i * 256;
        int k = id >> 5, cc = id & 31;
        srcB[i] = Wh + (size_t)k * HD + cc * 8;
        dstB[i] = (uint32_t)(PSTG_A + k * 512 + ((cc ^ (k & 7)) << 4));
    }

    int w = tid >> 5, l = tid & 31;
    int wm = (w >> 2) * 64, wn = (w & 3) * 64;
    int la = l & 15, hsel = l >> 4;
    uint32_t bmx = (uint32_t)(la & 7);
    uint32_t brow = (uint32_t)(la * 512);
    uint32_t bnc0 = (uint32_t)(wn >> 3);

    float d[4][8][4];
    #pragma unroll
    for (int mt = 0; mt < 4; mt++)
        #pragma unroll
        for (int nt = 0; nt < 8; nt++)
            #pragma unroll
            for (int r = 0; r < 4; r++) d[mt][nt][r] = 0.0f;

    // prologue: stages 0..2
    #pragma unroll
    for (int p = 0; p < 3; p++) {
        uint32_t bb = smb + (uint32_t)p * PSTG_BYTES;
        int kt = p * PKC;
        #pragma unroll
        for (int i = 0; i < 2; i++) cp16(bb + dstA[i], srcA[i] + kt);
        #pragma unroll
        for (int i = 0; i < 4; i++) cp16(bb + dstB[i], srcB[i] + (size_t)kt * HD);
        CP_COMMIT();
    }

    for (int s = 0; s < 32; s++) {
        if (s + 3 < 32) {
            uint32_t bb = smb + (uint32_t)((s + 3) & 3) * PSTG_BYTES;
            int kt = (s + 3) * PKC;
            #pragma unroll
            for (int i = 0; i < 2; i++) cp16(bb + dstA[i], srcA[i] + kt);
            #pragma unroll
            for (int i = 0; i < 4; i++) cp16(bb + dstB[i], srcB[i] + (size_t)kt * HD);
            CP_COMMIT();
            CP_WAIT(3);
        } else if (s + 2 < 32) {
            CP_WAIT(2);
        } else if (s + 1 < 32) {
            CP_WAIT(1);
        } else {
            CP_WAIT(0);
        }
        __syncthreads();

        uint32_t AS = smb + (uint32_t)(s & 3) * PSTG_BYTES;
        uint32_t BS = AS + PSTG_A;

        #pragma unroll
        for (int slab = 0; slab < 2; slab++) {
            uint32_t ah[4][4];
            #pragma unroll
            for (int mt = 0; mt < 4; mt++) {
                uint32_t row = (uint32_t)(wm + mt * 16 + la);
                ldsm4(ah[mt], AS + row * 80 + (uint32_t)((slab * 2 + hsel) * 16));
            }
            uint32_t krow = BS + (uint32_t)(slab * 16 * 512) + brow;
            #pragma unroll
            for (int half = 0; half < 2; half++) {
                uint32_t bh[2][4];
                #pragma unroll
                for (int j2 = 0; j2 < 2; j2++) {
                    uint32_t nc = bnc0 + (uint32_t)(half * 4 + j2 * 2 + hsel);
                    ldsm4t(bh[j2], krow + ((nc ^ bmx) << 4));
                }
                #pragma unroll
                for (int nt = 0; nt < 4; nt++) {
                    uint32_t h0 = bh[nt >> 1][(nt & 1) * 2], h1 = bh[nt >> 1][(nt & 1) * 2 + 1];
                    #pragma unroll
                    for (int mt = 0; mt < 4; mt++)
                        mma16816h(d[mt][half * 4 + nt], ah[mt], h0, h1);
                }
            }
        }
        __syncthreads();
    }

    // ---- epilogue: unscale + recentered rotary (Q,K) + store fp16 ----
    const float* ct = (z == 0) ? g_cosQ : g_cosK;
    const float* st = (z == 0) ? g_sinQ : g_sinK;
    __half* Oqk = (z == 0) ? g_Qh : g_Kh;
    const float DS = 0.0009765625f;     // 2^-10
    int mrb = m0 + wm + (l >> 2);
    int ncb = wn + (l & 3) * 2;
    #pragma unroll
    for (int mt = 0; mt < 4; mt++)
        #pragma unroll
        for (int r2 = 0; r2 < 2; r2++) {
            int m = mrb + mt * 16 + r2 * 8;
            int pos = m & (SEQ - 1);
            #pragma unroll
            for (int nt = 0; nt < 8; nt++) {
                int n = ncb + nt * 8;
                float v0 = d[mt][nt][r2 * 2] * DS, v1 = d[mt][nt][r2 * 2 + 1] * DS;
                if (z < 2) {
                    int j = n >> 1;
                    float C = ct[pos * 128 + j], S = st[pos * 128 + j];
                    float o0 = v0 * C - v1 * S;
                    float o1 = v1 * C + v0 * S;
                    *(uint32_t*)(Oqk + (size_t)m * HD + n) = fp16pair(o0, o1);
                } else {
                    *(uint32_t*)(g_Vf + (size_t)m * HD + n) = fp16pair(v0, v1);
                }
            }
        }
}

// ---------------- banded retention attention (all fp16 mma) ----------------
// phase1: Q,K single fp16 (recentered scale) -> 1 mma/step
// phase2: S hi/mid fp16 split-2 x V single fp16
#define ASM_Q  0
#define ASM_B0 32768
#define ASM_B1 65536
#define ASM_S  98304
#define ATTN_SMEM 114688

__device__ __forceinline__ uint32_t swzV(uint32_t row, uint32_t cc) {    // 512B rows
    return row * 512u + (((cc & 24u) | ((cc ^ row) & 7u)) << 4);
}
__device__ __forceinline__ uint32_t swzS(uint32_t row, uint32_t cc) {    // 256B rows
    return row * 256u + (((cc & 8u) | ((cc ^ row) & 7u)) << 4);
}

__global__ void __launch_bounds__(256, 2) attn_mma_kernel(float* __restrict__ out)
{
    extern __shared__ __align__(1024) char sm[];
    uint32_t smb = smem_u32(sm);
    int tid = threadIdx.x;
    int b = blockIdx.y;
    int q0 = blockIdx.x * 64;
    size_t base = (size_t)b * SEQ;

    // Q tile: 64 rows x 512B = 32KB
    #pragma unroll
    for (int i = 0; i < 8; i++) {
        int id = tid + i * 256;
        uint32_t row = (uint32_t)(id >> 5), cc = (uint32_t)(id & 31);
        cp16(smb + ASM_Q + swzV(row, cc), g_Qh + (base + q0 + row) * HD + cc * 8);
    }
    int kt_lo = q0 - DW; if (kt_lo < 0) kt_lo = 0;
    int nt = ((q0 - kt_lo) >> 6) + 1;
    #pragma unroll
    for (int i = 0; i < 8; i++) {       // K tile: 32KB
        int id = tid + i * 256;
        uint32_t row = (uint32_t)(id >> 5), cc = (uint32_t)(id & 31);
        cp16(smb + ASM_B0 + swzV(row, cc), g_Kh + (base + kt_lo + row) * HD + cc * 8);
    }
    CP_COMMIT();
    #pragma unroll
    for (int i = 0; i < 8; i++) {       // V tile: 32KB
        int id = tid + i * 256;
        uint32_t row = (uint32_t)(id >> 5), cc = (uint32_t)(id & 31);
        cp16(smb + ASM_B1 + swzV(row, cc), g_Vf + (base + kt_lo + row) * HD + cc * 8);
    }
    CP_COMMIT();

    int w = tid >> 5, l = tid & 31;
    int wm = w >> 2, wn = w & 3;
    uint32_t la = (uint32_t)(l & 15), hsel = (uint32_t)(l >> 4);

    float o[2][8][4];
    #pragma unroll
    for (int mt = 0; mt < 2; mt++)
        #pragma unroll
        for (int j = 0; j < 8; j++)
            #pragma unroll
            for (int r = 0; r < 4; r++) o[mt][j][r] = 0.0f;

    for (int it = 0; it < nt; it++) {
        int kt = kt_lo + it * 64;

        CP_WAIT(1);
        __syncthreads();

        // ---- phase 1: S = Q K^T, single fp16 mma ----
        float sacc[2][2][4];
        #pragma unroll
        for (int mt = 0; mt < 2; mt++)
            #pragma unroll
            for (int nti = 0; nti < 2; nti++)
                #pragma unroll
                for (int r = 0; r < 4; r++) sacc[mt][nti][r] = 0.0f;

        #pragma unroll 4
        for (int ks = 0; ks < 16; ks++) {
            uint32_t qf[2][4];
            #pragma unroll
            for (int mt = 0; mt < 2; mt++) {
                uint32_t row = (uint32_t)(wm * 32 + mt * 16) + la;
                ldsm4(qf[mt], smb + ASM_Q + swzV(row, (uint32_t)(ks * 2) + hsel));
            }
            uint32_t kf[4];
            {
                uint32_t row = (uint32_t)(wn * 16) + la;
                ldsm4(kf, smb + ASM_B0 + swzV(row, (uint32_t)(ks * 2) + hsel));
            }
            #pragma unroll
            for (int mt = 0; mt < 2; mt++)
                #pragma unroll
                for (int nti = 0; nti < 2; nti++)
                    mma16816h(sacc[mt][nti], qf[mt], kf[nti], kf[nti + 2]);
        }

        // ---- decay + fp16 split + stage S ----
        int dq = q0 - kt;
        #pragma unroll
        for (int mt = 0; mt < 2; mt++)
            #pragma unroll
            for (int nti = 0; nti < 2; nti++) {
                int qr0 = wm * 32 + mt * 16 + (l >> 2);
                int key = wn * 16 + nti * 8 + (l & 3) * 2;
                #pragma unroll
                for (int h = 0; h < 2; h++) {
                    int q = qr0 + 8 * h;
                    int e0 = dq + q - key;
                    float g0 = (e0 >= 0) ? g_gamma[e0] : 0.0f;
                    float g1 = (e0 >= 1) ? g_gamma[e0 - 1] : 0.0f;
                    float s0 = sacc[mt][nti][2 * h] * g0;
                    float s1 = sacc[mt][nti][2 * h + 1] * g1;
                    float h0f = __half2float(__float2half(s0));
                    float h1f = __half2float(__float2half(s1));
                    uint32_t hp = fp16pair(s0, s1);
                    uint32_t mp = fp16pair(s0 - h0f, s1 - h1f);
                    uint32_t cc = (uint32_t)(key >> 3);
                    uint32_t inb = (uint32_t)((key & 7) * 2);
                    *(uint32_t*)(sm + ASM_S + swzS((uint32_t)q, cc) + inb)      = hp;
                    *(uint32_t*)(sm + ASM_S + swzS((uint32_t)q, 8u + cc) + inb) = mp;
                }
            }
        __syncthreads();

        if (it + 1 < nt) {
            #pragma unroll
            for (int i = 0; i < 8; i++) {
                int id = tid + i * 256;
                uint32_t row = (uint32_t)(id >> 5), cc = (uint32_t)(id & 31);
                cp16(smb + ASM_B0 + swzV(row, cc),
                     g_Kh + (base + kt + 64 + row) * HD + cc * 8);
            }
            CP_COMMIT();
            CP_WAIT(1);
        } else {
            CP_WAIT(0);
        }
        __syncthreads();

        // ---- phase 2: O += S V, fp16 (split-2 x single) ----
        #pragma unroll
        for (int ks2 = 0; ks2 < 4; ks2++) {
            uint32_t sh[2][4], sd[2][4];
            #pragma unroll
            for (int mt = 0; mt < 2; mt++) {
                uint32_t row = (uint32_t)(wm * 32 + mt * 16) + la;
                ldsm4(sh[mt], smb + ASM_S + swzS(row, (uint32_t)(ks2 * 2) + hsel));
                ldsm4(sd[mt], smb + ASM_S + swzS(row, 8u + (uint32_t)(ks2 * 2) + hsel));
            }
            uint32_t vrow = (uint32_t)(ks2 * 16) + la;
            #pragma unroll
            for (int j = 0; j < 4; j++) {
                uint32_t vh[4];
                uint32_t cc = (uint32_t)(wn * 8 + j * 2) + hsel;
                ldsm4t(vh, smb + ASM_B1 + swzV(vrow, cc));
                #pragma unroll
                for (int nti = 0; nti < 2; nti++) {
                    uint32_t b0 = vh[nti * 2], b1 = vh[nti * 2 + 1];
                    #pragma unroll
                    for (int mt = 0; mt < 2; mt++) {
                        float* dd = o[mt][j * 2 + nti];
                        mma16816h(dd, sh[mt], b0, b1);   // Sh * V
                        mma16816h(dd, sd[mt], b0, b1);   // Sm * V
                    }
                }
            }
        }
        __syncthreads();

        if (it + 1 < nt) {
            #pragma unroll
            for (int i = 0; i < 8; i++) {
                int id = tid + i * 256;
                uint32_t row = (uint32_t)(id >> 5), cc = (uint32_t)(id & 31);
                cp16(smb + ASM_B1 + swzV(row, cc),
                     g_Vf + (base + kt + 64 + row) * HD + cc * 8);
            }
            CP_COMMIT();
        }
    }

    #pragma unroll
    for (int mt = 0; mt < 2; mt++)
        #pragma unroll
        for (int h = 0; h < 2; h++) {
            int q = q0 + wm * 32 + mt * 16 + (l >> 2) + 8 * h;
            size_t ro = (base + q) * (size_t)HD;
            #pragma unroll
            for (int j = 0; j < 8; j++) {
                int vd = wn * 64 + j * 8 + (l & 3) * 2;
                float2 v;
                v.x = o[mt][j][2 * h];
                v.y = o[mt][j][2 * h + 1];
                *(float2*)(out + ro + vd) = v;
            }
        }
}

// ---------------- launch ----------------
extern "C" void kernel_launch(void* const* d_in, const int* in_sizes, int n_in,
                              void* d_out, int out_size) {
    const float* X  = (const float*)d_in[0];
    const float* WQ = (const float*)d_in[1];
    const float* WK = (const float*)d_in[2];
    const float* WV = (const float*)d_in[3];
    float* out = (float*)d_out;

    const_kernel<<<16, 256>>>();
    tables_kernel<<<SEQ, 128>>>();

    splitx_kernel<<<(MTOT * HID / 8) / 256, 256>>>(X);
    splitw_kernel<<<(3 * HID * HD) / 256, 256>>>(WQ, WK, WV);

    cudaFuncSetAttribute(proj_mma_kernel, cudaFuncAttributeMaxDynamicSharedMemorySize,
                         PROJ_SMEM);
    dim3 pg(3, MTOT / 128);
    proj_mma_kernel<<<pg, 256, PROJ_SMEM>>>();

    cudaFuncSetAttribute(attn_mma_kernel, cudaFuncAttributeMaxDynamicSharedMemorySize,
                         ATTN_SMEM);
    dim3 ag(SEQ / 64, NB);
    attn_mma_kernel<<<ag, 256, ATTN_SMEM>>>(out);
}

// round 12
// speedup vs baseline: 5.4233x; 1.1297x over previous
#include <cuda_runtime.h>
#include <cuda_bf16.h>
#include <cuda_fp16.h>
#include <math.h>
#include <stdint.h>

#define SEQ 4096
#define NB 4
#define HID 1024
#define HD 256
#define MTOT (NB*SEQ)
#define DW 256            // gamma^256 ~ 2.9e-4, inside remaining error budget

typedef unsigned long long u64;

// ---------------- static device scratch (no cudaMalloc allowed) ----------------
__device__ __half g_Qh[(size_t)MTOT*HD];    // recentered xpos scale, fp16
__device__ __half g_Kh[(size_t)MTOT*HD];
__device__ __half g_Vf[(size_t)MTOT*HD];
__device__ __half g_Xh[(size_t)MTOT*HID];
__device__ __half g_Wh[3*HID*HD];           // [z][k][n], W*1024 fp16
__device__ float g_cosQ[SEQ*128];
__device__ float g_sinQ[SEQ*128];
__device__ float g_cosK[SEQ*128];
__device__ float g_sinK[SEQ*128];
__device__ float g_gamma[SEQ];
__device__ double g_invf[128];
__device__ double g_l2sb[128];

// ---------------- mma / async helpers (baseline PTX, sm_80+ ISA only) ----------------
__device__ __forceinline__ uint32_t smem_u32(const void* p) {
    uint32_t a;
    asm("{ .reg .u64 t; cvta.to.shared.u64 t, %1; cvt.u32.u64 %0, t; }" : "=r"(a) : "l"(p));
    return a;
}
__device__ __forceinline__ void cp16(uint32_t dst, const void* src) {
    asm volatile("cp.async.cg.shared.global [%0], [%1], 16;" :: "r"(dst), "l"(src));
}
#define CP_COMMIT()  asm volatile("cp.async.commit_group;" ::: "memory")
#define CP_WAIT(n)   asm volatile("cp.async.wait_group %0;" :: "n"(n) : "memory")

__device__ __forceinline__ void ldsm4(uint32_t (&r)[4], uint32_t a) {
    asm volatile("ldmatrix.sync.aligned.m8n8.x4.shared.b16 {%0,%1,%2,%3}, [%4];"
                 : "=r"(r[0]), "=r"(r[1]), "=r"(r[2]), "=r"(r[3]) : "r"(a));
}
__device__ __forceinline__ void ldsm4t(uint32_t (&r)[4], uint32_t a) {
    asm volatile("ldmatrix.sync.aligned.m8n8.x4.trans.shared.b16 {%0,%1,%2,%3}, [%4];"
                 : "=r"(r[0]), "=r"(r[1]), "=r"(r[2]), "=r"(r[3]) : "r"(a));
}
__device__ __forceinline__ void mma16816h(float* d, const uint32_t* a, uint32_t b0, uint32_t b1) {
    asm volatile(
        "mma.sync.aligned.m16n8k16.row.col.f32.f16.f16.f32 "
        "{%0,%1,%2,%3}, {%4,%5,%6,%7}, {%8,%9}, {%0,%1,%2,%3};"
        : "+f"(d[0]), "+f"(d[1]), "+f"(d[2]), "+f"(d[3])
        : "r"(a[0]), "r"(a[1]), "r"(a[2]), "r"(a[3]), "r"(b0), "r"(b1));
}
__device__ __forceinline__ uint32_t fp16pair(float a, float b) {
    __half2 t; t.x = __float2half(a); t.y = __float2half(b);
    uint32_t r; asm("mov.b32 %0, %1;" : "=r"(r) : "r"(*(uint32_t*)&t)); return r;
}

// ---------------- constants ----------------
__global__ void const_kernel() {
    int t = blockIdx.x * blockDim.x + threadIdx.x;
    if (t < 128) {
        g_invf[t] = pow(10000.0, -(double)t / 128.0);
        double sb = ((double)(2 * t) + 0.4 * 256.0) / (1.4 * 256.0);
        g_l2sb[t] = log2(sb);
    }
    if (t < SEQ) g_gamma[t] = (float)pow(0.96875, (double)t);
}

// ---------------- xpos sin/cos tables, RECENTERED scale ----------------
__global__ void tables_kernel() {
    int pos = blockIdx.x, j = threadIdx.x;
    float invf = (float)g_invf[j];
    float arg = (float)pos * invf;
    double ad = (double)arg;
    double qd = rint(ad * 0.63661977236758134308);
    double rd = fma(qd, -1.5707963267948966, ad);
    rd = fma(qd, -6.123233995736766e-17, rd);
    int qi = ((long long)qd) & 3;
    float rf = (float)rd;
    float sr = sinf(rf), cr = cosf(rf);
    float s, c;
    if      (qi == 0) { s =  sr; c =  cr; }
    else if (qi == 1) { s =  cr; c = -sr; }
    else if (qi == 2) { s = -sr; c = -cr; }
    else              { s = -cr; c =  sr; }
    float p  = ((float)pos - 2048.0f) * (1.0f / 512.0f);   // recentered
    float l2 = (float)g_l2sb[j];
    float sc  = exp2f(p * l2);
    float isc = exp2f(-p * l2);
    int idx = pos * 128 + j;
    g_cosQ[idx] = c * sc;   g_sinQ[idx] = s * sc;
    g_cosK[idx] = c * isc;  g_sinK[idx] = s * isc;
}

// ---------------- prep ----------------
__global__ void splitx_kernel(const float* __restrict__ X) {
    size_t i = (size_t)blockIdx.x * blockDim.x + threadIdx.x;   // 8 floats each
    float4 a = ((const float4*)X)[2 * i];
    float4 b = ((const float4*)X)[2 * i + 1];
    uint4 o;
    o.x = fp16pair(a.x, a.y); o.y = fp16pair(a.z, a.w);
    o.z = fp16pair(b.x, b.y); o.w = fp16pair(b.z, b.w);
    ((uint4*)g_Xh)[i] = o;
}

__global__ void splitw_kernel(const float* __restrict__ WQ,
                              const float* __restrict__ WK,
                              const float* __restrict__ WV) {
    int idx = blockIdx.x * blockDim.x + threadIdx.x;   // [z][k][n], 3*1024*256
    int z = idx >> 18;
    int kn = idx & 0x3FFFF;
    const float* W = (z == 0) ? WQ : (z == 1 ? WK : WV);
    g_Wh[idx] = __float2half(W[kn] * 1024.0f);
}

// ---------------- projection GEMM, fp16 single term, 2 CTAs/SM ----------------
// CTA = 128M x 128N, warp tile 32x64, K=1024 in 32 stages of KC=32, 4-stage ring.
#define PKC 32
#define PSTG_A 10240
#define PSTG_B 8192
#define PSTG_BYTES (PSTG_A + PSTG_B)
#define PROJ_SMEM (4 * PSTG_BYTES)

__global__ void __launch_bounds__(256, 2) proj_mma_kernel()
{
    extern __shared__ __align__(1024) char sm[];
    uint32_t smb = smem_u32(sm);
    int tid = threadIdx.x;
    int z  = blockIdx.x >> 1;
    int n0 = (blockIdx.x & 1) * 128;
    int m0 = blockIdx.y * 128;

    const __half* Wh = g_Wh + (size_t)z * HID * HD + n0;

    // A copy: 2 chunks/thread (128 rows x 64B, 80B stride)
    const __half* srcA[2]; uint32_t dstA[2];
    #pragma unroll
    for (int i = 0; i < 2; i++) {
        int id = tid + i * 256;
        int m = id >> 2, c = id & 3;
        srcA[i] = g_Xh + (size_t)(m0 + m) * HID + c * 8;
        dstA[i] = (uint32_t)(m * 80 + c * 16);
    }
    // B copy: 2 chunks/thread (32 k-rows x 256B, swzS-style swizzle)
    const __half* srcB[2]; uint32_t dstB[2];
    #pragma unroll
    for (int i = 0; i < 2; i++) {
        int id = tid + i * 256;
        int k = id >> 4, cc = id & 15;
        srcB[i] = Wh + (size_t)k * HD + cc * 8;
        dstB[i] = (uint32_t)(PSTG_A + k * 256 +
                             ((uint32_t)((cc & 8) | ((cc ^ (k & 7)) & 7)) << 4));
    }

    int w = tid >> 5, l = tid & 31;
    int wm = w >> 1, wn = w & 1;          // 4 M-groups x 2 N-groups
    int la = l & 15, hsel = l >> 4;
    uint32_t lam = (uint32_t)(la & 7);
    uint32_t brow = (uint32_t)(la * 256);
    uint32_t bnc0 = (uint32_t)(wn * 8);

    float d[2][8][4];
    #pragma unroll
    for (int mt = 0; mt < 2; mt++)
        #pragma unroll
        for (int nt = 0; nt < 8; nt++)
            #pragma unroll
            for (int r = 0; r < 4; r++) d[mt][nt][r] = 0.0f;

    // prologue: stages 0..2
    #pragma unroll
    for (int p = 0; p < 3; p++) {
        uint32_t bb = smb + (uint32_t)p * PSTG_BYTES;
        int kt = p * PKC;
        #pragma unroll
        for (int i = 0; i < 2; i++) cp16(bb + dstA[i], srcA[i] + kt);
        #pragma unroll
        for (int i = 0; i < 2; i++) cp16(bb + dstB[i], srcB[i] + (size_t)kt * HD);
        CP_COMMIT();
    }

    for (int s = 0; s < 32; s++) {
        if (s + 3 < 32) {
            uint32_t bb = smb + (uint32_t)((s + 3) & 3) * PSTG_BYTES;
            int kt = (s + 3) * PKC;
            #pragma unroll
            for (int i = 0; i < 2; i++) cp16(bb + dstA[i], srcA[i] + kt);
            #pragma unroll
            for (int i = 0; i < 2; i++) cp16(bb + dstB[i], srcB[i] + (size_t)kt * HD);
            CP_COMMIT();
            CP_WAIT(3);
        } else if (s + 2 < 32) {
            CP_WAIT(2);
        } else if (s + 1 < 32) {
            CP_WAIT(1);
        } else {
            CP_WAIT(0);
        }
        __syncthreads();

        uint32_t AS = smb + (uint32_t)(s & 3) * PSTG_BYTES;
        uint32_t BS = AS + PSTG_A;

        #pragma unroll
        for (int slab = 0; slab < 2; slab++) {
            uint32_t ah[2][4];
            #pragma unroll
            for (int mt = 0; mt < 2; mt++) {
                uint32_t row = (uint32_t)(wm * 32 + mt * 16 + la);
                ldsm4(ah[mt], AS + row * 80 + (uint32_t)((slab * 2 + hsel) * 16));
            }
            uint32_t krow = BS + (uint32_t)(slab * 16 * 256) + brow;
            #pragma unroll
            for (int half = 0; half < 2; half++) {
                uint32_t bh[2][4];
                #pragma unroll
                for (int j2 = 0; j2 < 2; j2++) {
                    uint32_t nc = bnc0 + (uint32_t)(half * 4 + j2 * 2 + hsel);
                    ldsm4t(bh[j2], krow + (((nc & 8u) | ((nc ^ lam) & 7u)) << 4));
                }
                #pragma unroll
                for (int nt = 0; nt < 4; nt++) {
                    uint32_t h0 = bh[nt >> 1][(nt & 1) * 2], h1 = bh[nt >> 1][(nt & 1) * 2 + 1];
                    #pragma unroll
                    for (int mt = 0; mt < 2; mt++)
                        mma16816h(d[mt][half * 4 + nt], ah[mt], h0, h1);
                }
            }
        }
        __syncthreads();
    }

    // ---- epilogue: unscale + recentered rotary (Q,K) + store fp16 ----
    const float* ct = (z == 0) ? g_cosQ : g_cosK;
    const float* st = (z == 0) ? g_sinQ : g_sinK;
    __half* Oqk = (z == 0) ? g_Qh : g_Kh;
    const float DS = 0.0009765625f;     // 2^-10
    int mrb = m0 + wm * 32 + (l >> 2);
    int ncb = n0 + wn * 64 + (l & 3) * 2;
    #pragma unroll
    for (int mt = 0; mt < 2; mt++)
        #pragma unroll
        for (int r2 = 0; r2 < 2; r2++) {
            int m = mrb + mt * 16 + r2 * 8;
            int pos = m & (SEQ - 1);
            #pragma unroll
            for (int nt = 0; nt < 8; nt++) {
                int n = ncb + nt * 8;
                float v0 = d[mt][nt][r2 * 2] * DS, v1 = d[mt][nt][r2 * 2 + 1] * DS;
                if (z < 2) {
                    int j = n >> 1;
                    float C = ct[pos * 128 + j], S = st[pos * 128 + j];
                    float o0 = v0 * C - v1 * S;
                    float o1 = v1 * C + v0 * S;
                    *(uint32_t*)(Oqk + (size_t)m * HD + n) = fp16pair(o0, o1);
                } else {
                    *(uint32_t*)(g_Vf + (size_t)m * HD + n) = fp16pair(v0, v1);
                }
            }
        }
}

// ---------------- banded retention attention (all fp16 mma) ----------------
#define ASM_Q  0
#define ASM_B0 32768
#define ASM_B1 65536
#define ASM_S  98304
#define ATTN_SMEM 114688

__device__ __forceinline__ uint32_t swzV(uint32_t row, uint32_t cc) {    // 512B rows
    return row * 512u + (((cc & 24u) | ((cc ^ row) & 7u)) << 4);
}
__device__ __forceinline__ uint32_t swzS(uint32_t row, uint32_t cc) {    // 256B rows
    return row * 256u + (((cc & 8u) | ((cc ^ row) & 7u)) << 4);
}

__global__ void __launch_bounds__(256, 2) attn_mma_kernel(float* __restrict__ out)
{
    extern __shared__ __align__(1024) char sm[];
    uint32_t smb = smem_u32(sm);
    int tid = threadIdx.x;
    int b = blockIdx.y;
    int q0 = blockIdx.x * 64;
    size_t base = (size_t)b * SEQ;

    #pragma unroll
    for (int i = 0; i < 8; i++) {
        int id = tid + i * 256;
        uint32_t row = (uint32_t)(id >> 5), cc = (uint32_t)(id & 31);
        cp16(smb + ASM_Q + swzV(row, cc), g_Qh + (base + q0 + row) * HD + cc * 8);
    }
    int kt_lo = q0 - DW; if (kt_lo < 0) kt_lo = 0;
    int nt = ((q0 - kt_lo) >> 6) + 1;
    #pragma unroll
    for (int i = 0; i < 8; i++) {
        int id = tid + i * 256;
        uint32_t row = (uint32_t)(id >> 5), cc = (uint32_t)(id & 31);
        cp16(smb + ASM_B0 + swzV(row, cc), g_Kh + (base + kt_lo + row) * HD + cc * 8);
    }
    CP_COMMIT();
    #pragma unroll
    for (int i = 0; i < 8; i++) {
        int id = tid + i * 256;
        uint32_t row = (uint32_t)(id >> 5), cc = (uint32_t)(id & 31);
        cp16(smb + ASM_B1 + swzV(row, cc), g_Vf + (base + kt_lo + row) * HD + cc * 8);
    }
    CP_COMMIT();

    int w = tid >> 5, l = tid & 31;
    int wm = w >> 2, wn = w & 3;
    uint32_t la = (uint32_t)(l & 15), hsel = (uint32_t)(l >> 4);

    float o[2][8][4];
    #pragma unroll
    for (int mt = 0; mt < 2; mt++)
        #pragma unroll
        for (int j = 0; j < 8; j++)
            #pragma unroll
            for (int r = 0; r < 4; r++) o[mt][j][r] = 0.0f;

    for (int it = 0; it < nt; it++) {
        int kt = kt_lo + it * 64;

        CP_WAIT(1);
        __syncthreads();

        // ---- phase 1: S = Q K^T, single fp16 mma ----
        float sacc[2][2][4];
        #pragma unroll
        for (int mt = 0; mt < 2; mt++)
            #pragma unroll
            for (int nti = 0; nti < 2; nti++)
                #pragma unroll
                for (int r = 0; r < 4; r++) sacc[mt][nti][r] = 0.0f;

        #pragma unroll 4
        for (int ks = 0; ks < 16; ks++) {
            uint32_t qf[2][4];
            #pragma unroll
            for (int mt = 0; mt < 2; mt++) {
                uint32_t row = (uint32_t)(wm * 32 + mt * 16) + la;
                ldsm4(qf[mt], smb + ASM_Q + swzV(row, (uint32_t)(ks * 2) + hsel));
            }
            uint32_t kf[4];
            {
                uint32_t row = (uint32_t)(wn * 16) + la;
                ldsm4(kf, smb + ASM_B0 + swzV(row, (uint32_t)(ks * 2) + hsel));
            }
            #pragma unroll
            for (int mt = 0; mt < 2; mt++)
                #pragma unroll
                for (int nti = 0; nti < 2; nti++)
                    mma16816h(sacc[mt][nti], qf[mt], kf[nti], kf[nti + 2]);
        }

        // ---- decay + fp16 split + stage S ----
        int dq = q0 - kt;
        #pragma unroll
        for (int mt = 0; mt < 2; mt++)
            #pragma unroll
            for (int nti = 0; nti < 2; nti++) {
                int qr0 = wm * 32 + mt * 16 + (l >> 2);
                int key = wn * 16 + nti * 8 + (l & 3) * 2;
                #pragma unroll
                for (int h = 0; h < 2; h++) {
                    int q = qr0 + 8 * h;
                    int e0 = dq + q - key;
                    float g0 = (e0 >= 0) ? g_gamma[e0] : 0.0f;
                    float g1 = (e0 >= 1) ? g_gamma[e0 - 1] : 0.0f;
                    float s0 = sacc[mt][nti][2 * h] * g0;
                    float s1 = sacc[mt][nti][2 * h + 1] * g1;
                    float h0f = __half2float(__float2half(s0));
                    float h1f = __half2float(__float2half(s1));
                    uint32_t hp = fp16pair(s0, s1);
                    uint32_t mp = fp16pair(s0 - h0f, s1 - h1f);
                    uint32_t cc = (uint32_t)(key >> 3);
                    uint32_t inb = (uint32_t)((key & 7) * 2);
                    *(uint32_t*)(sm + ASM_S + swzS((uint32_t)q, cc) + inb)      = hp;
                    *(uint32_t*)(sm + ASM_S + swzS((uint32_t)q, 8u + cc) + inb) = mp;
                }
            }
        __syncthreads();

        if (it + 1 < nt) {
            #pragma unroll
            for (int i = 0; i < 8; i++) {
                int id = tid + i * 256;
                uint32_t row = (uint32_t)(id >> 5), cc = (uint32_t)(id & 31);
                cp16(smb + ASM_B0 + swzV(row, cc),
                     g_Kh + (base + kt + 64 + row) * HD + cc * 8);
            }
            CP_COMMIT();
            CP_WAIT(1);
        } else {
            CP_WAIT(0);
        }
        __syncthreads();

        // ---- phase 2: O += S V, fp16 (split-2 x single) ----
        #pragma unroll
        for (int ks2 = 0; ks2 < 4; ks2++) {
            uint32_t sh[2][4], sd[2][4];
            #pragma unroll
            for (int mt = 0; mt < 2; mt++) {
                uint32_t row = (uint32_t)(wm * 32 + mt * 16) + la;
                ldsm4(sh[mt], smb + ASM_S + swzS(row, (uint32_t)(ks2 * 2) + hsel));
                ldsm4(sd[mt], smb + ASM_S + swzS(row, 8u + (uint32_t)(ks2 * 2) + hsel));
            }
            uint32_t vrow = (uint32_t)(ks2 * 16) + la;
            #pragma unroll
            for (int j = 0; j < 4; j++) {
                uint32_t vh[4];
                uint32_t cc = (uint32_t)(wn * 8 + j * 2) + hsel;
                ldsm4t(vh, smb + ASM_B1 + swzV(vrow, cc));
                #pragma unroll
                for (int nti = 0; nti < 2; nti++) {
                    uint32_t b0 = vh[nti * 2], b1 = vh[nti * 2 + 1];
                    #pragma unroll
                    for (int mt = 0; mt < 2; mt++) {
                        float* dd = o[mt][j * 2 + nti];
                        mma16816h(dd, sh[mt], b0, b1);   // Sh * V
                        mma16816h(dd, sd[mt], b0, b1);   // Sm * V
                    }
                }
            }
        }
        __syncthreads();

        if (it + 1 < nt) {
            #pragma unroll
            for (int i = 0; i < 8; i++) {
                int id = tid + i * 256;
                uint32_t row = (uint32_t)(id >> 5), cc = (uint32_t)(id & 31);
                cp16(smb + ASM_B1 + swzV(row, cc),
                     g_Vf + (base + kt + 64 + row) * HD + cc * 8);
            }
            CP_COMMIT();
        }
    }

    #pragma unroll
    for (int mt = 0; mt < 2; mt++)
        #pragma unroll
        for (int h = 0; h < 2; h++) {
            int q = q0 + wm * 32 + mt * 16 + (l >> 2) + 8 * h;
            size_t ro = (base + q) * (size_t)HD;
            #pragma unroll
            for (int j = 0; j < 8; j++) {
                int vd = wn * 64 + j * 8 + (l & 3) * 2;
                float2 v;
                v.x = o[mt][j][2 * h];
                v.y = o[mt][j][2 * h + 1];
                *(float2*)(out + ro + vd) = v;
            }
        }
}

// ---------------- launch ----------------
extern "C" void kernel_launch(void* const* d_in, const int* in_sizes, int n_in,
                              void* d_out, int out_size) {
    const float* X  = (const float*)d_in[0];
    const float* WQ = (const float*)d_in[1];
    const float* WK = (const float*)d_in[2];
    const float* WV = (const float*)d_in[3];
    float* out = (float*)d_out;

    const_kernel<<<16, 256>>>();
    tables_kernel<<<SEQ, 128>>>();

    splitx_kernel<<<(MTOT * HID / 8) / 256, 256>>>(X);
    splitw_kernel<<<(3 * HID * HD) / 256, 256>>>(WQ, WK, WV);

    cudaFuncSetAttribute(proj_mma_kernel, cudaFuncAttributeMaxDynamicSharedMemorySize,
                         PROJ_SMEM);
    dim3 pg(6, MTOT / 128);
    proj_mma_kernel<<<pg, 256, PROJ_SMEM>>>();

    cudaFuncSetAttribute(attn_mma_kernel, cudaFuncAttributeMaxDynamicSharedMemorySize,
                         ATTN_SMEM);
    dim3 ag(SEQ / 64, NB);
    attn_mma_kernel<<<ag, 256, ATTN_SMEM>>>(out);
}

// round 13
// speedup vs baseline: 5.7437x; 1.0591x over previous
#include <cuda_runtime.h>
#include <cuda_bf16.h>
#include <cuda_fp16.h>
#include <math.h>
#include <stdint.h>

#define SEQ 4096
#define NB 4
#define HID 1024
#define HD 256
#define MTOT (NB*SEQ)
#define DW 256            // gamma^256: measured truncation cost ~1e-4 in quadrature

typedef unsigned long long u64;

// ---------------- static device scratch (no cudaMalloc allowed) ----------------
__device__ __half g_Qh[(size_t)MTOT*HD];    // recentered xpos scale, fp16
__device__ __half g_Kh[(size_t)MTOT*HD];
__device__ __half g_Vf[(size_t)MTOT*HD];
__device__ __half g_Xh[(size_t)MTOT*HID];
__device__ __half g_Wh[3*HID*HD];           // [z][k][n], W*1024 fp16
__device__ float g_cosQ[SEQ*128];
__device__ float g_sinQ[SEQ*128];
__device__ float g_cosK[SEQ*128];
__device__ float g_sinK[SEQ*128];
__device__ float g_gamma[SEQ];
__device__ double g_invf[128];
__device__ double g_l2sb[128];

// ---------------- mma / async helpers (baseline PTX, sm_80+ ISA only) ----------------
__device__ __forceinline__ uint32_t smem_u32(const void* p) {
    uint32_t a;
    asm("{ .reg .u64 t; cvta.to.shared.u64 t, %1; cvt.u32.u64 %0, t; }" : "=r"(a) : "l"(p));
    return a;
}
__device__ __forceinline__ void cp16(uint32_t dst, const void* src) {
    asm volatile("cp.async.cg.shared.global [%0], [%1], 16;" :: "r"(dst), "l"(src));
}
#define CP_COMMIT()  asm volatile("cp.async.commit_group;" ::: "memory")
#define CP_WAIT(n)   asm volatile("cp.async.wait_group %0;" :: "n"(n) : "memory")

__device__ __forceinline__ void ldsm4(uint32_t (&r)[4], uint32_t a) {
    asm volatile("ldmatrix.sync.aligned.m8n8.x4.shared.b16 {%0,%1,%2,%3}, [%4];"
                 : "=r"(r[0]), "=r"(r[1]), "=r"(r[2]), "=r"(r[3]) : "r"(a));
}
__device__ __forceinline__ void ldsm4t(uint32_t (&r)[4], uint32_t a) {
    asm volatile("ldmatrix.sync.aligned.m8n8.x4.trans.shared.b16 {%0,%1,%2,%3}, [%4];"
                 : "=r"(r[0]), "=r"(r[1]), "=r"(r[2]), "=r"(r[3]) : "r"(a));
}
__device__ __forceinline__ void mma16816h(float* d, const uint32_t* a, uint32_t b0, uint32_t b1) {
    asm volatile(
        "mma.sync.aligned.m16n8k16.row.col.f32.f16.f16.f32 "
        "{%0,%1,%2,%3}, {%4,%5,%6,%7}, {%8,%9}, {%0,%1,%2,%3};"
        : "+f"(d[0]), "+f"(d[1]), "+f"(d[2]), "+f"(d[3])
        : "r"(a[0]), "r"(a[1]), "r"(a[2]), "r"(a[3]), "r"(b0), "r"(b1));
}
__device__ __forceinline__ uint32_t fp16pair(float a, float b) {
    __half2 t; t.x = __float2half(a); t.y = __float2half(b);
    uint32_t r; asm("mov.b32 %0, %1;" : "=r"(r) : "r"(*(uint32_t*)&t)); return r;
}

// ---------------- xpos sin/cos tables, RECENTERED scale ----------------
__global__ void tables_kernel() {
    int pos = blockIdx.x, j = threadIdx.x;
    float invf = (float)g_invf[j];
    float arg = (float)pos * invf;
    double ad = (double)arg;
    double qd = rint(ad * 0.63661977236758134308);
    double rd = fma(qd, -1.5707963267948966, ad);
    rd = fma(qd, -6.123233995736766e-17, rd);
    int qi = ((long long)qd) & 3;
    float rf = (float)rd;
    float sr = sinf(rf), cr = cosf(rf);
    float s, c;
    if      (qi == 0) { s =  sr; c =  cr; }
    else if (qi == 1) { s =  cr; c = -sr; }
    else if (qi == 2) { s = -sr; c = -cr; }
    else              { s = -cr; c =  sr; }
    float p  = ((float)pos - 2048.0f) * (1.0f / 512.0f);   // recentered
    float l2 = (float)g_l2sb[j];
    float sc  = exp2f(p * l2);
    float isc = exp2f(-p * l2);
    int idx = pos * 128 + j;
    g_cosQ[idx] = c * sc;   g_sinQ[idx] = s * sc;
    g_cosK[idx] = c * isc;  g_sinK[idx] = s * isc;
}

// ---------------- prep ----------------
__global__ void splitx_kernel(const float* __restrict__ X) {
    size_t i = (size_t)blockIdx.x * blockDim.x + threadIdx.x;   // 8 floats each
    float4 a = ((const float4*)X)[2 * i];
    float4 b = ((const float4*)X)[2 * i + 1];
    uint4 o;
    o.x = fp16pair(a.x, a.y); o.y = fp16pair(a.z, a.w);
    o.z = fp16pair(b.x, b.y); o.w = fp16pair(b.z, b.w);
    ((uint4*)g_Xh)[i] = o;
}

// also produces the constant tables (invf/l2sb/gamma) — runs before tables_kernel
__global__ void splitw_kernel(const float* __restrict__ WQ,
                              const float* __restrict__ WK,
                              const float* __restrict__ WV) {
    int idx = blockIdx.x * blockDim.x + threadIdx.x;   // [z][k][n], 3*1024*256
    if (idx < 128) {
        g_invf[idx] = pow(10000.0, -(double)idx / 128.0);
        double sb = ((double)(2 * idx) + 0.4 * 256.0) / (1.4 * 256.0);
        g_l2sb[idx] = log2(sb);
    }
    if (idx < SEQ) g_gamma[idx] = (float)pow(0.96875, (double)idx);
    int z = idx >> 18;
    int kn = idx & 0x3FFFF;
    const float* W = (z == 0) ? WQ : (z == 1 ? WK : WV);
    g_Wh[idx] = __float2half(W[kn] * 1024.0f);
}

// ---------------- projection GEMM, fp16 single term, 2 CTAs/SM ----------------
// CTA = 128M x 128N, warp tile 32x64, K=1024 in 32 stages of KC=32, 4-stage ring.
#define PKC 32
#define PSTG_A 10240
#define PSTG_B 8192
#define PSTG_BYTES (PSTG_A + PSTG_B)
#define PROJ_SMEM (4 * PSTG_BYTES)

__global__ void __launch_bounds__(256, 2) proj_mma_kernel()
{
    extern __shared__ __align__(1024) char sm[];
    uint32_t smb = smem_u32(sm);
    int tid = threadIdx.x;
    int z  = blockIdx.x >> 1;
    int n0 = (blockIdx.x & 1) * 128;
    int m0 = blockIdx.y * 128;

    const __half* Wh = g_Wh + (size_t)z * HID * HD + n0;

    const __half* srcA[2]; uint32_t dstA[2];
    #pragma unroll
    for (int i = 0; i < 2; i++) {
        int id = tid + i * 256;
        int m = id >> 2, c = id & 3;
        srcA[i] = g_Xh + (size_t)(m0 + m) * HID + c * 8;
        dstA[i] = (uint32_t)(m * 80 + c * 16);
    }
    const __half* srcB[2]; uint32_t dstB[2];
    #pragma unroll
    for (int i = 0; i < 2; i++) {
        int id = tid + i * 256;
        int k = id >> 4, cc = id & 15;
        srcB[i] = Wh + (size_t)k * HD + cc * 8;
        dstB[i] = (uint32_t)(PSTG_A + k * 256 +
                             ((uint32_t)((cc & 8) | ((cc ^ (k & 7)) & 7)) << 4));
    }

    int w = tid >> 5, l = tid & 31;
    int wm = w >> 1, wn = w & 1;
    int la = l & 15, hsel = l >> 4;
    uint32_t lam = (uint32_t)(la & 7);
    uint32_t brow = (uint32_t)(la * 256);
    uint32_t bnc0 = (uint32_t)(wn * 8);

    float d[2][8][4];
    #pragma unroll
    for (int mt = 0; mt < 2; mt++)
        #pragma unroll
        for (int nt = 0; nt < 8; nt++)
            #pragma unroll
            for (int r = 0; r < 4; r++) d[mt][nt][r] = 0.0f;

    #pragma unroll
    for (int p = 0; p < 3; p++) {
        uint32_t bb = smb + (uint32_t)p * PSTG_BYTES;
        int kt = p * PKC;
        #pragma unroll
        for (int i = 0; i < 2; i++) cp16(bb + dstA[i], srcA[i] + kt);
        #pragma unroll
        for (int i = 0; i < 2; i++) cp16(bb + dstB[i], srcB[i] + (size_t)kt * HD);
        CP_COMMIT();
    }

    for (int s = 0; s < 32; s++) {
        if (s + 3 < 32) {
            uint32_t bb = smb + (uint32_t)((s + 3) & 3) * PSTG_BYTES;
            int kt = (s + 3) * PKC;
            #pragma unroll
            for (int i = 0; i < 2; i++) cp16(bb + dstA[i], srcA[i] + kt);
            #pragma unroll
            for (int i = 0; i < 2; i++) cp16(bb + dstB[i], srcB[i] + (size_t)kt * HD);
            CP_COMMIT();
            CP_WAIT(3);
        } else if (s + 2 < 32) {
            CP_WAIT(2);
        } else if (s + 1 < 32) {
            CP_WAIT(1);
        } else {
            CP_WAIT(0);
        }
        __syncthreads();

        uint32_t AS = smb + (uint32_t)(s & 3) * PSTG_BYTES;
        uint32_t BS = AS + PSTG_A;

        #pragma unroll
        for (int slab = 0; slab < 2; slab++) {
            uint32_t ah[2][4];
            #pragma unroll
            for (int mt = 0; mt < 2; mt++) {
                uint32_t row = (uint32_t)(wm * 32 + mt * 16 + la);
                ldsm4(ah[mt], AS + row * 80 + (uint32_t)((slab * 2 + hsel) * 16));
            }
            uint32_t krow = BS + (uint32_t)(slab * 16 * 256) + brow;
            #pragma unroll
            for (int half = 0; half < 2; half++) {
                uint32_t bh[2][4];
                #pragma unroll
                for (int j2 = 0; j2 < 2; j2++) {
                    uint32_t nc = bnc0 + (uint32_t)(half * 4 + j2 * 2 + hsel);
                    ldsm4t(bh[j2], krow + (((nc & 8u) | ((nc ^ lam) & 7u)) << 4));
                }
                #pragma unroll
                for (int nt = 0; nt < 4; nt++) {
                    uint32_t h0 = bh[nt >> 1][(nt & 1) * 2], h1 = bh[nt >> 1][(nt & 1) * 2 + 1];
                    #pragma unroll
                    for (int mt = 0; mt < 2; mt++)
                        mma16816h(d[mt][half * 4 + nt], ah[mt], h0, h1);
                }
            }
        }
        __syncthreads();
    }

    // ---- epilogue: unscale + recentered rotary (Q,K) + store fp16 ----
    const float* ct = (z == 0) ? g_cosQ : g_cosK;
    const float* st = (z == 0) ? g_sinQ : g_sinK;
    __half* Oqk = (z == 0) ? g_Qh : g_Kh;
    const float DS = 0.0009765625f;     // 2^-10
    int mrb = m0 + wm * 32 + (l >> 2);
    int ncb = n0 + wn * 64 + (l & 3) * 2;
    #pragma unroll
    for (int mt = 0; mt < 2; mt++)
        #pragma unroll
        for (int r2 = 0; r2 < 2; r2++) {
            int m = mrb + mt * 16 + r2 * 8;
            int pos = m & (SEQ - 1);
            #pragma unroll
            for (int nt = 0; nt < 8; nt++) {
                int n = ncb + nt * 8;
                float v0 = d[mt][nt][r2 * 2] * DS, v1 = d[mt][nt][r2 * 2 + 1] * DS;
                if (z < 2) {
                    int j = n >> 1;
                    float C = ct[pos * 128 + j], S = st[pos * 128 + j];
                    float o0 = v0 * C - v1 * S;
                    float o1 = v1 * C + v0 * S;
                    *(uint32_t*)(Oqk + (size_t)m * HD + n) = fp16pair(o0, o1);
                } else {
                    *(uint32_t*)(g_Vf + (size_t)m * HD + n) = fp16pair(v0, v1);
                }
            }
        }
}

// ---------------- banded retention attention (all fp16 mma, single-S) ----------------
#define ASM_Q  0
#define ASM_B0 32768
#define ASM_B1 65536
#define ASM_S  98304
#define ATTN_SMEM 106496

__device__ __forceinline__ uint32_t swzV(uint32_t row, uint32_t cc) {    // 512B rows
    return row * 512u + (((cc & 24u) | ((cc ^ row) & 7u)) << 4);
}
__device__ __forceinline__ uint32_t swzS(uint32_t row, uint32_t cc) {    // 128B rows
    return row * 128u + (((cc ^ row) & 7u) << 4);
}

__global__ void __launch_bounds__(256, 2) attn_mma_kernel(float* __restrict__ out)
{
    extern __shared__ __align__(1024) char sm[];
    uint32_t smb = smem_u32(sm);
    int tid = threadIdx.x;
    int b = blockIdx.y;
    int q0 = blockIdx.x * 64;
    size_t base = (size_t)b * SEQ;

    #pragma unroll
    for (int i = 0; i < 8; i++) {
        int id = tid + i * 256;
        uint32_t row = (uint32_t)(id >> 5), cc = (uint32_t)(id & 31);
        cp16(smb + ASM_Q + swzV(row, cc), g_Qh + (base + q0 + row) * HD + cc * 8);
    }
    int kt_lo = q0 - DW; if (kt_lo < 0) kt_lo = 0;
    int nt = ((q0 - kt_lo) >> 6) + 1;
    #pragma unroll
    for (int i = 0; i < 8; i++) {
        int id = tid + i * 256;
        uint32_t row = (uint32_t)(id >> 5), cc = (uint32_t)(id & 31);
        cp16(smb + ASM_B0 + swzV(row, cc), g_Kh + (base + kt_lo + row) * HD + cc * 8);
    }
    CP_COMMIT();
    #pragma unroll
    for (int i = 0; i < 8; i++) {
        int id = tid + i * 256;
        uint32_t row = (uint32_t)(id >> 5), cc = (uint32_t)(id & 31);
        cp16(smb + ASM_B1 + swzV(row, cc), g_Vf + (base + kt_lo + row) * HD + cc * 8);
    }
    CP_COMMIT();

    int w = tid >> 5, l = tid & 31;
    int wm = w >> 2, wn = w & 3;
    uint32_t la = (uint32_t)(l & 15), hsel = (uint32_t)(l >> 4);

    float o[2][8][4];
    #pragma unroll
    for (int mt = 0; mt < 2; mt++)
        #pragma unroll
        for (int j = 0; j < 8; j++)
            #pragma unroll
            for (int r = 0; r < 4; r++) o[mt][j][r] = 0.0f;

    for (int it = 0; it < nt; it++) {
        int kt = kt_lo + it * 64;

        CP_WAIT(1);
        __syncthreads();

        // ---- phase 1: S = Q K^T, single fp16 mma ----
        float sacc[2][2][4];
        #pragma unroll
        for (int mt = 0; mt < 2; mt++)
            #pragma unroll
            for (int nti = 0; nti < 2; nti++)
                #pragma unroll
                for (int r = 0; r < 4; r++) sacc[mt][nti][r] = 0.0f;

        #pragma unroll 4
        for (int ks = 0; ks < 16; ks++) {
            uint32_t qf[2][4];
            #pragma unroll
            for (int mt = 0; mt < 2; mt++) {
                uint32_t row = (uint32_t)(wm * 32 + mt * 16) + la;
                ldsm4(qf[mt], smb + ASM_Q + swzV(row, (uint32_t)(ks * 2) + hsel));
            }
            uint32_t kf[4];
            {
                uint32_t row = (uint32_t)(wn * 16) + la;
                ldsm4(kf, smb + ASM_B0 + swzV(row, (uint32_t)(ks * 2) + hsel));
            }
            #pragma unroll
            for (int mt = 0; mt < 2; mt++)
                #pragma unroll
                for (int nti = 0; nti < 2; nti++)
                    mma16816h(sacc[mt][nti], qf[mt], kf[nti], kf[nti + 2]);
        }

        // ---- decay + single fp16 S staging ----
        int dq = q0 - kt;
        #pragma unroll
        for (int mt = 0; mt < 2; mt++)
            #pragma unroll
            for (int nti = 0; nti < 2; nti++) {
                int qr0 = wm * 32 + mt * 16 + (l >> 2);
                int key = wn * 16 + nti * 8 + (l & 3) * 2;
                #pragma unroll
                for (int h = 0; h < 2; h++) {
                    int q = qr0 + 8 * h;
                    int e0 = dq + q - key;
                    float g0 = (e0 >= 0) ? g_gamma[e0] : 0.0f;
                    float g1 = (e0 >= 1) ? g_gamma[e0 - 1] : 0.0f;
                    float s0 = sacc[mt][nti][2 * h] * g0;
                    float s1 = sacc[mt][nti][2 * h + 1] * g1;
                    uint32_t cc = (uint32_t)(key >> 3);
                    uint32_t inb = (uint32_t)((key & 7) * 2);
                    *(uint32_t*)(sm + ASM_S + swzS((uint32_t)q, cc) + inb) = fp16pair(s0, s1);
                }
            }
        __syncthreads();

        if (it + 1 < nt) {
            #pragma unroll
            for (int i = 0; i < 8; i++) {
                int id = tid + i * 256;
                uint32_t row = (uint32_t)(id >> 5), cc = (uint32_t)(id & 31);
                cp16(smb + ASM_B0 + swzV(row, cc),
                     g_Kh + (base + kt + 64 + row) * HD + cc * 8);
            }
            CP_COMMIT();
            CP_WAIT(1);
        } else {
            CP_WAIT(0);
        }
        __syncthreads();

        // ---- phase 2: O += S V, single fp16 ----
        #pragma unroll
        for (int ks2 = 0; ks2 < 4; ks2++) {
            uint32_t sh[2][4];
            #pragma unroll
            for (int mt = 0; mt < 2; mt++) {
                uint32_t row = (uint32_t)(wm * 32 + mt * 16) + la;
                ldsm4(sh[mt], smb + ASM_S + swzS(row, (uint32_t)(ks2 * 2) + hsel));
            }
            uint32_t vrow = (uint32_t)(ks2 * 16) + la;
            #pragma unroll
            for (int j = 0; j < 4; j++) {
                uint32_t vh[4];
                uint32_t cc = (uint32_t)(wn * 8 + j * 2) + hsel;
                ldsm4t(vh, smb + ASM_B1 + swzV(vrow, cc));
                #pragma unroll
                for (int nti = 0; nti < 2; nti++) {
                    uint32_t b0 = vh[nti * 2], b1 = vh[nti * 2 + 1];
                    #pragma unroll
                    for (int mt = 0; mt < 2; mt++)
                        mma16816h(o[mt][j * 2 + nti], sh[mt], b0, b1);
                }
            }
        }
        __syncthreads();

        if (it + 1 < nt) {
            #pragma unroll
            for (int i = 0; i < 8; i++) {
                int id = tid + i * 256;
                uint32_t row = (uint32_t)(id >> 5), cc = (uint32_t)(id & 31);
                cp16(smb + ASM_B1 + swzV(row, cc),
                     g_Vf + (base + kt + 64 + row) * HD + cc * 8);
            }
            CP_COMMIT();
        }
    }

    #pragma unroll
    for (int mt = 0; mt < 2; mt++)
        #pragma unroll
        for (int h = 0; h < 2; h++) {
            int q = q0 + wm * 32 + mt * 16 + (l >> 2) + 8 * h;
            size_t ro = (base + q) * (size_t)HD;
            #pragma unroll
            for (int j = 0; j < 8; j++) {
                int vd = wn * 64 + j * 8 + (l & 3) * 2;
                float2 v;
                v.x = o[mt][j][2 * h];
                v.y = o[mt][j][2 * h + 1];
                *(float2*)(out + ro + vd) = v;
            }
        }
}

// ---------------- launch ----------------
extern "C" void kernel_launch(void* const* d_in, const int* in_sizes, int n_in,
                              void* d_out, int out_size) {
    const float* X  = (const float*)d_in[0];
    const float* WQ = (const float*)d_in[1];
    const float* WK = (const float*)d_in[2];
    const float* WV = (const float*)d_in[3];
    float* out = (float*)d_out;

    splitw_kernel<<<(3 * HID * HD) / 256, 256>>>(WQ, WK, WV);   // also builds const tables
    tables_kernel<<<SEQ, 128>>>();
    splitx_kernel<<<(MTOT * HID / 8) / 256, 256>>>(X);

    cudaFuncSetAttribute(proj_mma_kernel, cudaFuncAttributeMaxDynamicSharedMemorySize,
                         PROJ_SMEM);
    dim3 pg(6, MTOT / 128);
    proj_mma_kernel<<<pg, 256, PROJ_SMEM>>>();

    cudaFuncSetAttribute(attn_mma_kernel, cudaFuncAttributeMaxDynamicSharedMemorySize,
                         ATTN_SMEM);
    dim3 ag(SEQ / 64, NB);
    attn_mma_kernel<<<ag, 256, ATTN_SMEM>>>(out);
}

// round 14
// speedup vs baseline: 5.8183x; 1.0130x over previous
#include <cuda_runtime.h>
#include <cuda_bf16.h>
#include <cuda_fp16.h>
#include <math.h>
#include <stdint.h>

#define SEQ 4096
#define NB 4
#define HID 1024
#define HD 256
#define MTOT (NB*SEQ)
#define DW 256            // gamma^256: measured truncation cost ~1e-4 in quadrature

typedef unsigned long long u64;

// ---------------- static device scratch (no cudaMalloc allowed) ----------------
__device__ __half g_Qh[(size_t)MTOT*HD];    // recentered xpos scale, fp16
__device__ __half g_Kh[(size_t)MTOT*HD];
__device__ __half g_Vf[(size_t)MTOT*HD];
__device__ __half g_Xh[(size_t)MTOT*HID];
__device__ __half g_Wh[3*HID*HD];           // [z][k][n], W*1024 fp16
__device__ float g_cosQ[SEQ*128];
__device__ float g_sinQ[SEQ*128];
__device__ float g_cosK[SEQ*128];
__device__ float g_sinK[SEQ*128];
__device__ float g_gamma[SEQ];
__device__ double g_invf[128];
__device__ double g_l2sb[128];

// ---------------- mma / async helpers (baseline PTX, sm_80+ ISA only) ----------------
__device__ __forceinline__ uint32_t smem_u32(const void* p) {
    uint32_t a;
    asm("{ .reg .u64 t; cvta.to.shared.u64 t, %1; cvt.u32.u64 %0, t; }" : "=r"(a) : "l"(p));
    return a;
}
__device__ __forceinline__ void cp16(uint32_t dst, const void* src) {
    asm volatile("cp.async.cg.shared.global [%0], [%1], 16;" :: "r"(dst), "l"(src));
}
#define CP_COMMIT()  asm volatile("cp.async.commit_group;" ::: "memory")
#define CP_WAIT(n)   asm volatile("cp.async.wait_group %0;" :: "n"(n) : "memory")

__device__ __forceinline__ void ldsm4(uint32_t (&r)[4], uint32_t a) {
    asm volatile("ldmatrix.sync.aligned.m8n8.x4.shared.b16 {%0,%1,%2,%3}, [%4];"
                 : "=r"(r[0]), "=r"(r[1]), "=r"(r[2]), "=r"(r[3]) : "r"(a));
}
__device__ __forceinline__ void ldsm4t(uint32_t (&r)[4], uint32_t a) {
    asm volatile("ldmatrix.sync.aligned.m8n8.x4.trans.shared.b16 {%0,%1,%2,%3}, [%4];"
                 : "=r"(r[0]), "=r"(r[1]), "=r"(r[2]), "=r"(r[3]) : "r"(a));
}
__device__ __forceinline__ void mma16816h(float* d, const uint32_t* a, uint32_t b0, uint32_t b1) {
    asm volatile(
        "mma.sync.aligned.m16n8k16.row.col.f32.f16.f16.f32 "
        "{%0,%1,%2,%3}, {%4,%5,%6,%7}, {%8,%9}, {%0,%1,%2,%3};"
        : "+f"(d[0]), "+f"(d[1]), "+f"(d[2]), "+f"(d[3])
        : "r"(a[0]), "r"(a[1]), "r"(a[2]), "r"(a[3]), "r"(b0), "r"(b1));
}
__device__ __forceinline__ uint32_t fp16pair(float a, float b) {
    __half2 t; t.x = __float2half(a); t.y = __float2half(b);
    uint32_t r; asm("mov.b32 %0, %1;" : "=r"(r) : "r"(*(uint32_t*)&t)); return r;
}

// ---------------- xpos sin/cos tables, RECENTERED scale ----------------
__global__ void tables_kernel() {
    int pos = blockIdx.x, j = threadIdx.x;
    float invf = (float)g_invf[j];
    float arg = (float)pos * invf;
    double ad = (double)arg;
    double qd = rint(ad * 0.63661977236758134308);
    double rd = fma(qd, -1.5707963267948966, ad);
    rd = fma(qd, -6.123233995736766e-17, rd);
    int qi = ((long long)qd) & 3;
    float rf = (float)rd;
    float sr = sinf(rf), cr = cosf(rf);
    float s, c;
    if      (qi == 0) { s =  sr; c =  cr; }
    else if (qi == 1) { s =  cr; c = -sr; }
    else if (qi == 2) { s = -sr; c = -cr; }
    else              { s = -cr; c =  sr; }
    float p  = ((float)pos - 2048.0f) * (1.0f / 512.0f);   // recentered
    float l2 = (float)g_l2sb[j];
    float sc  = exp2f(p * l2);
    float isc = exp2f(-p * l2);
    int idx = pos * 128 + j;
    g_cosQ[idx] = c * sc;   g_sinQ[idx] = s * sc;
    g_cosK[idx] = c * isc;  g_sinK[idx] = s * isc;
}

// ---------------- prep ----------------
__global__ void splitx_kernel(const float* __restrict__ X) {
    size_t i = (size_t)blockIdx.x * blockDim.x + threadIdx.x;   // 8 floats each
    float4 a = ((const float4*)X)[2 * i];
    float4 b = ((const float4*)X)[2 * i + 1];
    uint4 o;
    o.x = fp16pair(a.x, a.y); o.y = fp16pair(a.z, a.w);
    o.z = fp16pair(b.x, b.y); o.w = fp16pair(b.z, b.w);
    ((uint4*)g_Xh)[i] = o;
}

// also produces the constant tables (invf/l2sb/gamma) — runs before tables_kernel
__global__ void splitw_kernel(const float* __restrict__ WQ,
                              const float* __restrict__ WK,
                              const float* __restrict__ WV) {
    int idx = blockIdx.x * blockDim.x + threadIdx.x;   // [z][k][n], 3*1024*256
    if (idx < 128) {
        g_invf[idx] = pow(10000.0, -(double)idx / 128.0);
        double sb = ((double)(2 * idx) + 0.4 * 256.0) / (1.4 * 256.0);
        g_l2sb[idx] = log2(sb);
    }
    if (idx < SEQ) g_gamma[idx] = (float)pow(0.96875, (double)idx);
    int z = idx >> 18;
    int kn = idx & 0x3FFFF;
    const float* W = (z == 0) ? WQ : (z == 1 ? WK : WV);
    g_Wh[idx] = __float2half(W[kn] * 1024.0f);
}

// ---------------- projection GEMM, fp16 single term, 2 CTAs/SM ----------------
// CTA = 128M x 128N, warp tile 32x64, K=1024 in 16 stages of KC=64, 3-stage ring.
#define PKC 64
#define PNSTG 16
#define PSTG_A 18432          // 128 rows x 144B (128B payload + 16B pad)
#define PSTG_B 16384          // 64 k-rows x 256B, swizzled
#define PSTG_BYTES (PSTG_A + PSTG_B)
#define PROJ_SMEM (3 * PSTG_BYTES)

__global__ void __launch_bounds__(256, 2) proj_mma_kernel()
{
    extern __shared__ __align__(1024) char sm[];
    uint32_t smb = smem_u32(sm);
    int tid = threadIdx.x;
    int z  = blockIdx.x >> 1;
    int n0 = (blockIdx.x & 1) * 128;
    int m0 = blockIdx.y * 128;

    const __half* Wh = g_Wh + (size_t)z * HID * HD + n0;

    // A copy: 4 chunks/thread (128 rows x 128B payload, 144B stride)
    const __half* srcA[4]; uint32_t dstA[4];
    #pragma unroll
    for (int i = 0; i < 4; i++) {
        int id = tid + i * 256;
        int m = id >> 3, c = id & 7;
        srcA[i] = g_Xh + (size_t)(m0 + m) * HID + c * 8;
        dstA[i] = (uint32_t)(m * 144 + c * 16);
    }
    // B copy: 4 chunks/thread (64 k-rows x 256B, XOR swizzle)
    const __half* srcB[4]; uint32_t dstB[4];
    #pragma unroll
    for (int i = 0; i < 4; i++) {
        int id = tid + i * 256;
        int k = id >> 4, cc = id & 15;
        srcB[i] = Wh + (size_t)k * HD + cc * 8;
        dstB[i] = (uint32_t)(PSTG_A + k * 256 +
                             ((uint32_t)((cc & 8) | ((cc ^ (k & 7)) & 7)) << 4));
    }

    int w = tid >> 5, l = tid & 31;
    int wm = w >> 1, wn = w & 1;
    int la = l & 15, hsel = l >> 4;
    uint32_t lam = (uint32_t)(la & 7);
    uint32_t brow = (uint32_t)(la * 256);
    uint32_t bnc0 = (uint32_t)(wn * 8);

    float d[2][8][4];
    #pragma unroll
    for (int mt = 0; mt < 2; mt++)
        #pragma unroll
        for (int nt = 0; nt < 8; nt++)
            #pragma unroll
            for (int r = 0; r < 4; r++) d[mt][nt][r] = 0.0f;

    // prologue: stages 0, 1
    #pragma unroll
    for (int p = 0; p < 2; p++) {
        uint32_t bb = smb + (uint32_t)p * PSTG_BYTES;
        int kt = p * PKC;
        #pragma unroll
        for (int i = 0; i < 4; i++) cp16(bb + dstA[i], srcA[i] + kt);
        #pragma unroll
        for (int i = 0; i < 4; i++) cp16(bb + dstB[i], srcB[i] + (size_t)kt * HD);
        CP_COMMIT();
    }

    int buf = 0, nbuf = 2;    // compute buffer; copy-target buffer
    for (int s = 0; s < PNSTG; s++) {
        if (s + 2 < PNSTG) {
            uint32_t bb = smb + (uint32_t)nbuf * PSTG_BYTES;
            int kt = (s + 2) * PKC;
            #pragma unroll
            for (int i = 0; i < 4; i++) cp16(bb + dstA[i], srcA[i] + kt);
            #pragma unroll
            for (int i = 0; i < 4; i++) cp16(bb + dstB[i], srcB[i] + (size_t)kt * HD);
            CP_COMMIT();
            CP_WAIT(2);
        } else if (s + 1 < PNSTG) {
            CP_WAIT(1);
        } else {
            CP_WAIT(0);
        }
        __syncthreads();

        uint32_t AS = smb + (uint32_t)buf * PSTG_BYTES;
        uint32_t BS = AS + PSTG_A;
        buf = (buf + 1 == 3) ? 0 : buf + 1;
        nbuf = (nbuf + 1 == 3) ? 0 : nbuf + 1;

        #pragma unroll
        for (int slab = 0; slab < 4; slab++) {          // four k16 slabs
            uint32_t ah[2][4];
            #pragma unroll
            for (int mt = 0; mt < 2; mt++) {
                uint32_t row = (uint32_t)(wm * 32 + mt * 16 + la);
                ldsm4(ah[mt], AS + row * 144 + (uint32_t)((slab * 2 + hsel) * 16));
            }
            uint32_t krow = BS + (uint32_t)(slab * 16 * 256) + brow;
            #pragma unroll
            for (int half = 0; half < 2; half++) {
                uint32_t bh[2][4];
                #pragma unroll
                for (int j2 = 0; j2 < 2; j2++) {
                    uint32_t nc = bnc0 + (uint32_t)(half * 4 + j2 * 2 + hsel);
                    ldsm4t(bh[j2], krow + (((nc & 8u) | ((nc ^ lam) & 7u)) << 4));
                }
                #pragma unroll
                for (int nt = 0; nt < 4; nt++) {
                    uint32_t h0 = bh[nt >> 1][(nt & 1) * 2], h1 = bh[nt >> 1][(nt & 1) * 2 + 1];
                    #pragma unroll
                    for (int mt = 0; mt < 2; mt++)
                        mma16816h(d[mt][half * 4 + nt], ah[mt], h0, h1);
                }
            }
        }
        __syncthreads();
    }

    // ---- epilogue: unscale + recentered rotary (Q,K) + store fp16 ----
    const float* ct = (z == 0) ? g_cosQ : g_cosK;
    const float* st = (z == 0) ? g_sinQ : g_sinK;
    __half* Oqk = (z == 0) ? g_Qh : g_Kh;
    const float DS = 0.0009765625f;     // 2^-10
    int mrb = m0 + wm * 32 + (l >> 2);
    int ncb = n0 + wn * 64 + (l & 3) * 2;
    #pragma unroll
    for (int mt = 0; mt < 2; mt++)
        #pragma unroll
        for (int r2 = 0; r2 < 2; r2++) {
            int m = mrb + mt * 16 + r2 * 8;
            int pos = m & (SEQ - 1);
            #pragma unroll
            for (int nt = 0; nt < 8; nt++) {
                int n = ncb + nt * 8;
                float v0 = d[mt][nt][r2 * 2] * DS, v1 = d[mt][nt][r2 * 2 + 1] * DS;
                if (z < 2) {
                    int j = n >> 1;
                    float C = ct[pos * 128 + j], S = st[pos * 128 + j];
                    float o0 = v0 * C - v1 * S;
                    float o1 = v1 * C + v0 * S;
                    *(uint32_t*)(Oqk + (size_t)m * HD + n) = fp16pair(o0, o1);
                } else {
                    *(uint32_t*)(g_Vf + (size_t)m * HD + n) = fp16pair(v0, v1);
                }
            }
        }
}

// ---------------- banded retention attention (all fp16 mma, single-S) ----------------
#define ASM_Q  0
#define ASM_B0 32768
#define ASM_B1 65536
#define ASM_S  98304
#define ATTN_SMEM 106496

__device__ __forceinline__ uint32_t swzV(uint32_t row, uint32_t cc) {    // 512B rows
    return row * 512u + (((cc & 24u) | ((cc ^ row) & 7u)) << 4);
}
__device__ __forceinline__ uint32_t swzS(uint32_t row, uint32_t cc) {    // 128B rows
    return row * 128u + (((cc ^ row) & 7u) << 4);
}

__global__ void __launch_bounds__(256, 2) attn_mma_kernel(float* __restrict__ out)
{
    extern __shared__ __align__(1024) char sm[];
    uint32_t smb = smem_u32(sm);
    int tid = threadIdx.x;
    int b = blockIdx.y;
    int q0 = blockIdx.x * 64;
    size_t base = (size_t)b * SEQ;

    #pragma unroll
    for (int i = 0; i < 8; i++) {
        int id = tid + i * 256;
        uint32_t row = (uint32_t)(id >> 5), cc = (uint32_t)(id & 31);
        cp16(smb + ASM_Q + swzV(row, cc), g_Qh + (base + q0 + row) * HD + cc * 8);
    }
    int kt_lo = q0 - DW; if (kt_lo < 0) kt_lo = 0;
    int nt = ((q0 - kt_lo) >> 6) + 1;
    #pragma unroll
    for (int i = 0; i < 8; i++) {
        int id = tid + i * 256;
        uint32_t row = (uint32_t)(id >> 5), cc = (uint32_t)(id & 31);
        cp16(smb + ASM_B0 + swzV(row, cc), g_Kh + (base + kt_lo + row) * HD + cc * 8);
    }
    CP_COMMIT();
    #pragma unroll
    for (int i = 0; i < 8; i++) {
        int id = tid + i * 256;
        uint32_t row = (uint32_t)(id >> 5), cc = (uint32_t)(id & 31);
        cp16(smb + ASM_B1 + swzV(row, cc), g_Vf + (base + kt_lo + row) * HD + cc * 8);
    }
    CP_COMMIT();

    int w = tid >> 5, l = tid & 31;
    int wm = w >> 2, wn = w & 3;
    uint32_t la = (uint32_t)(l & 15), hsel = (uint32_t)(l >> 4);

    float o[2][8][4];
    #pragma unroll
    for (int mt = 0; mt < 2; mt++)
        #pragma unroll
        for (int j = 0; j < 8; j++)
            #pragma unroll
            for (int r = 0; r < 4; r++) o[mt][j][r] = 0.0f;

    for (int it = 0; it < nt; it++) {
        int kt = kt_lo + it * 64;

        CP_WAIT(1);
        __syncthreads();

        // ---- phase 1: S = Q K^T, single fp16 mma ----
        float sacc[2][2][4];
        #pragma unroll
        for (int mt = 0; mt < 2; mt++)
            #pragma unroll
            for (int nti = 0; nti < 2; nti++)
                #pragma unroll
                for (int r = 0; r < 4; r++) sacc[mt][nti][r] = 0.0f;

        #pragma unroll 4
        for (int ks = 0; ks < 16; ks++) {
            uint32_t qf[2][4];
            #pragma unroll
            for (int mt = 0; mt < 2; mt++) {
                uint32_t row = (uint32_t)(wm * 32 + mt * 16) + la;
                ldsm4(qf[mt], smb + ASM_Q + swzV(row, (uint32_t)(ks * 2) + hsel));
            }
            uint32_t kf[4];
            {
                uint32_t row = (uint32_t)(wn * 16) + la;
                ldsm4(kf, smb + ASM_B0 + swzV(row, (uint32_t)(ks * 2) + hsel));
            }
            #pragma unroll
            for (int mt = 0; mt < 2; mt++)
                #pragma unroll
                for (int nti = 0; nti < 2; nti++)
                    mma16816h(sacc[mt][nti], qf[mt], kf[nti], kf[nti + 2]);
        }

        // ---- decay + single fp16 S staging ----
        int dq = q0 - kt;
        #pragma unroll
        for (int mt = 0; mt < 2; mt++)
            #pragma unroll
            for (int nti = 0; nti < 2; nti++) {
                int qr0 = wm * 32 + mt * 16 + (l >> 2);
                int key = wn * 16 + nti * 8 + (l & 3) * 2;
                #pragma unroll
                for (int h = 0; h < 2; h++) {
                    int q = qr0 + 8 * h;
                    int e0 = dq + q - key;
                    float g0 = (e0 >= 0) ? g_gamma[e0] : 0.0f;
                    float g1 = (e0 >= 1) ? g_gamma[e0 - 1] : 0.0f;
                    float s0 = sacc[mt][nti][2 * h] * g0;
                    float s1 = sacc[mt][nti][2 * h + 1] * g1;
                    uint32_t cc = (uint32_t)(key >> 3);
                    uint32_t inb = (uint32_t)((key & 7) * 2);
                    *(uint32_t*)(sm + ASM_S + swzS((uint32_t)q, cc) + inb) = fp16pair(s0, s1);
                }
            }
        __syncthreads();

        if (it + 1 < nt) {
            #pragma unroll
            for (int i = 0; i < 8; i++) {
                int id = tid + i * 256;
                uint32_t row = (uint32_t)(id >> 5), cc = (uint32_t)(id & 31);
                cp16(smb + ASM_B0 + swzV(row, cc),
                     g_Kh + (base + kt + 64 + row) * HD + cc * 8);
            }
            CP_COMMIT();
            CP_WAIT(1);
        } else {
            CP_WAIT(0);
        }
        __syncthreads();

        // ---- phase 2: O += S V, single fp16 ----
        #pragma unroll
        for (int ks2 = 0; ks2 < 4; ks2++) {
            uint32_t sh[2][4];
            #pragma unroll
            for (int mt = 0; mt < 2; mt++) {
                uint32_t row = (uint32_t)(wm * 32 + mt * 16) + la;
                ldsm4(sh[mt], smb + ASM_S + swzS(row, (uint32_t)(ks2 * 2) + hsel));
            }
            uint32_t vrow = (uint32_t)(ks2 * 16) + la;
            #pragma unroll
            for (int j = 0; j < 4; j++) {
                uint32_t vh[4];
                uint32_t cc = (uint32_t)(wn * 8 + j * 2) + hsel;
                ldsm4t(vh, smb + ASM_B1 + swzV(vrow, cc));
                #pragma unroll
                for (int nti = 0; nti < 2; nti++) {
                    uint32_t b0 = vh[nti * 2], b1 = vh[nti * 2 + 1];
                    #pragma unroll
                    for (int mt = 0; mt < 2; mt++)
                        mma16816h(o[mt][j * 2 + nti], sh[mt], b0, b1);
                }
            }
        }
        __syncthreads();

        if (it + 1 < nt) {
            #pragma unroll
            for (int i = 0; i < 8; i++) {
                int id = tid + i * 256;
                uint32_t row = (uint32_t)(id >> 5), cc = (uint32_t)(id & 31);
                cp16(smb + ASM_B1 + swzV(row, cc),
                     g_Vf + (base + kt + 64 + row) * HD + cc * 8);
            }
            CP_COMMIT();
        }
    }

    #pragma unroll
    for (int mt = 0; mt < 2; mt++)
        #pragma unroll
        for (int h = 0; h < 2; h++) {
            int q = q0 + wm * 32 + mt * 16 + (l >> 2) + 8 * h;
            size_t ro = (base + q) * (size_t)HD;
            #pragma unroll
            for (int j = 0; j < 8; j++) {
                int vd = wn * 64 + j * 8 + (l & 3) * 2;
                float2 v;
                v.x = o[mt][j][2 * h];
                v.y = o[mt][j][2 * h + 1];
                *(float2*)(out + ro + vd) = v;
            }
        }
}

// ---------------- launch ----------------
extern "C" void kernel_launch(void* const* d_in, const int* in_sizes, int n_in,
                              void* d_out, int out_size) {
    const float* X  = (const float*)d_in[0];
    const float* WQ = (const float*)d_in[1];
    const float* WK = (const float*)d_in[2];
    const float* WV = (const float*)d_in[3];
    float* out = (float*)d_out;

    splitw_kernel<<<(3 * HID * HD) / 256, 256>>>(WQ, WK, WV);   // also builds const tables
    tables_kernel<<<SEQ, 128>>>();
    splitx_kernel<<<(MTOT * HID / 8) / 256, 256>>>(X);

    cudaFuncSetAttribute(proj_mma_kernel, cudaFuncAttributeMaxDynamicSharedMemorySize,
                         PROJ_SMEM);
    dim3 pg(6, MTOT / 128);
    proj_mma_kernel<<<pg, 256, PROJ_SMEM>>>();

    cudaFuncSetAttribute(attn_mma_kernel, cudaFuncAttributeMaxDynamicSharedMemorySize,
                         ATTN_SMEM);
    dim3 ag(SEQ / 64, NB);
    attn_mma_kernel<<<ag, 256, ATTN_SMEM>>>(out);
}